// round 2
// baseline (speedup 1.0000x reference)
#include <cuda_runtime.h>

// Problem constants
#define NB  4
#define GRP 8
#define HWP 1024

// Scratch (device globals; no runtime allocation allowed)
__device__ float g_q [NB*GRP*256*HWP];
__device__ float g_k [NB*GRP*256*HWP];
__device__ float g_v [NB*GRP*256*HWP];
__device__ float g_av[NB*GRP*256*HWP];
__device__ float g_y [NB*GRP*256*HWP];
__device__ float g_t [NB*GRP*256*HWP];
__device__ float g_h1[NB*GRP*256*HWP];
__device__ float g_f [NB*GRP*256*HWP];

// ---- packed f32x2 helpers (Blackwell FFMA2) ----
typedef unsigned long long u64;
__device__ __forceinline__ u64 pk2(float x, float y) {
    u64 r; asm("mov.b64 %0, {%1, %2};" : "=l"(r) : "f"(x), "f"(y)); return r;
}
__device__ __forceinline__ void fma2(u64& d, u64 a, u64 b) {
    asm("fma.rn.f32x2 %0, %1, %2, %3;" : "=l"(d) : "l"(a), "l"(b), "l"(d));
}
__device__ __forceinline__ float2 upk(u64 v) {
    float2 f; asm("mov.b64 {%0, %1}, %2;" : "=f"(f.x), "=f"(f.y) : "l"(v)); return f;
}

// ---------------------------------------------------------------------------
// Batched grouped GEMM with FFMA2: C[bz][o][p] = sum_i W[g][o][i]*X[bz][i][p]
// O=256, I=256, P=1024, 32 batches. BM=BN=128, BK=8, 256 thr, 8x8 microtile
// with row-pair-packed f32x2 accumulators.
// ---------------------------------------------------------------------------
__global__ __launch_bounds__(256) void gemm_kernel(
    const float* __restrict__ Wt, const float* __restrict__ X,
    const float* __restrict__ bias, float* __restrict__ C, int relu)
{
    int bz = blockIdx.z;
    int g  = bz & 7;
    const float* A = Wt + (size_t)g  * 256 * 256;
    const float* B = X  + (size_t)bz * 256 * 1024;
    float*      Cb = C  + (size_t)bz * 256 * 1024;
    int o0 = blockIdx.y * 128;
    int p0 = blockIdx.x * 128;

    __shared__ float As[8][128];
    __shared__ float Bs[8][128];

    int t  = threadIdx.x;
    int ar = t >> 1,  ac = (t & 1) << 2;
    int br = t >> 5,  bc = (t & 31) << 2;
    int to = (t >> 4) << 3;
    int tp = (t & 15) << 3;

    u64 acc[4][8];
#pragma unroll
    for (int i = 0; i < 4; i++)
#pragma unroll
        for (int j = 0; j < 8; j++) acc[i][j] = 0ull;

    for (int k0 = 0; k0 < 256; k0 += 8) {
        float4 a4 = *(const float4*)(A + (size_t)(o0 + ar) * 256 + k0 + ac);
        float4 b4 = *(const float4*)(B + (size_t)(k0 + br) * 1024 + p0 + bc);
        __syncthreads();
        As[ac + 0][ar] = a4.x; As[ac + 1][ar] = a4.y;
        As[ac + 2][ar] = a4.z; As[ac + 3][ar] = a4.w;
        *(float4*)(&Bs[br][bc]) = b4;
        __syncthreads();
#pragma unroll
        for (int k = 0; k < 8; k++) {
            // a row pairs: (to,to+1),(to+2,to+3),(to+4,to+5),(to+6,to+7)
            ulonglong2 a01 = *(const ulonglong2*)(&As[k][to]);
            ulonglong2 a23 = *(const ulonglong2*)(&As[k][to + 4]);
            float4 bx = *(const float4*)(&Bs[k][tp]);
            float4 by = *(const float4*)(&Bs[k][tp + 4]);
            u64 bb[8];
            bb[0] = pk2(bx.x, bx.x); bb[1] = pk2(bx.y, bx.y);
            bb[2] = pk2(bx.z, bx.z); bb[3] = pk2(bx.w, bx.w);
            bb[4] = pk2(by.x, by.x); bb[5] = pk2(by.y, by.y);
            bb[6] = pk2(by.z, by.z); bb[7] = pk2(by.w, by.w);
#pragma unroll
            for (int j = 0; j < 8; j++) {
                fma2(acc[0][j], a01.x, bb[j]);
                fma2(acc[1][j], a01.y, bb[j]);
                fma2(acc[2][j], a23.x, bb[j]);
                fma2(acc[3][j], a23.y, bb[j]);
            }
        }
    }

#pragma unroll
    for (int ip = 0; ip < 4; ip++) {
        int oa = o0 + to + 2 * ip;
        float bia = bias ? bias[g * 256 + oa]     : 0.f;
        float bib = bias ? bias[g * 256 + oa + 1] : 0.f;
        float4 ra0, ra1, rb0, rb1;
        float2 f;
        f = upk(acc[ip][0]); ra0.x = f.x + bia; rb0.x = f.y + bib;
        f = upk(acc[ip][1]); ra0.y = f.x + bia; rb0.y = f.y + bib;
        f = upk(acc[ip][2]); ra0.z = f.x + bia; rb0.z = f.y + bib;
        f = upk(acc[ip][3]); ra0.w = f.x + bia; rb0.w = f.y + bib;
        f = upk(acc[ip][4]); ra1.x = f.x + bia; rb1.x = f.y + bib;
        f = upk(acc[ip][5]); ra1.y = f.x + bia; rb1.y = f.y + bib;
        f = upk(acc[ip][6]); ra1.z = f.x + bia; rb1.z = f.y + bib;
        f = upk(acc[ip][7]); ra1.w = f.x + bia; rb1.w = f.y + bib;
        if (relu) {
            ra0.x=fmaxf(ra0.x,0.f); ra0.y=fmaxf(ra0.y,0.f); ra0.z=fmaxf(ra0.z,0.f); ra0.w=fmaxf(ra0.w,0.f);
            ra1.x=fmaxf(ra1.x,0.f); ra1.y=fmaxf(ra1.y,0.f); ra1.z=fmaxf(ra1.z,0.f); ra1.w=fmaxf(ra1.w,0.f);
            rb0.x=fmaxf(rb0.x,0.f); rb0.y=fmaxf(rb0.y,0.f); rb0.z=fmaxf(rb0.z,0.f); rb0.w=fmaxf(rb0.w,0.f);
            rb1.x=fmaxf(rb1.x,0.f); rb1.y=fmaxf(rb1.y,0.f); rb1.z=fmaxf(rb1.z,0.f); rb1.w=fmaxf(rb1.w,0.f);
        }
        *(float4*)(Cb + (size_t)oa * 1024 + p0 + tp)           = ra0;
        *(float4*)(Cb + (size_t)oa * 1024 + p0 + tp + 4)       = ra1;
        *(float4*)(Cb + (size_t)(oa + 1) * 1024 + p0 + tp)     = rb0;
        *(float4*)(Cb + (size_t)(oa + 1) * 1024 + p0 + tp + 4) = rb1;
    }
}

// ---------------------------------------------------------------------------
// Windowed attention, 4 pixels per 128-thread block (warp = pixel).
// smem (floats, padded stride 516 per halo position):
//   sk[18*516]=9288 | sv 9288 | sq[4*516]=2064 | srh 768 | srw 768
//   satT[4][72][8][2]=4608  -> total 26784 floats = 107136 B (2 CTAs/SM)
// ---------------------------------------------------------------------------
#define PSTR 516
__global__ __launch_bounds__(128) void attn_kernel(
    const float* __restrict__ q, const float* __restrict__ k,
    const float* __restrict__ v, const float* __restrict__ hm,
    const float* __restrict__ wmm, float* __restrict__ outp)
{
    extern __shared__ float smem[];
    float* sk   = smem;
    float* sv   = sk  + 18 * PSTR;
    float* sq   = sv  + 18 * PSTR;
    float* srh  = sq  + 4 * PSTR;
    float* srw  = srh + 768;
    float* satT = srw + 768;

    int t  = threadIdx.x;
    int w0 = blockIdx.x << 2;
    int h  = blockIdx.y;
    int nm = blockIdx.z;
    int n  = nm >> 2, m = nm & 3;

    // ---- halo load: 3 rows x 6 cols x 512 ch ----
    for (int idx = t; idx < 9216; idx += 128) {
        int c    = idx % 6;
        int rest = idx / 6;          // r*512 + ed
        int ed   = rest & 511;
        int r    = rest >> 9;
        int e    = ed >> 6, d = ed & 63;
        int h2 = h + r - 1, w2 = w0 + c - 1;
        float kv = 0.f, vv = 0.f;
        if (h2 >= 0 && h2 < 32 && w2 >= 0 && w2 < 32) {
            size_t gi = (((size_t)(n * 8 + e) * 256) + m * 64 + d) * 1024 + h2 * 32 + w2;
            kv = k[gi]; vv = v[gi];
        }
        int si = (r * 6 + c) * PSTR + ed;
        sk[si] = kv; sv[si] = vv;
    }
    // ---- q for the 4 pixels ----
    for (int idx = t; idx < 2048; idx += 128) {
        int pix = idx & 3, gd = idx >> 2;
        size_t gi = (((size_t)(n * 8 + (gd >> 6)) * 256) + m * 64 + (gd & 63)) * 1024
                    + h * 32 + w0 + pix;
        sq[pix * PSTR + gd] = q[gi];
    }
    // ---- relative embeddings ----
    for (int idx = t; idx < 768; idx += 128) {
        int d  = idx & 63;
        int ei = idx >> 6;            // e*3+i
        int e  = ei / 3, i = ei % 3;
        srh[ei * 64 + d] = hm [((e * 256 + m * 64 + d) * 3) + i];
        srw[ei * 64 + d] = wmm[((e * 256 + m * 64 + d) * 3) + i];
    }
    __syncthreads();

    int wi = t >> 5, l = t & 31;
    int g  = l >> 2, e0 = l & 3;
    const float* sqw = sq + wi * PSTR + g * 64;
    int cc = wi + 1;

    // ---- q . rel (packed) ----
    u64 hA[3] = {0,0,0}, hB[3] = {0,0,0};
#pragma unroll 4
    for (int dd = 0; dd < 64; dd += 4) {
        ulonglong2 q2 = *(const ulonglong2*)(sqw + dd);
#pragma unroll
        for (int u = 0; u < 3; u++) {
            ulonglong2 r2 = *(const ulonglong2*)(srh + (e0 * 3 + u) * 64 + dd);
            ulonglong2 s2 = *(const ulonglong2*)(srw + (e0 * 3 + u) * 64 + dd);
            fma2(hA[u], q2.x, r2.x); fma2(hA[u], q2.y, r2.y);
            fma2(hB[u], q2.x, s2.x); fma2(hB[u], q2.y, s2.y);
        }
    }
    float qrA[3], qrB[3];
#pragma unroll
    for (int u = 0; u < 3; u++) {
        float2 fa = upk(hA[u]), fb = upk(hB[u]);
        qrA[u] = fa.x + fa.y; qrB[u] = fb.x + fb.y;
    }

    // ---- scores over 9 neighbors for e0 and e0+4 ----
    const float* kb[9];
#pragma unroll
    for (int i = 0; i < 3; i++)
#pragma unroll
        for (int j = 0; j < 3; j++)
            kb[i * 3 + j] = sk + (i * 6 + cc - 1 + j) * PSTR + e0 * 64;

    u64 cA[9], cB[9];
#pragma unroll
    for (int u = 0; u < 9; u++) { cA[u] = 0ull; cB[u] = 0ull; }
#pragma unroll 2
    for (int dd = 0; dd < 64; dd += 4) {
        ulonglong2 q2 = *(const ulonglong2*)(sqw + dd);
#pragma unroll
        for (int u = 0; u < 9; u++) {
            ulonglong2 ka = *(const ulonglong2*)(kb[u] + dd);
            ulonglong2 kc = *(const ulonglong2*)(kb[u] + 256 + dd);
            fma2(cA[u], q2.x, ka.x); fma2(cA[u], q2.y, ka.y);
            fma2(cB[u], q2.x, kc.x); fma2(cB[u], q2.y, kc.y);
        }
    }
    float sA[9], sB[9];
#pragma unroll
    for (int u = 0; u < 9; u++) {
        float2 fa = upk(cA[u]), fb = upk(cB[u]);
        sA[u] = fa.x + fa.y + qrA[u / 3];
        sB[u] = fb.x + fb.y + qrB[u % 3];
    }

    // ---- softmax over 72, shared by the 4 lanes of equal g ----
    float mx = -1e30f;
#pragma unroll
    for (int u = 0; u < 9; u++) mx = fmaxf(mx, fmaxf(sA[u], sB[u]));
    mx = fmaxf(mx, __shfl_xor_sync(0xffffffffu, mx, 1));
    mx = fmaxf(mx, __shfl_xor_sync(0xffffffffu, mx, 2));
    float sum = 0.f;
#pragma unroll
    for (int u = 0; u < 9; u++) {
        sA[u] = __expf(sA[u] - mx);
        sB[u] = __expf(sB[u] - mx);
        sum += sA[u] + sB[u];
    }
    sum += __shfl_xor_sync(0xffffffffu, sum, 1);
    sum += __shfl_xor_sync(0xffffffffu, sum, 2);
    float inv = 1.f / sum;

    // store duplicated weights: satT[wi][e*9+nb][g][2]
    float* awT = satT + wi * 1152;
#pragma unroll
    for (int u = 0; u < 9; u++) {
        float wa = sA[u] * inv, wb = sB[u] * inv;
        *(float2*)(awT + ((e0 * 9 + u) * 8 + g) * 2)       = make_float2(wa, wa);
        *(float2*)(awT + (((e0 + 4) * 9 + u) * 8 + g) * 2) = make_float2(wb, wb);
    }
    __syncwarp();

    // ---- AV: lane owns d = 2l, 2l+1 ; v loaded once per (e,nb), all 8 g ----
    int posoff[9];
#pragma unroll
    for (int i = 0; i < 3; i++)
#pragma unroll
        for (int j = 0; j < 3; j++)
            posoff[i * 3 + j] = (i * 6 + cc - 1 + j) * PSTR;

    u64 acc[8];
#pragma unroll
    for (int gg = 0; gg < 8; gg++) acc[gg] = 0ull;
#pragma unroll 1
    for (int e = 0; e < 8; e++) {
        const float* vb = sv + e * 64 + 2 * l;
#pragma unroll
        for (int nb = 0; nb < 9; nb++) {
            u64 v2 = *(const u64*)(vb + posoff[nb]);
            const ulonglong2* wp = (const ulonglong2*)(awT + (e * 9 + nb) * 16);
            ulonglong2 w01 = wp[0], w23 = wp[1], w45 = wp[2], w67 = wp[3];
            fma2(acc[0], w01.x, v2); fma2(acc[1], w01.y, v2);
            fma2(acc[2], w23.x, v2); fma2(acc[3], w23.y, v2);
            fma2(acc[4], w45.x, v2); fma2(acc[5], w45.y, v2);
            fma2(acc[6], w67.x, v2); fma2(acc[7], w67.y, v2);
        }
    }
    // write av into sq region (own pixel only; q fully consumed)
    float* sav = sq + wi * PSTR;
#pragma unroll
    for (int gg = 0; gg < 8; gg++) {
        float2 f = upk(acc[gg]);
        *(float2*)(sav + gg * 64 + 2 * l) = f;
    }
    __syncthreads();

    // ---- coalesced transpose write: out[n,g2,m*64+d2, h*32 + w0..w0+3] ----
#pragma unroll
    for (int it = 0; it < 4; it++) {
        int rr = t + it * 128;
        int g2 = rr >> 6, d2 = rr & 63;
        size_t ob = (((size_t)(n * 8 + g2) * 256) + m * 64 + d2) * 1024 + h * 32 + w0;
        float4 o;
        o.x = sq[0 * PSTR + rr]; o.y = sq[1 * PSTR + rr];
        o.z = sq[2 * PSTR + rr]; o.w = sq[3 * PSTR + rr];
        *(float4*)(outp + ob) = o;
    }
}

// ---------------------------------------------------------------------------
// Fused skip + LayerNorm over d=64; writes flat (n,p,m,g,d) order.
// ---------------------------------------------------------------------------
__global__ __launch_bounds__(256) void ln_kernel(
    const float* __restrict__ X, const float* __restrict__ Y,
    const float* __restrict__ gamma, const float* __restrict__ beta,
    float* __restrict__ T)
{
    __shared__ float sx[64][33];
    int t  = threadIdx.x;
    int p0 = blockIdx.x << 5;
    int gm = blockIdx.y;
    int g  = gm >> 2, m = gm & 3;
    int n  = blockIdx.z;
    size_t base = (((size_t)(n * 8 + g) * 256) + m * 64) * 1024 + p0;
    int pp = t & 31;
#pragma unroll
    for (int pass = 0; pass < 8; pass++) {
        int d = (t >> 5) + pass * 8;
        sx[d][pp] = X[base + (size_t)d * 1024 + pp] + Y[base + (size_t)d * 1024 + pp];
    }
    __syncthreads();
    int c = t >> 3, sub = t & 7;
    float s1 = 0.f, s2 = 0.f;
#pragma unroll
    for (int u = 0; u < 8; u++) {
        float vv = sx[sub * 8 + u][c];
        s1 += vv; s2 += vv * vv;
    }
#pragma unroll
    for (int off = 1; off < 8; off <<= 1) {
        s1 += __shfl_xor_sync(0xffffffffu, s1, off);
        s2 += __shfl_xor_sync(0xffffffffu, s2, off);
    }
    float mu  = s1 * 0.015625f;
    float var = s2 * 0.015625f - mu * mu;
    float inv = rsqrtf(var + 1e-5f);
    float* op = T + ((((size_t)n * 1024 + p0 + c) * 4 + m) * 8 + g) * 64;
#pragma unroll
    for (int u = 0; u < 8; u++) {
        int d = sub * 8 + u;
        op[d] = (sx[d][c] - mu) * inv * gamma[d] + beta[d];
    }
}

// ---------------------------------------------------------------------------
extern "C" void kernel_launch(void* const* d_in, const int* in_sizes, int n_in,
                              void* d_out, int out_size)
{
    (void)in_sizes; (void)n_in; (void)out_size;
    const float* x     = (const float*)d_in[0];
    const float* wq    = (const float*)d_in[1];
    const float* wk    = (const float*)d_in[2];
    const float* wv    = (const float*)d_in[3];
    const float* hm    = (const float*)d_in[4];
    const float* wm    = (const float*)d_in[5];
    const float* wconv = (const float*)d_in[6];
    const float* bconv = (const float*)d_in[7];
    const float* wf1   = (const float*)d_in[8];
    const float* bf1   = (const float*)d_in[9];
    const float* wf2   = (const float*)d_in[10];
    const float* bf2   = (const float*)d_in[11];
    const float* g1    = (const float*)d_in[12];
    const float* b1    = (const float*)d_in[13];
    const float* g2    = (const float*)d_in[14];
    const float* b2    = (const float*)d_in[15];

    float *q, *k, *v, *av, *y, *tb, *h1, *f;
    cudaGetSymbolAddress((void**)&q,  g_q);
    cudaGetSymbolAddress((void**)&k,  g_k);
    cudaGetSymbolAddress((void**)&v,  g_v);
    cudaGetSymbolAddress((void**)&av, g_av);
    cudaGetSymbolAddress((void**)&y,  g_y);
    cudaGetSymbolAddress((void**)&tb, g_t);
    cudaGetSymbolAddress((void**)&h1, g_h1);
    cudaGetSymbolAddress((void**)&f,  g_f);

    cudaFuncSetAttribute(attn_kernel,
                         cudaFuncAttributeMaxDynamicSharedMemorySize, 107136);

    dim3 gdim(8, 2, 32);
    gemm_kernel<<<gdim, 256>>>(wq, x, nullptr, q, 0);
    gemm_kernel<<<gdim, 256>>>(wk, x, nullptr, k, 0);
    gemm_kernel<<<gdim, 256>>>(wv, x, nullptr, v, 0);

    attn_kernel<<<dim3(8, 32, 16), 128, 107136>>>(q, k, v, hm, wm, av);

    gemm_kernel<<<gdim, 256>>>(wconv, av, bconv, y, 0);
    ln_kernel<<<dim3(32, 32, 4), 256>>>(x, y, g1, b1, tb);
    gemm_kernel<<<gdim, 256>>>(wf1, tb, bf1, h1, 1);
    gemm_kernel<<<gdim, 256>>>(wf2, h1, bf2, f, 0);
    ln_kernel<<<dim3(32, 32, 4), 256>>>(tb, f, g2, b2, (float*)d_out);
}

// round 3
// speedup vs baseline: 1.5040x; 1.5040x over previous
#include <cuda_runtime.h>

#define HWP 1024

// Scratch (device globals)
__device__ float g_q [4*8*256*HWP];
__device__ float g_k [4*8*256*HWP];
__device__ float g_v [4*8*256*HWP];
__device__ float g_av[4*8*256*HWP];
__device__ float g_y [4*8*256*HWP];
__device__ float g_t [4*8*256*HWP];
__device__ float g_h1[4*8*256*HWP];
__device__ float g_f [4*8*256*HWP];

typedef unsigned long long u64;
__device__ __forceinline__ u64 pk2(float x, float y) {
    u64 r; asm("mov.b64 %0, {%1, %2};" : "=l"(r) : "f"(x), "f"(y)); return r;
}
__device__ __forceinline__ void fma2(u64& d, u64 a, u64 b) {
    asm("fma.rn.f32x2 %0, %1, %2, %3;" : "=l"(d) : "l"(a), "l"(b), "l"(d));
}
__device__ __forceinline__ float2 upk(u64 v) {
    float2 f; asm("mov.b64 {%0, %1}, %2;" : "=f"(f.x), "=f"(f.y) : "l"(v)); return f;
}

// ---------------------------------------------------------------------------
// Batched grouped GEMM, double-buffered smem pipeline.
// C[bz][o][p] = sum_i W[g][o][i] * X[bz][i][p] (+bias)(+relu)
// ---------------------------------------------------------------------------
__global__ __launch_bounds__(256, 2) void gemm_kernel(
    const float* __restrict__ Wt, const float* __restrict__ X,
    const float* __restrict__ bias, float* __restrict__ C, int relu)
{
    int bz = blockIdx.z;
    int g  = bz & 7;
    const float* A = Wt + (size_t)g  * 256 * 256;
    const float* B = X  + (size_t)bz * 256 * 1024;
    float*      Cb = C  + (size_t)bz * 256 * 1024;
    int o0 = blockIdx.y * 128;
    int p0 = blockIdx.x * 128;

    __shared__ float As[2][8][128];
    __shared__ float Bs[2][8][128];

    int t  = threadIdx.x;
    int ar = t >> 1,  ac = (t & 1) << 2;
    int br = t >> 5,  bc = (t & 31) << 2;
    int to = (t >> 4) << 3;
    int tp = (t & 15) << 3;

    u64 acc[4][8];
#pragma unroll
    for (int i = 0; i < 4; i++)
#pragma unroll
        for (int j = 0; j < 8; j++) acc[i][j] = 0ull;

    // prologue: stage k0=0 into buf 0
    {
        float4 a4 = *(const float4*)(A + (size_t)(o0 + ar) * 256 + ac);
        float4 b4 = *(const float4*)(B + (size_t)br * 1024 + p0 + bc);
        As[0][ac + 0][ar] = a4.x; As[0][ac + 1][ar] = a4.y;
        As[0][ac + 2][ar] = a4.z; As[0][ac + 3][ar] = a4.w;
        *(float4*)(&Bs[0][br][bc]) = b4;
    }
    __syncthreads();

    int cur = 0;
    for (int it = 0; it < 32; it++) {
        float4 a4n, b4n;
        if (it < 31) {
            int k0 = (it + 1) << 3;
            a4n = *(const float4*)(A + (size_t)(o0 + ar) * 256 + k0 + ac);
            b4n = *(const float4*)(B + (size_t)(k0 + br) * 1024 + p0 + bc);
        }
#pragma unroll
        for (int k = 0; k < 8; k++) {
            ulonglong2 a01 = *(const ulonglong2*)(&As[cur][k][to]);
            ulonglong2 a23 = *(const ulonglong2*)(&As[cur][k][to + 4]);
            float4 bx = *(const float4*)(&Bs[cur][k][tp]);
            float4 by = *(const float4*)(&Bs[cur][k][tp + 4]);
            u64 bb[8];
            bb[0] = pk2(bx.x, bx.x); bb[1] = pk2(bx.y, bx.y);
            bb[2] = pk2(bx.z, bx.z); bb[3] = pk2(bx.w, bx.w);
            bb[4] = pk2(by.x, by.x); bb[5] = pk2(by.y, by.y);
            bb[6] = pk2(by.z, by.z); bb[7] = pk2(by.w, by.w);
#pragma unroll
            for (int j = 0; j < 8; j++) {
                fma2(acc[0][j], a01.x, bb[j]);
                fma2(acc[1][j], a01.y, bb[j]);
                fma2(acc[2][j], a23.x, bb[j]);
                fma2(acc[3][j], a23.y, bb[j]);
            }
        }
        if (it < 31) {
            int nxt = cur ^ 1;
            As[nxt][ac + 0][ar] = a4n.x; As[nxt][ac + 1][ar] = a4n.y;
            As[nxt][ac + 2][ar] = a4n.z; As[nxt][ac + 3][ar] = a4n.w;
            *(float4*)(&Bs[nxt][br][bc]) = b4n;
            __syncthreads();
            cur = nxt;
        }
    }

#pragma unroll
    for (int ip = 0; ip < 4; ip++) {
        int oa = o0 + to + 2 * ip;
        float bia = bias ? bias[g * 256 + oa]     : 0.f;
        float bib = bias ? bias[g * 256 + oa + 1] : 0.f;
        float4 ra0, ra1, rb0, rb1;
        float2 f;
        f = upk(acc[ip][0]); ra0.x = f.x + bia; rb0.x = f.y + bib;
        f = upk(acc[ip][1]); ra0.y = f.x + bia; rb0.y = f.y + bib;
        f = upk(acc[ip][2]); ra0.z = f.x + bia; rb0.z = f.y + bib;
        f = upk(acc[ip][3]); ra0.w = f.x + bia; rb0.w = f.y + bib;
        f = upk(acc[ip][4]); ra1.x = f.x + bia; rb1.x = f.y + bib;
        f = upk(acc[ip][5]); ra1.y = f.x + bia; rb1.y = f.y + bib;
        f = upk(acc[ip][6]); ra1.z = f.x + bia; rb1.z = f.y + bib;
        f = upk(acc[ip][7]); ra1.w = f.x + bia; rb1.w = f.y + bib;
        if (relu) {
            ra0.x=fmaxf(ra0.x,0.f); ra0.y=fmaxf(ra0.y,0.f); ra0.z=fmaxf(ra0.z,0.f); ra0.w=fmaxf(ra0.w,0.f);
            ra1.x=fmaxf(ra1.x,0.f); ra1.y=fmaxf(ra1.y,0.f); ra1.z=fmaxf(ra1.z,0.f); ra1.w=fmaxf(ra1.w,0.f);
            rb0.x=fmaxf(rb0.x,0.f); rb0.y=fmaxf(rb0.y,0.f); rb0.z=fmaxf(rb0.z,0.f); rb0.w=fmaxf(rb0.w,0.f);
            rb1.x=fmaxf(rb1.x,0.f); rb1.y=fmaxf(rb1.y,0.f); rb1.z=fmaxf(rb1.z,0.f); rb1.w=fmaxf(rb1.w,0.f);
        }
        *(float4*)(Cb + (size_t)oa * 1024 + p0 + tp)           = ra0;
        *(float4*)(Cb + (size_t)oa * 1024 + p0 + tp + 4)       = ra1;
        *(float4*)(Cb + (size_t)(oa + 1) * 1024 + p0 + tp)     = rb0;
        *(float4*)(Cb + (size_t)(oa + 1) * 1024 + p0 + tp + 4) = rb1;
    }
}

// ---------------------------------------------------------------------------
// Windowed attention, 2x8 pixel tile, 512 threads (warp = pixel), fp32.
// Conflict-free padded smem layouts. Region reuse:
//   A: k-halo (40 pos x 548) -> attn-weight dup [pix][72][8][2]
//   B: v-halo (40 pos x 548)
//   C: q (16 x 548) + rel (2 x 12 x 68) -> out staging (16 x 522)
// Total 54240 floats = 216960 B, 1 CTA x 16 warps / SM.
// ---------------------------------------------------------------------------
#define HPS 548
#define EPS 68
#define QPS 548
#define OPS 522
#define SK_F   (40*HPS)         // 21920
#define SQ_F   (16*QPS)         // 8768
#define REL_F  (12*EPS)         // 816

__global__ __launch_bounds__(512) void attn_kernel(
    const float* __restrict__ q, const float* __restrict__ k,
    const float* __restrict__ v, const float* __restrict__ hm,
    const float* __restrict__ wmm, float* __restrict__ outp)
{
    extern __shared__ float smem[];
    float* sk   = smem;                    // region A
    float* sv   = sk + SK_F;               // region B
    float* sq   = sv + SK_F;               // region C
    float* srh  = sq + SQ_F;
    float* srw  = srh + REL_F;
    float* attd = sk;                      // overlay A (after scores)
    float* sout = sq;                      // overlay C (after scores)

    int t  = threadIdx.x;
    int w0 = blockIdx.x << 3;
    int h0 = blockIdx.y << 1;
    int nm = blockIdx.z;
    int n  = nm >> 2, m = nm & 3;

    // ---- halo load: 4 rows x 10 cols x 512 ch ----
    for (int idx = t; idx < 20480; idx += 512) {
        int c   = idx % 10;
        int red = idx / 10;                // r*512 + e*64 + d
        int d   = red & 63;
        int e   = (red >> 6) & 7;
        int r   = red >> 9;
        int h2 = h0 + r - 1, w2 = w0 + c - 1;
        float kv = 0.f, vv = 0.f;
        if (h2 >= 0 && h2 < 32 && w2 >= 0 && w2 < 32) {
            size_t gi = (((size_t)(n * 8 + e) * 256) + m * 64 + d) * 1024 + h2 * 32 + w2;
            kv = k[gi]; vv = v[gi];
        }
        int si = (r * 10 + c) * HPS + e * EPS + d;
        sk[si] = kv; sv[si] = vv;
    }
    // ---- q for the 16 pixels ----
    for (int idx = t; idx < 8192; idx += 512) {
        int pix = idx & 15, gd = idx >> 4;
        int gq = gd >> 6, d = gd & 63;
        int pr = pix >> 3, pc = pix & 7;
        size_t gi = (((size_t)(n * 8 + gq) * 256) + m * 64 + d) * 1024
                    + (h0 + pr) * 32 + w0 + pc;
        sq[pix * QPS + gq * EPS + d] = q[gi];
    }
    // ---- relative embeddings ----
    for (int idx = t; idx < 768; idx += 512) {
        int d  = idx & 63;
        int ei = idx >> 6;                 // e*3+i, e<4
        int e  = ei / 3, i = ei % 3;
        srh[ei * EPS + d] = hm [((e * 256 + m * 64 + d) * 3) + i];
        srw[ei * EPS + d] = wmm[((e * 256 + m * 64 + d) * 3) + i];
    }
    __syncthreads();

    int wi = t >> 5, l = t & 31;
    int g  = l >> 2, e0 = l & 3;
    int pr = wi >> 3, cc = (wi & 7) + 1;
    const float* sqw = sq + wi * QPS + g * EPS;
    int eoff = e0 * EPS;

    int posoff[9];
#pragma unroll
    for (int i = 0; i < 3; i++)
#pragma unroll
        for (int j = 0; j < 3; j++)
            posoff[i * 3 + j] = ((pr + i) * 10 + cc - 1 + j) * HPS;

    // ---- q . rel ----
    u64 hA[3] = {0,0,0}, hB[3] = {0,0,0};
#pragma unroll 4
    for (int dd = 0; dd < 64; dd += 4) {
        ulonglong2 q2 = *(const ulonglong2*)(sqw + dd);
#pragma unroll
        for (int u = 0; u < 3; u++) {
            ulonglong2 r2 = *(const ulonglong2*)(srh + (e0 * 3 + u) * EPS + dd);
            ulonglong2 s2 = *(const ulonglong2*)(srw + (e0 * 3 + u) * EPS + dd);
            fma2(hA[u], q2.x, r2.x); fma2(hA[u], q2.y, r2.y);
            fma2(hB[u], q2.x, s2.x); fma2(hB[u], q2.y, s2.y);
        }
    }
    float qrA[3], qrB[3];
#pragma unroll
    for (int u = 0; u < 3; u++) {
        float2 fa = upk(hA[u]), fb = upk(hB[u]);
        qrA[u] = fa.x + fa.y; qrB[u] = fb.x + fb.y;
    }

    // ---- scores ----
    u64 cA[9], cB[9];
#pragma unroll
    for (int u = 0; u < 9; u++) { cA[u] = 0ull; cB[u] = 0ull; }
#pragma unroll 2
    for (int dd = 0; dd < 64; dd += 4) {
        ulonglong2 q2 = *(const ulonglong2*)(sqw + dd);
#pragma unroll
        for (int u = 0; u < 9; u++) {
            const float* kp = sk + posoff[u] + eoff + dd;
            ulonglong2 ka = *(const ulonglong2*)(kp);
            ulonglong2 kc = *(const ulonglong2*)(kp + 4 * EPS);
            fma2(cA[u], q2.x, ka.x); fma2(cA[u], q2.y, ka.y);
            fma2(cB[u], q2.x, kc.x); fma2(cB[u], q2.y, kc.y);
        }
    }
    float sA[9], sB[9];
#pragma unroll
    for (int u = 0; u < 9; u++) {
        float2 fa = upk(cA[u]), fb = upk(cB[u]);
        sA[u] = fa.x + fa.y + qrA[u / 3];
        sB[u] = fb.x + fb.y + qrB[u % 3];
    }

    // ---- softmax over 72 (4 lanes share same g) ----
    float mx = -1e30f;
#pragma unroll
    for (int u = 0; u < 9; u++) mx = fmaxf(mx, fmaxf(sA[u], sB[u]));
    mx = fmaxf(mx, __shfl_xor_sync(0xffffffffu, mx, 1));
    mx = fmaxf(mx, __shfl_xor_sync(0xffffffffu, mx, 2));
    float sum = 0.f;
#pragma unroll
    for (int u = 0; u < 9; u++) {
        sA[u] = __expf(sA[u] - mx);
        sB[u] = __expf(sB[u] - mx);
        sum += sA[u] + sB[u];
    }
    sum += __shfl_xor_sync(0xffffffffu, sum, 1);
    sum += __shfl_xor_sync(0xffffffffu, sum, 2);
    float inv = 1.f / sum;

    // all warps must be done reading sk (k) and sq (q) before overlays
    __syncthreads();

    // ---- store duplicated attn weights: attd[pix][e*9+nb][g][2] ----
    float* awT = attd + wi * 1152;
#pragma unroll
    for (int u = 0; u < 9; u++) {
        float wa = sA[u] * inv, wb = sB[u] * inv;
        *(float2*)(awT + ((e0 * 9 + u) * 8 + g) * 2)       = make_float2(wa, wa);
        *(float2*)(awT + (((e0 + 4) * 9 + u) * 8 + g) * 2) = make_float2(wb, wb);
    }
    __syncwarp();

    // ---- AV: lane owns d = 2l, 2l+1 for all 8 g ----
    u64 acc[8];
#pragma unroll
    for (int gg = 0; gg < 8; gg++) acc[gg] = 0ull;
#pragma unroll 1
    for (int e = 0; e < 8; e++) {
        const float* vb = sv + e * EPS + 2 * l;
#pragma unroll
        for (int nb = 0; nb < 9; nb++) {
            u64 v2 = *(const u64*)(vb + posoff[nb]);
            const ulonglong2* wp = (const ulonglong2*)(awT + (e * 9 + nb) * 16);
            ulonglong2 w01 = wp[0], w23 = wp[1], w45 = wp[2], w67 = wp[3];
            fma2(acc[0], w01.x, v2); fma2(acc[1], w01.y, v2);
            fma2(acc[2], w23.x, v2); fma2(acc[3], w23.y, v2);
            fma2(acc[4], w45.x, v2); fma2(acc[5], w45.y, v2);
            fma2(acc[6], w67.x, v2); fma2(acc[7], w67.y, v2);
        }
    }
    // stage av (overlay C, q fully consumed)
    float* so = sout + wi * OPS;
#pragma unroll
    for (int gg = 0; gg < 8; gg++) {
        float2 f = upk(acc[gg]);
        *(float2*)(so + gg * 64 + 2 * l) = f;
    }
    __syncthreads();

    // ---- coalesced transposed store ----
#pragma unroll
    for (int it = 0; it < 4; it++) {
        int idx = t + it * 512;            // 0..2047
        int quad = idx & 1, row = (idx >> 1) & 1, ch = idx >> 2;  // ch 0..511
        int g2 = ch >> 6, d2 = ch & 63;
        int pb = row * 8 + quad * 4;
        float4 o;
        o.x = sout[(pb + 0) * OPS + ch];
        o.y = sout[(pb + 1) * OPS + ch];
        o.z = sout[(pb + 2) * OPS + ch];
        o.w = sout[(pb + 3) * OPS + ch];
        size_t ob = (((size_t)(n * 8 + g2) * 256) + m * 64 + d2) * 1024
                    + (h0 + row) * 32 + w0 + quad * 4;
        *(float4*)(outp + ob) = o;
    }
}

// ---------------------------------------------------------------------------
// Fused skip + LayerNorm over d=64; writes flat (n,p,m,g,d) order.
// ---------------------------------------------------------------------------
__global__ __launch_bounds__(256) void ln_kernel(
    const float* __restrict__ X, const float* __restrict__ Y,
    const float* __restrict__ gamma, const float* __restrict__ beta,
    float* __restrict__ T)
{
    __shared__ float sx[64][33];
    int t  = threadIdx.x;
    int p0 = blockIdx.x << 5;
    int gm = blockIdx.y;
    int g  = gm >> 2, m = gm & 3;
    int n  = blockIdx.z;
    size_t base = (((size_t)(n * 8 + g) * 256) + m * 64) * 1024 + p0;
    int pp = t & 31;
#pragma unroll
    for (int pass = 0; pass < 8; pass++) {
        int d = (t >> 5) + pass * 8;
        sx[d][pp] = X[base + (size_t)d * 1024 + pp] + Y[base + (size_t)d * 1024 + pp];
    }
    __syncthreads();
    int c = t >> 3, sub = t & 7;
    float s1 = 0.f, s2 = 0.f;
#pragma unroll
    for (int u = 0; u < 8; u++) {
        float vv = sx[sub * 8 + u][c];
        s1 += vv; s2 += vv * vv;
    }
#pragma unroll
    for (int off = 1; off < 8; off <<= 1) {
        s1 += __shfl_xor_sync(0xffffffffu, s1, off);
        s2 += __shfl_xor_sync(0xffffffffu, s2, off);
    }
    float mu  = s1 * 0.015625f;
    float var = s2 * 0.015625f - mu * mu;
    float inv = rsqrtf(var + 1e-5f);
    float* op = T + ((((size_t)n * 1024 + p0 + c) * 4 + m) * 8 + g) * 64;
#pragma unroll
    for (int u = 0; u < 8; u++) {
        int d = sub * 8 + u;
        op[d] = (sx[d][c] - mu) * inv * gamma[d] + beta[d];
    }
}

// ---------------------------------------------------------------------------
extern "C" void kernel_launch(void* const* d_in, const int* in_sizes, int n_in,
                              void* d_out, int out_size)
{
    (void)in_sizes; (void)n_in; (void)out_size;
    const float* x     = (const float*)d_in[0];
    const float* wq    = (const float*)d_in[1];
    const float* wk    = (const float*)d_in[2];
    const float* wv    = (const float*)d_in[3];
    const float* hm    = (const float*)d_in[4];
    const float* wm    = (const float*)d_in[5];
    const float* wconv = (const float*)d_in[6];
    const float* bconv = (const float*)d_in[7];
    const float* wf1   = (const float*)d_in[8];
    const float* bf1   = (const float*)d_in[9];
    const float* wf2   = (const float*)d_in[10];
    const float* bf2   = (const float*)d_in[11];
    const float* g1    = (const float*)d_in[12];
    const float* b1    = (const float*)d_in[13];
    const float* g2    = (const float*)d_in[14];
    const float* b2    = (const float*)d_in[15];

    float *q, *k, *v, *av, *y, *tb, *h1, *f;
    cudaGetSymbolAddress((void**)&q,  g_q);
    cudaGetSymbolAddress((void**)&k,  g_k);
    cudaGetSymbolAddress((void**)&v,  g_v);
    cudaGetSymbolAddress((void**)&av, g_av);
    cudaGetSymbolAddress((void**)&y,  g_y);
    cudaGetSymbolAddress((void**)&tb, g_t);
    cudaGetSymbolAddress((void**)&h1, g_h1);
    cudaGetSymbolAddress((void**)&f,  g_f);

    const int ATTN_SMEM = (SK_F * 2 + SQ_F + REL_F * 2) * 4;   // 216960 B
    cudaFuncSetAttribute(attn_kernel,
                         cudaFuncAttributeMaxDynamicSharedMemorySize, ATTN_SMEM);

    dim3 gdim(8, 2, 32);
    gemm_kernel<<<gdim, 256>>>(wq, x, nullptr, q, 0);
    gemm_kernel<<<gdim, 256>>>(wk, x, nullptr, k, 0);
    gemm_kernel<<<gdim, 256>>>(wv, x, nullptr, v, 0);

    attn_kernel<<<dim3(4, 16, 16), 512, ATTN_SMEM>>>(q, k, v, hm, wm, av);

    gemm_kernel<<<gdim, 256>>>(wconv, av, bconv, y, 0);
    ln_kernel<<<dim3(32, 32, 4), 256>>>(x, y, g1, b1, tb);
    gemm_kernel<<<gdim, 256>>>(wf1, tb, bf1, h1, 1);
    gemm_kernel<<<gdim, 256>>>(wf2, h1, bf2, f, 0);
    ln_kernel<<<dim3(32, 32, 4), 256>>>(tb, f, g2, b2, (float*)d_out);
}

// round 5
// speedup vs baseline: 2.1753x; 1.4464x over previous
#include <cuda_runtime.h>
#include <cuda_bf16.h>
#include <cstdint>

#define HWP 1024

// fp32 scratch
__device__ float g_q [4*8*256*HWP];
__device__ float g_k [4*8*256*HWP];
__device__ float g_v [4*8*256*HWP];
__device__ float g_av[4*8*256*HWP];
__device__ float g_y [4*8*256*HWP];
__device__ float g_t [4*8*256*HWP];
__device__ float g_h1[4*8*256*HWP];
__device__ float g_f [4*8*256*HWP];
// bf16 split operands
__device__ __nv_bfloat16 g_xhiT[32*1024*256];   // [bz][p][k]
__device__ __nv_bfloat16 g_xloT[32*1024*256];
__device__ __nv_bfloat16 g_whi [6*8*256*256];   // [slot][g][o][k]
__device__ __nv_bfloat16 g_wlo [6*8*256*256];

typedef unsigned long long u64;
__device__ __forceinline__ u64 pk2(float x, float y) {
    u64 r; asm("mov.b64 %0, {%1, %2};" : "=l"(r) : "f"(x), "f"(y)); return r;
}
__device__ __forceinline__ void fma2(u64& d, u64 a, u64 b) {
    asm("fma.rn.f32x2 %0, %1, %2, %3;" : "=l"(d) : "l"(a), "l"(b), "l"(d));
}
__device__ __forceinline__ float2 upk(u64 v) {
    float2 f; asm("mov.b64 {%0, %1}, %2;" : "=f"(f.x), "=f"(f.y) : "l"(v)); return f;
}

__device__ __forceinline__ uint32_t smem_u32(const void* p) {
    uint32_t a;
    asm("{ .reg .u64 tmp; cvta.to.shared.u64 tmp, %1; cvt.u32.u64 %0, tmp; }"
        : "=r"(a) : "l"(p));
    return a;
}
__device__ __forceinline__ void ldsm4(uint32_t* r, uint32_t addr) {
    asm volatile("ldmatrix.sync.aligned.m8n8.x4.shared.b16 {%0,%1,%2,%3}, [%4];"
        : "=r"(r[0]), "=r"(r[1]), "=r"(r[2]), "=r"(r[3]) : "r"(addr));
}
__device__ __forceinline__ void mma_bf16(float* c, const uint32_t* a,
                                         uint32_t b0, uint32_t b1) {
    asm volatile("mma.sync.aligned.m16n8k16.row.col.f32.bf16.bf16.f32 "
        "{%0,%1,%2,%3}, {%4,%5,%6,%7}, {%8,%9}, {%0,%1,%2,%3};"
        : "+f"(c[0]), "+f"(c[1]), "+f"(c[2]), "+f"(c[3])
        : "r"(a[0]), "r"(a[1]), "r"(a[2]), "r"(a[3]), "r"(b0), "r"(b1));
}

// ---------------------------------------------------------------------------
// Split fp32 W [g][o][k] into hi/lo bf16. grid (512, 6)
// ---------------------------------------------------------------------------
__global__ __launch_bounds__(256) void convw_kernel(
    const float* __restrict__ w0, const float* __restrict__ w1,
    const float* __restrict__ w2, const float* __restrict__ w3,
    const float* __restrict__ w4, const float* __restrict__ w5,
    __nv_bfloat16* __restrict__ whi, __nv_bfloat16* __restrict__ wlo)
{
    const float* srcs[6] = {w0, w1, w2, w3, w4, w5};
    int slot = blockIdx.y;
    size_t idx = ((size_t)blockIdx.x * 256 + threadIdx.x) * 4;
    float4 v = *(const float4*)(srcs[slot] + idx);
    float vv[4] = {v.x, v.y, v.z, v.w};
    u64 hp = 0, lp = 0;
#pragma unroll
    for (int j = 0; j < 4; j++) {
        __nv_bfloat16 h = __float2bfloat16(vv[j]);
        __nv_bfloat16 lo = __float2bfloat16(vv[j] - __bfloat162float(h));
        hp |= (u64)__bfloat16_as_ushort(h)  << (16 * j);
        lp |= (u64)__bfloat16_as_ushort(lo) << (16 * j);
    }
    size_t o = (size_t)slot * 524288 + idx;
    *(u64*)(whi + o) = hp;
    *(u64*)(wlo + o) = lp;
}

// ---------------------------------------------------------------------------
// Transpose + split: X [bz][k=256][p=1024] fp32 -> hiT/loT [bz][p][k] bf16.
// grid (32 p-tiles, 8 k-tiles, 32 bz), block 256.
// ---------------------------------------------------------------------------
__global__ __launch_bounds__(256) void convx_kernel(
    const float* __restrict__ X,
    __nv_bfloat16* __restrict__ hiT, __nv_bfloat16* __restrict__ loT)
{
    __shared__ float s[32][33];
    int t = threadIdx.x;
    int pt = blockIdx.x, kt = blockIdx.y, bz = blockIdx.z;
    const float* Xb = X + ((size_t)bz * 256 + kt * 32) * 1024 + pt * 32;
    int kr = t >> 5, pc = t & 31;
#pragma unroll
    for (int i = 0; i < 4; i++)
        s[kr + i * 8][pc] = Xb[(size_t)(kr + i * 8) * 1024 + pc];
    __syncthreads();
    int pr = t >> 3, kq = t & 7;
    u64 hp = 0, lp = 0;
#pragma unroll
    for (int j = 0; j < 4; j++) {
        float vv = s[kq * 4 + j][pr];
        __nv_bfloat16 h = __float2bfloat16(vv);
        __nv_bfloat16 lo = __float2bfloat16(vv - __bfloat162float(h));
        hp |= (u64)__bfloat16_as_ushort(h)  << (16 * j);
        lp |= (u64)__bfloat16_as_ushort(lo) << (16 * j);
    }
    size_t o = ((size_t)bz * 1024 + pt * 32 + pr) * 256 + kt * 32 + kq * 4;
    *(u64*)(hiT + o) = hp;
    *(u64*)(loT + o) = lp;
}

// ---------------------------------------------------------------------------
// HMMA GEMM: C[bz][o][p] = sum_k W[g][o][k] * X[bz][k][p], 3-pass bf16 split.
// CTA 128(o) x 128(p), 256 thr = 8 warps (2x4), warp tile 64x32.
// 12 stages (3 passes x 4 k-chunks of 64), double-buffered smem.
// smem: A bufs 2x16KB @0, B bufs 2x16KB @32768. ldmatrix with SW128 swizzle.
// ---------------------------------------------------------------------------
__global__ __launch_bounds__(256) void hgemm_kernel(
    const __nv_bfloat16* __restrict__ whi, const __nv_bfloat16* __restrict__ wlo,
    const __nv_bfloat16* __restrict__ xhiT, const __nv_bfloat16* __restrict__ xloT,
    const float* __restrict__ bias, float* __restrict__ C, int relu)
{
    extern __shared__ char smem[];
    uint32_t sbase = smem_u32(smem);

    int t  = threadIdx.x;
    int wi = t >> 5, l = t & 31;
    int wo = wi >> 2, wp = wi & 3;
    int p0 = blockIdx.x * 128, o0 = blockIdx.y * 128;
    int bz = blockIdx.z, g = bz & 7;

    const __nv_bfloat16* Ahi = whi  + (size_t)g  * 65536;
    const __nv_bfloat16* Alo = wlo  + (size_t)g  * 65536;
    const __nv_bfloat16* Bhi = xhiT + (size_t)bz * 262144;
    const __nv_bfloat16* Blo = xloT + (size_t)bz * 262144;

    float acc[4][4][4];
#pragma unroll
    for (int i = 0; i < 4; i++)
#pragma unroll
        for (int j = 0; j < 4; j++)
#pragma unroll
            for (int r = 0; r < 4; r++) acc[i][j][r] = 0.f;

    // per-thread staging indices (same for loads and smem stores)
    int rowi[4], kqi[4], swoff[4];
#pragma unroll
    for (int i = 0; i < 4; i++) {
        int v2 = t + i * 256;
        rowi[i] = v2 >> 3; kqi[i] = v2 & 7;
        int off = rowi[i] * 128 + kqi[i] * 16;
        swoff[i] = off ^ ((off >> 3) & 0x70);
    }

    // ldmatrix per-lane base offsets (byte), A and B, before per-ks column add
    // A: row = wo*64 + i*16 + (l&15), colB = (l>>4)*16 + ks*32
    int a_row_l = (l & 15), a_col_l = (l >> 4) << 4;
    // B: n = wp*32 + j2*16 + ((l>>4)&1? no:) quad = l>>3
    int b_quad = l >> 3, b_lr = l & 7;
    int b_row_l = ((b_quad >> 1) << 3) + b_lr;   // + wp*32 + j2*16
    int b_col_l = (b_quad & 1) << 4;             // + ks*32

    // prologue: stage 0 (HH, chunk 0) into buffer 0
    {
#pragma unroll
        for (int i = 0; i < 4; i++) {
            uint4 a  = *(const uint4*)(Ahi + ((size_t)(o0 + rowi[i]) * 256 + kqi[i] * 8));
            uint4 bq = *(const uint4*)(Bhi + ((size_t)(p0 + rowi[i]) * 256 + kqi[i] * 8));
            *(uint4*)(smem + swoff[i])         = a;
            *(uint4*)(smem + 32768 + swoff[i]) = bq;
        }
    }
    __syncthreads();

    for (int s = 0; s < 12; s++) {
        int b = s & 1;
        uint4 ra[4], rb[4];
        if (s < 11) {
            int pass = (s + 1) >> 2, k0 = ((s + 1) & 3) * 64;
            const __nv_bfloat16* As = (pass < 2)  ? Ahi : Alo;   // HH,HL,LH
            const __nv_bfloat16* Bs = (pass == 1) ? Blo : Bhi;
#pragma unroll
            for (int i = 0; i < 4; i++) {
                ra[i] = *(const uint4*)(As + ((size_t)(o0 + rowi[i]) * 256 + k0 + kqi[i] * 8));
                rb[i] = *(const uint4*)(Bs + ((size_t)(p0 + rowi[i]) * 256 + k0 + kqi[i] * 8));
            }
        }
        // compute on buffer b
        uint32_t sa = sbase + b * 16384;
        uint32_t sb = sbase + 32768 + b * 16384;
#pragma unroll
        for (int ks = 0; ks < 4; ks++) {
            uint32_t af[4][4];
#pragma unroll
            for (int i = 0; i < 4; i++) {
                int row = wo * 64 + i * 16 + a_row_l;
                int off = row * 128 + ks * 32 + a_col_l;
                ldsm4(af[i], sa + (off ^ ((off >> 3) & 0x70)));
            }
            uint32_t bfr[2][4];
#pragma unroll
            for (int j2 = 0; j2 < 2; j2++) {
                int n = wp * 32 + j2 * 16 + b_row_l;
                int off = n * 128 + ks * 32 + b_col_l;
                ldsm4(bfr[j2], sb + (off ^ ((off >> 3) & 0x70)));
            }
#pragma unroll
            for (int i = 0; i < 4; i++)
#pragma unroll
                for (int j = 0; j < 4; j++)
                    mma_bf16(acc[i][j], af[i], bfr[j >> 1][(j & 1) * 2],
                             bfr[j >> 1][(j & 1) * 2 + 1]);
        }
        if (s < 11) {
            int nb = b ^ 1;
#pragma unroll
            for (int i = 0; i < 4; i++) {
                *(uint4*)(smem + nb * 16384 + swoff[i])         = ra[i];
                *(uint4*)(smem + 32768 + nb * 16384 + swoff[i]) = rb[i];
            }
            __syncthreads();
        }
    }

    // epilogue: direct float2 stores with bias/relu
    float* Cb = C + (size_t)bz * 256 * 1024;
#pragma unroll
    for (int i = 0; i < 4; i++) {
        int row = o0 + wo * 64 + i * 16 + (l >> 2);
        float b0 = bias ? bias[g * 256 + row]     : 0.f;
        float b8 = bias ? bias[g * 256 + row + 8] : 0.f;
#pragma unroll
        for (int j = 0; j < 4; j++) {
            int col = p0 + wp * 32 + j * 8 + (l & 3) * 2;
            float2 v0 = make_float2(acc[i][j][0] + b0, acc[i][j][1] + b0);
            float2 v1 = make_float2(acc[i][j][2] + b8, acc[i][j][3] + b8);
            if (relu) {
                v0.x = fmaxf(v0.x, 0.f); v0.y = fmaxf(v0.y, 0.f);
                v1.x = fmaxf(v1.x, 0.f); v1.y = fmaxf(v1.y, 0.f);
            }
            *(float2*)(Cb + (size_t)row * 1024 + col)       = v0;
            *(float2*)(Cb + (size_t)(row + 8) * 1024 + col) = v1;
        }
    }
}

// ---------------------------------------------------------------------------
// Windowed attention (R3 winner, unchanged).
// ---------------------------------------------------------------------------
#define HPS 548
#define EPS 68
#define QPS 548
#define OPS 522
#define SK_F   (40*HPS)
#define SQ_F   (16*QPS)
#define REL_F  (12*EPS)

__global__ __launch_bounds__(512) void attn_kernel(
    const float* __restrict__ q, const float* __restrict__ k,
    const float* __restrict__ v, const float* __restrict__ hm,
    const float* __restrict__ wmm, float* __restrict__ outp)
{
    extern __shared__ float smemf[];
    float* sk   = smemf;
    float* sv   = sk + SK_F;
    float* sq   = sv + SK_F;
    float* srh  = sq + SQ_F;
    float* srw  = srh + REL_F;
    float* attd = sk;
    float* sout = sq;

    int t  = threadIdx.x;
    int w0 = blockIdx.x << 3;
    int h0 = blockIdx.y << 1;
    int nm = blockIdx.z;
    int n  = nm >> 2, m = nm & 3;

    for (int idx = t; idx < 20480; idx += 512) {
        int c   = idx % 10;
        int red = idx / 10;
        int d   = red & 63;
        int e   = (red >> 6) & 7;
        int r   = red >> 9;
        int h2 = h0 + r - 1, w2 = w0 + c - 1;
        float kv = 0.f, vv = 0.f;
        if (h2 >= 0 && h2 < 32 && w2 >= 0 && w2 < 32) {
            size_t gi = (((size_t)(n * 8 + e) * 256) + m * 64 + d) * 1024 + h2 * 32 + w2;
            kv = k[gi]; vv = v[gi];
        }
        int si = (r * 10 + c) * HPS + e * EPS + d;
        sk[si] = kv; sv[si] = vv;
    }
    for (int idx = t; idx < 8192; idx += 512) {
        int pix = idx & 15, gd = idx >> 4;
        int gq = gd >> 6, d = gd & 63;
        int pr = pix >> 3, pc = pix & 7;
        size_t gi = (((size_t)(n * 8 + gq) * 256) + m * 64 + d) * 1024
                    + (h0 + pr) * 32 + w0 + pc;
        sq[pix * QPS + gq * EPS + d] = q[gi];
    }
    for (int idx = t; idx < 768; idx += 512) {
        int d  = idx & 63;
        int ei = idx >> 6;
        int e  = ei / 3, i = ei % 3;
        srh[ei * EPS + d] = hm [((e * 256 + m * 64 + d) * 3) + i];
        srw[ei * EPS + d] = wmm[((e * 256 + m * 64 + d) * 3) + i];
    }
    __syncthreads();

    int wi = t >> 5, l = t & 31;
    int g  = l >> 2, e0 = l & 3;
    int pr = wi >> 3, cc = (wi & 7) + 1;
    const float* sqw = sq + wi * QPS + g * EPS;
    int eoff = e0 * EPS;

    int posoff[9];
#pragma unroll
    for (int i = 0; i < 3; i++)
#pragma unroll
        for (int j = 0; j < 3; j++)
            posoff[i * 3 + j] = ((pr + i) * 10 + cc - 1 + j) * HPS;

    u64 hA[3] = {0,0,0}, hB[3] = {0,0,0};
#pragma unroll 4
    for (int dd = 0; dd < 64; dd += 4) {
        ulonglong2 q2 = *(const ulonglong2*)(sqw + dd);
#pragma unroll
        for (int u = 0; u < 3; u++) {
            ulonglong2 r2 = *(const ulonglong2*)(srh + (e0 * 3 + u) * EPS + dd);
            ulonglong2 s2 = *(const ulonglong2*)(srw + (e0 * 3 + u) * EPS + dd);
            fma2(hA[u], q2.x, r2.x); fma2(hA[u], q2.y, r2.y);
            fma2(hB[u], q2.x, s2.x); fma2(hB[u], q2.y, s2.y);
        }
    }
    float qrA[3], qrB[3];
#pragma unroll
    for (int u = 0; u < 3; u++) {
        float2 fa = upk(hA[u]), fb = upk(hB[u]);
        qrA[u] = fa.x + fa.y; qrB[u] = fb.x + fb.y;
    }

    u64 cA[9], cB[9];
#pragma unroll
    for (int u = 0; u < 9; u++) { cA[u] = 0ull; cB[u] = 0ull; }
#pragma unroll 2
    for (int dd = 0; dd < 64; dd += 4) {
        ulonglong2 q2 = *(const ulonglong2*)(sqw + dd);
#pragma unroll
        for (int u = 0; u < 9; u++) {
            const float* kp = sk + posoff[u] + eoff + dd;
            ulonglong2 ka = *(const ulonglong2*)(kp);
            ulonglong2 kc = *(const ulonglong2*)(kp + 4 * EPS);
            fma2(cA[u], q2.x, ka.x); fma2(cA[u], q2.y, ka.y);
            fma2(cB[u], q2.x, kc.x); fma2(cB[u], q2.y, kc.y);
        }
    }
    float sA[9], sB[9];
#pragma unroll
    for (int u = 0; u < 9; u++) {
        float2 fa = upk(cA[u]), fb = upk(cB[u]);
        sA[u] = fa.x + fa.y + qrA[u / 3];
        sB[u] = fb.x + fb.y + qrB[u % 3];
    }

    float mx = -1e30f;
#pragma unroll
    for (int u = 0; u < 9; u++) mx = fmaxf(mx, fmaxf(sA[u], sB[u]));
    mx = fmaxf(mx, __shfl_xor_sync(0xffffffffu, mx, 1));
    mx = fmaxf(mx, __shfl_xor_sync(0xffffffffu, mx, 2));
    float sum = 0.f;
#pragma unroll
    for (int u = 0; u < 9; u++) {
        sA[u] = __expf(sA[u] - mx);
        sB[u] = __expf(sB[u] - mx);
        sum += sA[u] + sB[u];
    }
    sum += __shfl_xor_sync(0xffffffffu, sum, 1);
    sum += __shfl_xor_sync(0xffffffffu, sum, 2);
    float inv = 1.f / sum;

    __syncthreads();

    float* awT = attd + wi * 1152;
#pragma unroll
    for (int u = 0; u < 9; u++) {
        float wa = sA[u] * inv, wb = sB[u] * inv;
        *(float2*)(awT + ((e0 * 9 + u) * 8 + g) * 2)       = make_float2(wa, wa);
        *(float2*)(awT + (((e0 + 4) * 9 + u) * 8 + g) * 2) = make_float2(wb, wb);
    }
    __syncwarp();

    u64 acc[8];
#pragma unroll
    for (int gg = 0; gg < 8; gg++) acc[gg] = 0ull;
#pragma unroll 1
    for (int e = 0; e < 8; e++) {
        const float* vb = sv + e * EPS + 2 * l;
#pragma unroll
        for (int nb = 0; nb < 9; nb++) {
            u64 v2 = *(const u64*)(vb + posoff[nb]);
            const ulonglong2* wp2 = (const ulonglong2*)(awT + (e * 9 + nb) * 16);
            ulonglong2 w01 = wp2[0], w23 = wp2[1], w45 = wp2[2], w67 = wp2[3];
            fma2(acc[0], w01.x, v2); fma2(acc[1], w01.y, v2);
            fma2(acc[2], w23.x, v2); fma2(acc[3], w23.y, v2);
            fma2(acc[4], w45.x, v2); fma2(acc[5], w45.y, v2);
            fma2(acc[6], w67.x, v2); fma2(acc[7], w67.y, v2);
        }
    }
    float* so = sout + wi * OPS;
#pragma unroll
    for (int gg = 0; gg < 8; gg++) {
        float2 f = upk(acc[gg]);
        *(float2*)(so + gg * 64 + 2 * l) = f;
    }
    __syncthreads();

#pragma unroll
    for (int it = 0; it < 4; it++) {
        int idx = t + it * 512;
        int quad = idx & 1, row = (idx >> 1) & 1, ch = idx >> 2;
        int g2 = ch >> 6, d2 = ch & 63;
        int pb = row * 8 + quad * 4;
        float4 o;
        o.x = sout[(pb + 0) * OPS + ch];
        o.y = sout[(pb + 1) * OPS + ch];
        o.z = sout[(pb + 2) * OPS + ch];
        o.w = sout[(pb + 3) * OPS + ch];
        size_t ob = (((size_t)(n * 8 + g2) * 256) + m * 64 + d2) * 1024
                    + (h0 + row) * 32 + w0 + quad * 4;
        *(float4*)(outp + ob) = o;
    }
}

// ---------------------------------------------------------------------------
// Fused skip + LayerNorm (unchanged).
// ---------------------------------------------------------------------------
__global__ __launch_bounds__(256) void ln_kernel(
    const float* __restrict__ X, const float* __restrict__ Y,
    const float* __restrict__ gamma, const float* __restrict__ beta,
    float* __restrict__ T)
{
    __shared__ float sx[64][33];
    int t  = threadIdx.x;
    int p0 = blockIdx.x << 5;
    int gm = blockIdx.y;
    int g  = gm >> 2, m = gm & 3;
    int n  = blockIdx.z;
    size_t base = (((size_t)(n * 8 + g) * 256) + m * 64) * 1024 + p0;
    int pp = t & 31;
#pragma unroll
    for (int pass = 0; pass < 8; pass++) {
        int d = (t >> 5) + pass * 8;
        sx[d][pp] = X[base + (size_t)d * 1024 + pp] + Y[base + (size_t)d * 1024 + pp];
    }
    __syncthreads();
    int c = t >> 3, sub = t & 7;
    float s1 = 0.f, s2 = 0.f;
#pragma unroll
    for (int u = 0; u < 8; u++) {
        float vv = sx[sub * 8 + u][c];
        s1 += vv; s2 += vv * vv;
    }
#pragma unroll
    for (int off = 1; off < 8; off <<= 1) {
        s1 += __shfl_xor_sync(0xffffffffu, s1, off);
        s2 += __shfl_xor_sync(0xffffffffu, s2, off);
    }
    float mu  = s1 * 0.015625f;
    float var = s2 * 0.015625f - mu * mu;
    float inv = rsqrtf(var + 1e-5f);
    float* op = T + ((((size_t)n * 1024 + p0 + c) * 4 + m) * 8 + g) * 64;
#pragma unroll
    for (int u = 0; u < 8; u++) {
        int d = sub * 8 + u;
        op[d] = (sx[d][c] - mu) * inv * gamma[d] + beta[d];
    }
}

// ---------------------------------------------------------------------------
extern "C" void kernel_launch(void* const* d_in, const int* in_sizes, int n_in,
                              void* d_out, int out_size)
{
    (void)in_sizes; (void)n_in; (void)out_size;
    const float* x     = (const float*)d_in[0];
    const float* wq    = (const float*)d_in[1];
    const float* wk    = (const float*)d_in[2];
    const float* wv    = (const float*)d_in[3];
    const float* hm    = (const float*)d_in[4];
    const float* wm    = (const float*)d_in[5];
    const float* wconv = (const float*)d_in[6];
    const float* bconv = (const float*)d_in[7];
    const float* wf1   = (const float*)d_in[8];
    const float* bf1   = (const float*)d_in[9];
    const float* wf2   = (const float*)d_in[10];
    const float* bf2   = (const float*)d_in[11];
    const float* g1    = (const float*)d_in[12];
    const float* b1    = (const float*)d_in[13];
    const float* g2    = (const float*)d_in[14];
    const float* b2    = (const float*)d_in[15];

    float *q, *k, *v, *av, *y, *tb, *h1, *f;
    __nv_bfloat16 *xhiT, *xloT, *whi, *wlo;
    cudaGetSymbolAddress((void**)&q,  g_q);
    cudaGetSymbolAddress((void**)&k,  g_k);
    cudaGetSymbolAddress((void**)&v,  g_v);
    cudaGetSymbolAddress((void**)&av, g_av);
    cudaGetSymbolAddress((void**)&y,  g_y);
    cudaGetSymbolAddress((void**)&tb, g_t);
    cudaGetSymbolAddress((void**)&h1, g_h1);
    cudaGetSymbolAddress((void**)&f,  g_f);
    cudaGetSymbolAddress((void**)&xhiT, g_xhiT);
    cudaGetSymbolAddress((void**)&xloT, g_xloT);
    cudaGetSymbolAddress((void**)&whi,  g_whi);
    cudaGetSymbolAddress((void**)&wlo,  g_wlo);

    const int ATTN_SMEM = (SK_F * 2 + SQ_F + REL_F * 2) * 4;   // 216960 B
    cudaFuncSetAttribute(attn_kernel,
                         cudaFuncAttributeMaxDynamicSharedMemorySize, ATTN_SMEM);
    const int GEMM_SMEM = 65536;
    cudaFuncSetAttribute(hgemm_kernel,
                         cudaFuncAttributeMaxDynamicSharedMemorySize, GEMM_SMEM);

    const size_t WS = 524288;  // per-slot W elements
    dim3 ggrid(8, 2, 32);
    dim3 cxgrid(32, 8, 32);

    convw_kernel<<<dim3(512, 6), 256>>>(wq, wk, wv, wconv, wf1, wf2, whi, wlo);
    convx_kernel<<<cxgrid, 256>>>(x, xhiT, xloT);

    hgemm_kernel<<<ggrid, 256, GEMM_SMEM>>>(whi + 0*WS, wlo + 0*WS, xhiT, xloT, nullptr, q, 0);
    hgemm_kernel<<<ggrid, 256, GEMM_SMEM>>>(whi + 1*WS, wlo + 1*WS, xhiT, xloT, nullptr, k, 0);
    hgemm_kernel<<<ggrid, 256, GEMM_SMEM>>>(whi + 2*WS, wlo + 2*WS, xhiT, xloT, nullptr, v, 0);

    attn_kernel<<<dim3(4, 16, 16), 512, ATTN_SMEM>>>(q, k, v, hm, wm, av);

    convx_kernel<<<cxgrid, 256>>>(av, xhiT, xloT);
    hgemm_kernel<<<ggrid, 256, GEMM_SMEM>>>(whi + 3*WS, wlo + 3*WS, xhiT, xloT, bconv, y, 0);
    ln_kernel<<<dim3(32, 32, 4), 256>>>(x, y, g1, b1, tb);

    convx_kernel<<<cxgrid, 256>>>(tb, xhiT, xloT);
    hgemm_kernel<<<ggrid, 256, GEMM_SMEM>>>(whi + 4*WS, wlo + 4*WS, xhiT, xloT, bf1, h1, 1);

    convx_kernel<<<cxgrid, 256>>>(h1, xhiT, xloT);
    hgemm_kernel<<<ggrid, 256, GEMM_SMEM>>>(whi + 5*WS, wlo + 5*WS, xhiT, xloT, bf2, f, 0);

    ln_kernel<<<dim3(32, 32, 4), 256>>>(tb, f, g2, b2, (float*)d_out);
}

// round 6
// speedup vs baseline: 2.2469x; 1.0329x over previous
#include <cuda_runtime.h>
#include <cuda_bf16.h>
#include <cstdint>

#define HWP 1024

// fp32 scratch
__device__ float g_q [4*8*256*HWP];
__device__ float g_k [4*8*256*HWP];
__device__ float g_v [4*8*256*HWP];
__device__ float g_y [4*8*256*HWP];
__device__ float g_t [4*8*256*HWP];
__device__ float g_h1[4*8*256*HWP];
__device__ float g_f [4*8*256*HWP];
// bf16 split operands
__device__ __nv_bfloat16 g_xhiT[32*1024*256];   // [bz][p][k]
__device__ __nv_bfloat16 g_xloT[32*1024*256];
__device__ __nv_bfloat16 g_whi [6*8*256*256];   // [slot][g][o][k]
__device__ __nv_bfloat16 g_wlo [6*8*256*256];

typedef unsigned long long u64;
__device__ __forceinline__ u64 pk2(float x, float y) {
    u64 r; asm("mov.b64 %0, {%1, %2};" : "=l"(r) : "f"(x), "f"(y)); return r;
}
__device__ __forceinline__ void fma2(u64& d, u64 a, u64 b) {
    asm("fma.rn.f32x2 %0, %1, %2, %3;" : "=l"(d) : "l"(a), "l"(b), "l"(d));
}
__device__ __forceinline__ float2 upk(u64 v) {
    float2 f; asm("mov.b64 {%0, %1}, %2;" : "=f"(f.x), "=f"(f.y) : "l"(v)); return f;
}

__device__ __forceinline__ uint32_t smem_u32(const void* p) {
    uint32_t a;
    asm("{ .reg .u64 tmp; cvta.to.shared.u64 tmp, %1; cvt.u32.u64 %0, tmp; }"
        : "=r"(a) : "l"(p));
    return a;
}
__device__ __forceinline__ void ldsm4(uint32_t* r, uint32_t addr) {
    asm volatile("ldmatrix.sync.aligned.m8n8.x4.shared.b16 {%0,%1,%2,%3}, [%4];"
        : "=r"(r[0]), "=r"(r[1]), "=r"(r[2]), "=r"(r[3]) : "r"(addr));
}
__device__ __forceinline__ void mma_bf16(float* c, const uint32_t* a,
                                         uint32_t b0, uint32_t b1) {
    asm volatile("mma.sync.aligned.m16n8k16.row.col.f32.bf16.bf16.f32 "
        "{%0,%1,%2,%3}, {%4,%5,%6,%7}, {%8,%9}, {%0,%1,%2,%3};"
        : "+f"(c[0]), "+f"(c[1]), "+f"(c[2]), "+f"(c[3])
        : "r"(a[0]), "r"(a[1]), "r"(a[2]), "r"(a[3]), "r"(b0), "r"(b1));
}
__device__ __forceinline__ void cpasync16(uint32_t saddr, const void* g) {
    asm volatile("cp.async.cg.shared.global [%0], [%1], 16;" :: "r"(saddr), "l"(g));
}
#define CP_COMMIT() asm volatile("cp.async.commit_group;" ::: "memory")

// split helper
__device__ __forceinline__ void bfsplit(float x, unsigned short& h, unsigned short& l2) {
    __nv_bfloat16 h0 = __float2bfloat16(x);
    __nv_bfloat16 l0 = __float2bfloat16(x - __bfloat162float(h0));
    h = __bfloat16_as_ushort(h0); l2 = __bfloat16_as_ushort(l0);
}

// ---------------------------------------------------------------------------
// Split fp32 W [g][o][k] into hi/lo bf16. grid (512, 6)
// ---------------------------------------------------------------------------
__global__ __launch_bounds__(256) void convw_kernel(
    const float* __restrict__ w0, const float* __restrict__ w1,
    const float* __restrict__ w2, const float* __restrict__ w3,
    const float* __restrict__ w4, const float* __restrict__ w5,
    __nv_bfloat16* __restrict__ whi, __nv_bfloat16* __restrict__ wlo)
{
    const float* srcs[6] = {w0, w1, w2, w3, w4, w5};
    int slot = blockIdx.y;
    size_t idx = ((size_t)blockIdx.x * 256 + threadIdx.x) * 4;
    float4 v = *(const float4*)(srcs[slot] + idx);
    float vv[4] = {v.x, v.y, v.z, v.w};
    u64 hp = 0, lp = 0;
#pragma unroll
    for (int j = 0; j < 4; j++) {
        unsigned short h, l2; bfsplit(vv[j], h, l2);
        hp |= (u64)h  << (16 * j);
        lp |= (u64)l2 << (16 * j);
    }
    size_t o = (size_t)slot * 524288 + idx;
    *(u64*)(whi + o) = hp;
    *(u64*)(wlo + o) = lp;
}

// ---------------------------------------------------------------------------
// Transpose + split: X [bz][k=256][p=1024] fp32 -> hiT/loT [bz][p][k] bf16.
// ---------------------------------------------------------------------------
__global__ __launch_bounds__(256) void convx_kernel(
    const float* __restrict__ X,
    __nv_bfloat16* __restrict__ hiT, __nv_bfloat16* __restrict__ loT)
{
    __shared__ float s[32][33];
    int t = threadIdx.x;
    int pt = blockIdx.x, kt = blockIdx.y, bz = blockIdx.z;
    const float* Xb = X + ((size_t)bz * 256 + kt * 32) * 1024 + pt * 32;
    int kr = t >> 5, pc = t & 31;
#pragma unroll
    for (int i = 0; i < 4; i++)
        s[kr + i * 8][pc] = Xb[(size_t)(kr + i * 8) * 1024 + pc];
    __syncthreads();
    int pr = t >> 3, kq = t & 7;
    u64 hp = 0, lp = 0;
#pragma unroll
    for (int j = 0; j < 4; j++) {
        unsigned short h, l2; bfsplit(s[kq * 4 + j][pr], h, l2);
        hp |= (u64)h  << (16 * j);
        lp |= (u64)l2 << (16 * j);
    }
    size_t o = ((size_t)bz * 1024 + pt * 32 + pr) * 256 + kt * 32 + kq * 4;
    *(u64*)(hiT + o) = hp;
    *(u64*)(loT + o) = lp;
}

// ---------------------------------------------------------------------------
// HMMA GEMM with cp.async 3-stage ring.
// C[bz][o][p] = sum_k W[g][o][k] * X[bz][k][p], 3-pass bf16 split.
// CTA 128x128, 8 warps (2x4), warp tile 64x32. 12 stages (3 passes x 4 k64).
// smem: A ring 3x16KB @0, B ring 3x16KB @49152 (total 96KB).
// ---------------------------------------------------------------------------
__global__ __launch_bounds__(256) void hgemm_kernel(
    const __nv_bfloat16* __restrict__ whi, const __nv_bfloat16* __restrict__ wlo,
    const __nv_bfloat16* __restrict__ xhiT, const __nv_bfloat16* __restrict__ xloT,
    const float* __restrict__ bias, float* __restrict__ C, int relu)
{
    extern __shared__ char smem[];
    uint32_t sbase = smem_u32(smem);

    int t  = threadIdx.x;
    int wi = t >> 5, l = t & 31;
    int wo = wi >> 2, wp = wi & 3;
    int p0 = blockIdx.x * 128, o0 = blockIdx.y * 128;
    int bz = blockIdx.z, g = bz & 7;

    const __nv_bfloat16* Ahi = whi  + (size_t)g  * 65536;
    const __nv_bfloat16* Alo = wlo  + (size_t)g  * 65536;
    const __nv_bfloat16* Bhi = xhiT + (size_t)bz * 262144;
    const __nv_bfloat16* Blo = xloT + (size_t)bz * 262144;

    float acc[4][4][4];
#pragma unroll
    for (int i = 0; i < 4; i++)
#pragma unroll
        for (int j = 0; j < 4; j++)
#pragma unroll
            for (int r = 0; r < 4; r++) acc[i][j][r] = 0.f;

    int rowi[4], kqi[4], swoff[4];
#pragma unroll
    for (int i = 0; i < 4; i++) {
        int v2 = t + i * 256;
        rowi[i] = v2 >> 3; kqi[i] = v2 & 7;
        int off = rowi[i] * 128 + kqi[i] * 16;
        swoff[i] = off ^ ((off >> 3) & 0x70);
    }

    int a_row_l = (l & 15), a_col_l = (l >> 4) << 4;
    int b_quad = l >> 3, b_lr = l & 7;
    int b_row_l = ((b_quad >> 1) << 3) + b_lr;
    int b_col_l = (b_quad & 1) << 4;

#define ISSUE_STAGE(s) do {                                                    \
        int pass_ = (s) >> 2, k0_ = ((s) & 3) * 64;                            \
        const __nv_bfloat16* As_ = (pass_ < 2)  ? Ahi : Alo;                   \
        const __nv_bfloat16* Bs_ = (pass_ == 1) ? Blo : Bhi;                   \
        uint32_t sa_ = sbase + ((s) % 3) * 16384;                              \
        uint32_t sb_ = sbase + 49152 + ((s) % 3) * 16384;                      \
        _Pragma("unroll")                                                      \
        for (int i_ = 0; i_ < 4; i_++) {                                       \
            cpasync16(sa_ + swoff[i_],                                         \
                As_ + ((size_t)(o0 + rowi[i_]) * 256 + k0_ + kqi[i_] * 8));    \
            cpasync16(sb_ + swoff[i_],                                         \
                Bs_ + ((size_t)(p0 + rowi[i_]) * 256 + k0_ + kqi[i_] * 8));    \
        }                                                                      \
        CP_COMMIT();                                                           \
    } while (0)

    ISSUE_STAGE(0);
    ISSUE_STAGE(1);

    for (int s = 0; s < 12; s++) {
        if (s < 11) asm volatile("cp.async.wait_group 1;" ::: "memory");
        else        asm volatile("cp.async.wait_group 0;" ::: "memory");
        __syncthreads();
        if (s < 10) ISSUE_STAGE(s + 2);

        uint32_t sa = sbase + (s % 3) * 16384;
        uint32_t sb = sbase + 49152 + (s % 3) * 16384;
#pragma unroll
        for (int ks = 0; ks < 4; ks++) {
            uint32_t af[4][4];
#pragma unroll
            for (int i = 0; i < 4; i++) {
                int row = wo * 64 + i * 16 + a_row_l;
                int off = row * 128 + ks * 32 + a_col_l;
                ldsm4(af[i], sa + (off ^ ((off >> 3) & 0x70)));
            }
            uint32_t bfr[2][4];
#pragma unroll
            for (int j2 = 0; j2 < 2; j2++) {
                int n = wp * 32 + j2 * 16 + b_row_l;
                int off = n * 128 + ks * 32 + b_col_l;
                ldsm4(bfr[j2], sb + (off ^ ((off >> 3) & 0x70)));
            }
#pragma unroll
            for (int i = 0; i < 4; i++)
#pragma unroll
                for (int j = 0; j < 4; j++)
                    mma_bf16(acc[i][j], af[i], bfr[j >> 1][(j & 1) * 2],
                             bfr[j >> 1][(j & 1) * 2 + 1]);
        }
    }
#undef ISSUE_STAGE

    // epilogue: direct float2 stores with bias/relu
    float* Cb = C + (size_t)bz * 256 * 1024;
#pragma unroll
    for (int i = 0; i < 4; i++) {
        int row = o0 + wo * 64 + i * 16 + (l >> 2);
        float b0 = bias ? bias[g * 256 + row]     : 0.f;
        float b8 = bias ? bias[g * 256 + row + 8] : 0.f;
#pragma unroll
        for (int j = 0; j < 4; j++) {
            int col = p0 + wp * 32 + j * 8 + (l & 3) * 2;
            float2 v0 = make_float2(acc[i][j][0] + b0, acc[i][j][1] + b0);
            float2 v1 = make_float2(acc[i][j][2] + b8, acc[i][j][3] + b8);
            if (relu) {
                v0.x = fmaxf(v0.x, 0.f); v0.y = fmaxf(v0.y, 0.f);
                v1.x = fmaxf(v1.x, 0.f); v1.y = fmaxf(v1.y, 0.f);
            }
            *(float2*)(Cb + (size_t)row * 1024 + col)       = v0;
            *(float2*)(Cb + (size_t)(row + 8) * 1024 + col) = v1;
        }
    }
}

// ---------------------------------------------------------------------------
// Windowed attention; epilogue now writes bf16 hi/lo split transposed
// [bz][p][k] directly (feeds GEMM#4, no fp32 av round trip).
// ---------------------------------------------------------------------------
#define HPS 548
#define EPS 68
#define QPS 548
#define OPS 522
#define SK_F   (40*HPS)
#define SQ_F   (16*QPS)
#define REL_F  (12*EPS)

__global__ __launch_bounds__(512) void attn_kernel(
    const float* __restrict__ q, const float* __restrict__ k,
    const float* __restrict__ v, const float* __restrict__ hm,
    const float* __restrict__ wmm,
    __nv_bfloat16* __restrict__ avhiT, __nv_bfloat16* __restrict__ avloT)
{
    extern __shared__ float smemf[];
    float* sk   = smemf;
    float* sv   = sk + SK_F;
    float* sq   = sv + SK_F;
    float* srh  = sq + SQ_F;
    float* srw  = srh + REL_F;
    float* attd = sk;
    float* sout = sq;

    int t  = threadIdx.x;
    int w0 = blockIdx.x << 3;
    int h0 = blockIdx.y << 1;
    int nm = blockIdx.z;
    int n  = nm >> 2, m = nm & 3;

    for (int idx = t; idx < 20480; idx += 512) {
        int c   = idx % 10;
        int red = idx / 10;
        int d   = red & 63;
        int e   = (red >> 6) & 7;
        int r   = red >> 9;
        int h2 = h0 + r - 1, w2 = w0 + c - 1;
        float kv = 0.f, vv = 0.f;
        if (h2 >= 0 && h2 < 32 && w2 >= 0 && w2 < 32) {
            size_t gi = (((size_t)(n * 8 + e) * 256) + m * 64 + d) * 1024 + h2 * 32 + w2;
            kv = k[gi]; vv = v[gi];
        }
        int si = (r * 10 + c) * HPS + e * EPS + d;
        sk[si] = kv; sv[si] = vv;
    }
    for (int idx = t; idx < 8192; idx += 512) {
        int pix = idx & 15, gd = idx >> 4;
        int gq = gd >> 6, d = gd & 63;
        int pr = pix >> 3, pc = pix & 7;
        size_t gi = (((size_t)(n * 8 + gq) * 256) + m * 64 + d) * 1024
                    + (h0 + pr) * 32 + w0 + pc;
        sq[pix * QPS + gq * EPS + d] = q[gi];
    }
    for (int idx = t; idx < 768; idx += 512) {
        int d  = idx & 63;
        int ei = idx >> 6;
        int e  = ei / 3, i = ei % 3;
        srh[ei * EPS + d] = hm [((e * 256 + m * 64 + d) * 3) + i];
        srw[ei * EPS + d] = wmm[((e * 256 + m * 64 + d) * 3) + i];
    }
    __syncthreads();

    int wi = t >> 5, l = t & 31;
    int g  = l >> 2, e0 = l & 3;
    int pr = wi >> 3, cc = (wi & 7) + 1;
    const float* sqw = sq + wi * QPS + g * EPS;
    int eoff = e0 * EPS;

    int posoff[9];
#pragma unroll
    for (int i = 0; i < 3; i++)
#pragma unroll
        for (int j = 0; j < 3; j++)
            posoff[i * 3 + j] = ((pr + i) * 10 + cc - 1 + j) * HPS;

    u64 hA[3] = {0,0,0}, hB[3] = {0,0,0};
#pragma unroll 4
    for (int dd = 0; dd < 64; dd += 4) {
        ulonglong2 q2 = *(const ulonglong2*)(sqw + dd);
#pragma unroll
        for (int u = 0; u < 3; u++) {
            ulonglong2 r2 = *(const ulonglong2*)(srh + (e0 * 3 + u) * EPS + dd);
            ulonglong2 s2 = *(const ulonglong2*)(srw + (e0 * 3 + u) * EPS + dd);
            fma2(hA[u], q2.x, r2.x); fma2(hA[u], q2.y, r2.y);
            fma2(hB[u], q2.x, s2.x); fma2(hB[u], q2.y, s2.y);
        }
    }
    float qrA[3], qrB[3];
#pragma unroll
    for (int u = 0; u < 3; u++) {
        float2 fa = upk(hA[u]), fb = upk(hB[u]);
        qrA[u] = fa.x + fa.y; qrB[u] = fb.x + fb.y;
    }

    u64 cA[9], cB[9];
#pragma unroll
    for (int u = 0; u < 9; u++) { cA[u] = 0ull; cB[u] = 0ull; }
#pragma unroll 2
    for (int dd = 0; dd < 64; dd += 4) {
        ulonglong2 q2 = *(const ulonglong2*)(sqw + dd);
#pragma unroll
        for (int u = 0; u < 9; u++) {
            const float* kp = sk + posoff[u] + eoff + dd;
            ulonglong2 ka = *(const ulonglong2*)(kp);
            ulonglong2 kc = *(const ulonglong2*)(kp + 4 * EPS);
            fma2(cA[u], q2.x, ka.x); fma2(cA[u], q2.y, ka.y);
            fma2(cB[u], q2.x, kc.x); fma2(cB[u], q2.y, kc.y);
        }
    }
    float sA[9], sB[9];
#pragma unroll
    for (int u = 0; u < 9; u++) {
        float2 fa = upk(cA[u]), fb = upk(cB[u]);
        sA[u] = fa.x + fa.y + qrA[u / 3];
        sB[u] = fb.x + fb.y + qrB[u % 3];
    }

    float mx = -1e30f;
#pragma unroll
    for (int u = 0; u < 9; u++) mx = fmaxf(mx, fmaxf(sA[u], sB[u]));
    mx = fmaxf(mx, __shfl_xor_sync(0xffffffffu, mx, 1));
    mx = fmaxf(mx, __shfl_xor_sync(0xffffffffu, mx, 2));
    float sum = 0.f;
#pragma unroll
    for (int u = 0; u < 9; u++) {
        sA[u] = __expf(sA[u] - mx);
        sB[u] = __expf(sB[u] - mx);
        sum += sA[u] + sB[u];
    }
    sum += __shfl_xor_sync(0xffffffffu, sum, 1);
    sum += __shfl_xor_sync(0xffffffffu, sum, 2);
    float inv = 1.f / sum;

    __syncthreads();

    float* awT = attd + wi * 1152;
#pragma unroll
    for (int u = 0; u < 9; u++) {
        float wa = sA[u] * inv, wb = sB[u] * inv;
        *(float2*)(awT + ((e0 * 9 + u) * 8 + g) * 2)       = make_float2(wa, wa);
        *(float2*)(awT + (((e0 + 4) * 9 + u) * 8 + g) * 2) = make_float2(wb, wb);
    }
    __syncwarp();

    u64 acc[8];
#pragma unroll
    for (int gg = 0; gg < 8; gg++) acc[gg] = 0ull;
#pragma unroll 1
    for (int e = 0; e < 8; e++) {
        const float* vb = sv + e * EPS + 2 * l;
#pragma unroll
        for (int nb = 0; nb < 9; nb++) {
            u64 v2 = *(const u64*)(vb + posoff[nb]);
            const ulonglong2* wp2 = (const ulonglong2*)(awT + (e * 9 + nb) * 16);
            ulonglong2 w01 = wp2[0], w23 = wp2[1], w45 = wp2[2], w67 = wp2[3];
            fma2(acc[0], w01.x, v2); fma2(acc[1], w01.y, v2);
            fma2(acc[2], w23.x, v2); fma2(acc[3], w23.y, v2);
            fma2(acc[4], w45.x, v2); fma2(acc[5], w45.y, v2);
            fma2(acc[6], w67.x, v2); fma2(acc[7], w67.y, v2);
        }
    }
    float* so = sout + wi * OPS;
#pragma unroll
    for (int gg = 0; gg < 8; gg++) {
        float2 f = upk(acc[gg]);
        *(float2*)(so + gg * 64 + 2 * l) = f;
    }
    __syncthreads();

    // transposed bf16 hi/lo store: avT[bz=n*8+g2][p][m*64+d]
#pragma unroll
    for (int it = 0; it < 4; it++) {
        int flat = t + it * 512;            // covers 2048 quads (16pix*8g*16dq)
        int dq  = flat & 15;
        int g2  = (flat >> 4) & 7;
        int pix = flat >> 7;
        const float* src = sout + pix * OPS + g2 * 64 + dq * 4;
        u64 hp = 0, lp = 0;
#pragma unroll
        for (int j = 0; j < 4; j++) {
            unsigned short h, l2; bfsplit(src[j], h, l2);
            hp |= (u64)h  << (16 * j);
            lp |= (u64)l2 << (16 * j);
        }
        int p = (h0 + (pix >> 3)) * 32 + w0 + (pix & 7);
        size_t o = (((size_t)(n * 8 + g2) * 1024) + p) * 256 + m * 64 + dq * 4;
        *(u64*)(avhiT + o) = hp;
        *(u64*)(avloT + o) = lp;
    }
}

// ---------------------------------------------------------------------------
// Fused skip + LayerNorm (unchanged).
// ---------------------------------------------------------------------------
__global__ __launch_bounds__(256) void ln_kernel(
    const float* __restrict__ X, const float* __restrict__ Y,
    const float* __restrict__ gamma, const float* __restrict__ beta,
    float* __restrict__ T)
{
    __shared__ float sx[64][33];
    int t  = threadIdx.x;
    int p0 = blockIdx.x << 5;
    int gm = blockIdx.y;
    int g  = gm >> 2, m = gm & 3;
    int n  = blockIdx.z;
    size_t base = (((size_t)(n * 8 + g) * 256) + m * 64) * 1024 + p0;
    int pp = t & 31;
#pragma unroll
    for (int pass = 0; pass < 8; pass++) {
        int d = (t >> 5) + pass * 8;
        sx[d][pp] = X[base + (size_t)d * 1024 + pp] + Y[base + (size_t)d * 1024 + pp];
    }
    __syncthreads();
    int c = t >> 3, sub = t & 7;
    float s1 = 0.f, s2 = 0.f;
#pragma unroll
    for (int u = 0; u < 8; u++) {
        float vv = sx[sub * 8 + u][c];
        s1 += vv; s2 += vv * vv;
    }
#pragma unroll
    for (int off = 1; off < 8; off <<= 1) {
        s1 += __shfl_xor_sync(0xffffffffu, s1, off);
        s2 += __shfl_xor_sync(0xffffffffu, s2, off);
    }
    float mu  = s1 * 0.015625f;
    float var = s2 * 0.015625f - mu * mu;
    float inv = rsqrtf(var + 1e-5f);
    float* op = T + ((((size_t)n * 1024 + p0 + c) * 4 + m) * 8 + g) * 64;
#pragma unroll
    for (int u = 0; u < 8; u++) {
        int d = sub * 8 + u;
        op[d] = (sx[d][c] - mu) * inv * gamma[d] + beta[d];
    }
}

// ---------------------------------------------------------------------------
extern "C" void kernel_launch(void* const* d_in, const int* in_sizes, int n_in,
                              void* d_out, int out_size)
{
    (void)in_sizes; (void)n_in; (void)out_size;
    const float* x     = (const float*)d_in[0];
    const float* wq    = (const float*)d_in[1];
    const float* wk    = (const float*)d_in[2];
    const float* wv    = (const float*)d_in[3];
    const float* hm    = (const float*)d_in[4];
    const float* wm    = (const float*)d_in[5];
    const float* wconv = (const float*)d_in[6];
    const float* bconv = (const float*)d_in[7];
    const float* wf1   = (const float*)d_in[8];
    const float* bf1   = (const float*)d_in[9];
    const float* wf2   = (const float*)d_in[10];
    const float* bf2   = (const float*)d_in[11];
    const float* g1    = (const float*)d_in[12];
    const float* b1    = (const float*)d_in[13];
    const float* g2    = (const float*)d_in[14];
    const float* b2    = (const float*)d_in[15];

    float *q, *k, *v, *y, *tb, *h1, *f;
    __nv_bfloat16 *xhiT, *xloT, *whi, *wlo;
    cudaGetSymbolAddress((void**)&q,  g_q);
    cudaGetSymbolAddress((void**)&k,  g_k);
    cudaGetSymbolAddress((void**)&v,  g_v);
    cudaGetSymbolAddress((void**)&y,  g_y);
    cudaGetSymbolAddress((void**)&tb, g_t);
    cudaGetSymbolAddress((void**)&h1, g_h1);
    cudaGetSymbolAddress((void**)&f,  g_f);
    cudaGetSymbolAddress((void**)&xhiT, g_xhiT);
    cudaGetSymbolAddress((void**)&xloT, g_xloT);
    cudaGetSymbolAddress((void**)&whi,  g_whi);
    cudaGetSymbolAddress((void**)&wlo,  g_wlo);

    const int ATTN_SMEM = (SK_F * 2 + SQ_F + REL_F * 2) * 4;   // 216960 B
    cudaFuncSetAttribute(attn_kernel,
                         cudaFuncAttributeMaxDynamicSharedMemorySize, ATTN_SMEM);
    const int GEMM_SMEM = 98304;                                // 2x 3x16KB
    cudaFuncSetAttribute(hgemm_kernel,
                         cudaFuncAttributeMaxDynamicSharedMemorySize, GEMM_SMEM);

    const size_t WS = 524288;  // per-slot W elements
    dim3 ggrid(8, 2, 32);
    dim3 cxgrid(32, 8, 32);

    convw_kernel<<<dim3(512, 6), 256>>>(wq, wk, wv, wconv, wf1, wf2, whi, wlo);
    convx_kernel<<<cxgrid, 256>>>(x, xhiT, xloT);

    hgemm_kernel<<<ggrid, 256, GEMM_SMEM>>>(whi + 0*WS, wlo + 0*WS, xhiT, xloT, nullptr, q, 0);
    hgemm_kernel<<<ggrid, 256, GEMM_SMEM>>>(whi + 1*WS, wlo + 1*WS, xhiT, xloT, nullptr, k, 0);
    hgemm_kernel<<<ggrid, 256, GEMM_SMEM>>>(whi + 2*WS, wlo + 2*WS, xhiT, xloT, nullptr, v, 0);

    // attn writes bf16 split transposed directly into xhiT/xloT
    attn_kernel<<<dim3(4, 16, 16), 512, ATTN_SMEM>>>(q, k, v, hm, wm, xhiT, xloT);

    hgemm_kernel<<<ggrid, 256, GEMM_SMEM>>>(whi + 3*WS, wlo + 3*WS, xhiT, xloT, bconv, y, 0);
    ln_kernel<<<dim3(32, 32, 4), 256>>>(x, y, g1, b1, tb);

    convx_kernel<<<cxgrid, 256>>>(tb, xhiT, xloT);
    hgemm_kernel<<<ggrid, 256, GEMM_SMEM>>>(whi + 4*WS, wlo + 4*WS, xhiT, xloT, bf1, h1, 1);

    convx_kernel<<<cxgrid, 256>>>(h1, xhiT, xloT);
    hgemm_kernel<<<ggrid, 256, GEMM_SMEM>>>(whi + 5*WS, wlo + 5*WS, xhiT, xloT, bf2, f, 0);

    ln_kernel<<<dim3(32, 32, 4), 256>>>(tb, f, g2, b2, (float*)d_out);
}

// round 7
// speedup vs baseline: 2.3958x; 1.0663x over previous
#include <cuda_runtime.h>
#include <cuda_bf16.h>
#include <cstdint>

#define HWP 1024

// fp32 scratch
__device__ float g_q [4*8*256*HWP];
__device__ float g_k [4*8*256*HWP];
__device__ float g_v [4*8*256*HWP];
__device__ float g_y [4*8*256*HWP];
__device__ float g_t [4*8*256*HWP];
__device__ float g_h1[4*8*256*HWP];
__device__ float g_f [4*8*256*HWP];
// bf16 split operands
__device__ __nv_bfloat16 g_xhiT[32*1024*256];   // [bz][p][k]
__device__ __nv_bfloat16 g_xloT[32*1024*256];
__device__ __nv_bfloat16 g_whi [6*8*256*256];   // [slot][g][o][k]
__device__ __nv_bfloat16 g_wlo [6*8*256*256];

typedef unsigned long long u64;
__device__ __forceinline__ u64 pk2(float x, float y) {
    u64 r; asm("mov.b64 %0, {%1, %2};" : "=l"(r) : "f"(x), "f"(y)); return r;
}
__device__ __forceinline__ void fma2(u64& d, u64 a, u64 b) {
    asm("fma.rn.f32x2 %0, %1, %2, %3;" : "=l"(d) : "l"(a), "l"(b), "l"(d));
}
__device__ __forceinline__ float2 upk(u64 v) {
    float2 f; asm("mov.b64 {%0, %1}, %2;" : "=f"(f.x), "=f"(f.y) : "l"(v)); return f;
}

__device__ __forceinline__ uint32_t smem_u32(const void* p) {
    uint32_t a;
    asm("{ .reg .u64 tmp; cvta.to.shared.u64 tmp, %1; cvt.u32.u64 %0, tmp; }"
        : "=r"(a) : "l"(p));
    return a;
}
__device__ __forceinline__ void ldsm4(uint32_t* r, uint32_t addr) {
    asm volatile("ldmatrix.sync.aligned.m8n8.x4.shared.b16 {%0,%1,%2,%3}, [%4];"
        : "=r"(r[0]), "=r"(r[1]), "=r"(r[2]), "=r"(r[3]) : "r"(addr));
}
__device__ __forceinline__ void mma_bf16(float* c, const uint32_t* a,
                                         uint32_t b0, uint32_t b1) {
    asm volatile("mma.sync.aligned.m16n8k16.row.col.f32.bf16.bf16.f32 "
        "{%0,%1,%2,%3}, {%4,%5,%6,%7}, {%8,%9}, {%0,%1,%2,%3};"
        : "+f"(c[0]), "+f"(c[1]), "+f"(c[2]), "+f"(c[3])
        : "r"(a[0]), "r"(a[1]), "r"(a[2]), "r"(a[3]), "r"(b0), "r"(b1));
}
__device__ __forceinline__ void cpasync16(uint32_t saddr, const void* g) {
    asm volatile("cp.async.cg.shared.global [%0], [%1], 16;" :: "r"(saddr), "l"(g));
}
#define CP_COMMIT() asm volatile("cp.async.commit_group;" ::: "memory")

// split helper
__device__ __forceinline__ void bfsplit(float x, unsigned short& h, unsigned short& l2) {
    __nv_bfloat16 h0 = __float2bfloat16(x);
    __nv_bfloat16 l0 = __float2bfloat16(x - __bfloat162float(h0));
    h = __bfloat16_as_ushort(h0); l2 = __bfloat16_as_ushort(l0);
}

// ---------------------------------------------------------------------------
// Split fp32 W [g][o][k] into hi/lo bf16. grid (512, 6)
// ---------------------------------------------------------------------------
__global__ __launch_bounds__(256) void convw_kernel(
    const float* __restrict__ w0, const float* __restrict__ w1,
    const float* __restrict__ w2, const float* __restrict__ w3,
    const float* __restrict__ w4, const float* __restrict__ w5,
    __nv_bfloat16* __restrict__ whi, __nv_bfloat16* __restrict__ wlo)
{
    const float* srcs[6] = {w0, w1, w2, w3, w4, w5};
    int slot = blockIdx.y;
    size_t idx = ((size_t)blockIdx.x * 256 + threadIdx.x) * 4;
    float4 v = *(const float4*)(srcs[slot] + idx);
    float vv[4] = {v.x, v.y, v.z, v.w};
    u64 hp = 0, lp = 0;
#pragma unroll
    for (int j = 0; j < 4; j++) {
        unsigned short h, l2; bfsplit(vv[j], h, l2);
        hp |= (u64)h  << (16 * j);
        lp |= (u64)l2 << (16 * j);
    }
    size_t o = (size_t)slot * 524288 + idx;
    *(u64*)(whi + o) = hp;
    *(u64*)(wlo + o) = lp;
}

// ---------------------------------------------------------------------------
// Transpose + split: X [bz][k=256][p=1024] fp32 -> hiT/loT [bz][p][k] bf16.
// ---------------------------------------------------------------------------
__global__ __launch_bounds__(256) void convx_kernel(
    const float* __restrict__ X,
    __nv_bfloat16* __restrict__ hiT, __nv_bfloat16* __restrict__ loT)
{
    __shared__ float s[32][33];
    int t = threadIdx.x;
    int pt = blockIdx.x, kt = blockIdx.y, bz = blockIdx.z;
    const float* Xb = X + ((size_t)bz * 256 + kt * 32) * 1024 + pt * 32;
    int kr = t >> 5, pc = t & 31;
#pragma unroll
    for (int i = 0; i < 4; i++)
        s[kr + i * 8][pc] = Xb[(size_t)(kr + i * 8) * 1024 + pc];
    __syncthreads();
    int pr = t >> 3, kq = t & 7;
    u64 hp = 0, lp = 0;
#pragma unroll
    for (int j = 0; j < 4; j++) {
        unsigned short h, l2; bfsplit(s[kq * 4 + j][pr], h, l2);
        hp |= (u64)h  << (16 * j);
        lp |= (u64)l2 << (16 * j);
    }
    size_t o = ((size_t)bz * 1024 + pt * 32 + pr) * 256 + kt * 32 + kq * 4;
    *(u64*)(hiT + o) = hp;
    *(u64*)(loT + o) = lp;
}

// ---------------------------------------------------------------------------
// HMMA GEMM with cp.async 3-stage ring, 2 CTAs/SM (128-reg cap).
// C[bz][o][p] = sum_k W[g][o][k] * X[bz][k][p], 3-pass bf16 split.
// CTA 128x128, 8 warps (2x4), warp tile 64x32. 12 stages (3 passes x 4 k64).
// smem: A ring 3x16KB @0, B ring 3x16KB @49152 (total 96KB).
// ---------------------------------------------------------------------------
__global__ __launch_bounds__(256, 2) void hgemm_kernel(
    const __nv_bfloat16* __restrict__ whi, const __nv_bfloat16* __restrict__ wlo,
    const __nv_bfloat16* __restrict__ xhiT, const __nv_bfloat16* __restrict__ xloT,
    const float* __restrict__ bias, float* __restrict__ C, int relu)
{
    extern __shared__ char smem[];
    uint32_t sbase = smem_u32(smem);

    int t  = threadIdx.x;
    int wi = t >> 5, l = t & 31;
    int wo = wi >> 2, wp = wi & 3;
    int p0 = blockIdx.x * 128, o0 = blockIdx.y * 128;
    int bz = blockIdx.z, g = bz & 7;

    const __nv_bfloat16* Ahi = whi  + (size_t)g  * 65536;
    const __nv_bfloat16* Alo = wlo  + (size_t)g  * 65536;
    const __nv_bfloat16* Bhi = xhiT + (size_t)bz * 262144;
    const __nv_bfloat16* Blo = xloT + (size_t)bz * 262144;

    float acc[4][4][4];
#pragma unroll
    for (int i = 0; i < 4; i++)
#pragma unroll
        for (int j = 0; j < 4; j++)
#pragma unroll
            for (int r = 0; r < 4; r++) acc[i][j][r] = 0.f;

    int rowi[4], kqi[4], swoff[4];
#pragma unroll
    for (int i = 0; i < 4; i++) {
        int v2 = t + i * 256;
        rowi[i] = v2 >> 3; kqi[i] = v2 & 7;
        int off = rowi[i] * 128 + kqi[i] * 16;
        swoff[i] = off ^ ((off >> 3) & 0x70);
    }

    int a_row_l = (l & 15), a_col_l = (l >> 4) << 4;
    int b_quad = l >> 3, b_lr = l & 7;
    int b_row_l = ((b_quad >> 1) << 3) + b_lr;
    int b_col_l = (b_quad & 1) << 4;

#define ISSUE_STAGE(s) do {                                                    \
        int pass_ = (s) >> 2, k0_ = ((s) & 3) * 64;                            \
        const __nv_bfloat16* As_ = (pass_ < 2)  ? Ahi : Alo;                   \
        const __nv_bfloat16* Bs_ = (pass_ == 1) ? Blo : Bhi;                   \
        uint32_t sa_ = sbase + ((s) % 3) * 16384;                              \
        uint32_t sb_ = sbase + 49152 + ((s) % 3) * 16384;                      \
        _Pragma("unroll")                                                      \
        for (int i_ = 0; i_ < 4; i_++) {                                       \
            cpasync16(sa_ + swoff[i_],                                         \
                As_ + ((size_t)(o0 + rowi[i_]) * 256 + k0_ + kqi[i_] * 8));    \
            cpasync16(sb_ + swoff[i_],                                         \
                Bs_ + ((size_t)(p0 + rowi[i_]) * 256 + k0_ + kqi[i_] * 8));    \
        }                                                                      \
        CP_COMMIT();                                                           \
    } while (0)

    ISSUE_STAGE(0);
    ISSUE_STAGE(1);

    for (int s = 0; s < 12; s++) {
        if (s < 11) asm volatile("cp.async.wait_group 1;" ::: "memory");
        else        asm volatile("cp.async.wait_group 0;" ::: "memory");
        __syncthreads();
        if (s < 10) ISSUE_STAGE(s + 2);

        uint32_t sa = sbase + (s % 3) * 16384;
        uint32_t sb = sbase + 49152 + (s % 3) * 16384;
#pragma unroll
        for (int ks = 0; ks < 4; ks++) {
            uint32_t af[4][4];
#pragma unroll
            for (int i = 0; i < 4; i++) {
                int row = wo * 64 + i * 16 + a_row_l;
                int off = row * 128 + ks * 32 + a_col_l;
                ldsm4(af[i], sa + (off ^ ((off >> 3) & 0x70)));
            }
            uint32_t bfr[2][4];
#pragma unroll
            for (int j2 = 0; j2 < 2; j2++) {
                int n = wp * 32 + j2 * 16 + b_row_l;
                int off = n * 128 + ks * 32 + b_col_l;
                ldsm4(bfr[j2], sb + (off ^ ((off >> 3) & 0x70)));
            }
#pragma unroll
            for (int i = 0; i < 4; i++)
#pragma unroll
                for (int j = 0; j < 4; j++)
                    mma_bf16(acc[i][j], af[i], bfr[j >> 1][(j & 1) * 2],
                             bfr[j >> 1][(j & 1) * 2 + 1]);
        }
    }
#undef ISSUE_STAGE

    // epilogue: direct float2 stores with bias/relu
    float* Cb = C + (size_t)bz * 256 * 1024;
#pragma unroll
    for (int i = 0; i < 4; i++) {
        int row = o0 + wo * 64 + i * 16 + (l >> 2);
        float b0 = bias ? bias[g * 256 + row]     : 0.f;
        float b8 = bias ? bias[g * 256 + row + 8] : 0.f;
#pragma unroll
        for (int j = 0; j < 4; j++) {
            int col = p0 + wp * 32 + j * 8 + (l & 3) * 2;
            float2 v0 = make_float2(acc[i][j][0] + b0, acc[i][j][1] + b0);
            float2 v1 = make_float2(acc[i][j][2] + b8, acc[i][j][3] + b8);
            if (relu) {
                v0.x = fmaxf(v0.x, 0.f); v0.y = fmaxf(v0.y, 0.f);
                v1.x = fmaxf(v1.x, 0.f); v1.y = fmaxf(v1.y, 0.f);
            }
            *(float2*)(Cb + (size_t)row * 1024 + col)       = v0;
            *(float2*)(Cb + (size_t)(row + 8) * 1024 + col) = v1;
        }
    }
}

// ---------------------------------------------------------------------------
// Windowed attention; bf16 hi/lo transposed epilogue (feeds GEMM#4).
// ---------------------------------------------------------------------------
#define HPS 548
#define EPS 68
#define QPS 548
#define OPS 522
#define SK_F   (40*HPS)
#define SQ_F   (16*QPS)
#define REL_F  (12*EPS)

__global__ __launch_bounds__(512) void attn_kernel(
    const float* __restrict__ q, const float* __restrict__ k,
    const float* __restrict__ v, const float* __restrict__ hm,
    const float* __restrict__ wmm,
    __nv_bfloat16* __restrict__ avhiT, __nv_bfloat16* __restrict__ avloT)
{
    extern __shared__ float smemf[];
    float* sk   = smemf;
    float* sv   = sk + SK_F;
    float* sq   = sv + SK_F;
    float* srh  = sq + SQ_F;
    float* srw  = srh + REL_F;
    float* attd = sk;
    float* sout = sq;

    int t  = threadIdx.x;
    int w0 = blockIdx.x << 3;
    int h0 = blockIdx.y << 1;
    int nm = blockIdx.z;
    int n  = nm >> 2, m = nm & 3;

    for (int idx = t; idx < 20480; idx += 512) {
        int c   = idx % 10;
        int red = idx / 10;
        int d   = red & 63;
        int e   = (red >> 6) & 7;
        int r   = red >> 9;
        int h2 = h0 + r - 1, w2 = w0 + c - 1;
        float kv = 0.f, vv = 0.f;
        if (h2 >= 0 && h2 < 32 && w2 >= 0 && w2 < 32) {
            size_t gi = (((size_t)(n * 8 + e) * 256) + m * 64 + d) * 1024 + h2 * 32 + w2;
            kv = k[gi]; vv = v[gi];
        }
        int si = (r * 10 + c) * HPS + e * EPS + d;
        sk[si] = kv; sv[si] = vv;
    }
    for (int idx = t; idx < 8192; idx += 512) {
        int pix = idx & 15, gd = idx >> 4;
        int gq = gd >> 6, d = gd & 63;
        int pr = pix >> 3, pc = pix & 7;
        size_t gi = (((size_t)(n * 8 + gq) * 256) + m * 64 + d) * 1024
                    + (h0 + pr) * 32 + w0 + pc;
        sq[pix * QPS + gq * EPS + d] = q[gi];
    }
    for (int idx = t; idx < 768; idx += 512) {
        int d  = idx & 63;
        int ei = idx >> 6;
        int e  = ei / 3, i = ei % 3;
        srh[ei * EPS + d] = hm [((e * 256 + m * 64 + d) * 3) + i];
        srw[ei * EPS + d] = wmm[((e * 256 + m * 64 + d) * 3) + i];
    }
    __syncthreads();

    int wi = t >> 5, l = t & 31;
    int g  = l >> 2, e0 = l & 3;
    int pr = wi >> 3, cc = (wi & 7) + 1;
    const float* sqw = sq + wi * QPS + g * EPS;
    int eoff = e0 * EPS;

    int posoff[9];
#pragma unroll
    for (int i = 0; i < 3; i++)
#pragma unroll
        for (int j = 0; j < 3; j++)
            posoff[i * 3 + j] = ((pr + i) * 10 + cc - 1 + j) * HPS;

    u64 hA[3] = {0,0,0}, hB[3] = {0,0,0};
#pragma unroll 4
    for (int dd = 0; dd < 64; dd += 4) {
        ulonglong2 q2 = *(const ulonglong2*)(sqw + dd);
#pragma unroll
        for (int u = 0; u < 3; u++) {
            ulonglong2 r2 = *(const ulonglong2*)(srh + (e0 * 3 + u) * EPS + dd);
            ulonglong2 s2 = *(const ulonglong2*)(srw + (e0 * 3 + u) * EPS + dd);
            fma2(hA[u], q2.x, r2.x); fma2(hA[u], q2.y, r2.y);
            fma2(hB[u], q2.x, s2.x); fma2(hB[u], q2.y, s2.y);
        }
    }
    float qrA[3], qrB[3];
#pragma unroll
    for (int u = 0; u < 3; u++) {
        float2 fa = upk(hA[u]), fb = upk(hB[u]);
        qrA[u] = fa.x + fa.y; qrB[u] = fb.x + fb.y;
    }

    u64 cA[9], cB[9];
#pragma unroll
    for (int u = 0; u < 9; u++) { cA[u] = 0ull; cB[u] = 0ull; }
#pragma unroll 4
    for (int dd = 0; dd < 64; dd += 4) {
        ulonglong2 q2 = *(const ulonglong2*)(sqw + dd);
#pragma unroll
        for (int u = 0; u < 9; u++) {
            const float* kp = sk + posoff[u] + eoff + dd;
            ulonglong2 ka = *(const ulonglong2*)(kp);
            ulonglong2 kc = *(const ulonglong2*)(kp + 4 * EPS);
            fma2(cA[u], q2.x, ka.x); fma2(cA[u], q2.y, ka.y);
            fma2(cB[u], q2.x, kc.x); fma2(cB[u], q2.y, kc.y);
        }
    }
    float sA[9], sB[9];
#pragma unroll
    for (int u = 0; u < 9; u++) {
        float2 fa = upk(cA[u]), fb = upk(cB[u]);
        sA[u] = fa.x + fa.y + qrA[u / 3];
        sB[u] = fb.x + fb.y + qrB[u % 3];
    }

    float mx = -1e30f;
#pragma unroll
    for (int u = 0; u < 9; u++) mx = fmaxf(mx, fmaxf(sA[u], sB[u]));
    mx = fmaxf(mx, __shfl_xor_sync(0xffffffffu, mx, 1));
    mx = fmaxf(mx, __shfl_xor_sync(0xffffffffu, mx, 2));
    float sum = 0.f;
#pragma unroll
    for (int u = 0; u < 9; u++) {
        sA[u] = __expf(sA[u] - mx);
        sB[u] = __expf(sB[u] - mx);
        sum += sA[u] + sB[u];
    }
    sum += __shfl_xor_sync(0xffffffffu, sum, 1);
    sum += __shfl_xor_sync(0xffffffffu, sum, 2);
    float inv = 1.f / sum;

    __syncthreads();

    float* awT = attd + wi * 1152;
#pragma unroll
    for (int u = 0; u < 9; u++) {
        float wa = sA[u] * inv, wb = sB[u] * inv;
        *(float2*)(awT + ((e0 * 9 + u) * 8 + g) * 2)       = make_float2(wa, wa);
        *(float2*)(awT + (((e0 + 4) * 9 + u) * 8 + g) * 2) = make_float2(wb, wb);
    }
    __syncwarp();

    u64 acc[8];
#pragma unroll
    for (int gg = 0; gg < 8; gg++) acc[gg] = 0ull;
#pragma unroll 1
    for (int e = 0; e < 8; e++) {
        const float* vb = sv + e * EPS + 2 * l;
#pragma unroll
        for (int nb = 0; nb < 9; nb++) {
            u64 v2 = *(const u64*)(vb + posoff[nb]);
            const ulonglong2* wp2 = (const ulonglong2*)(awT + (e * 9 + nb) * 16);
            ulonglong2 w01 = wp2[0], w23 = wp2[1], w45 = wp2[2], w67 = wp2[3];
            fma2(acc[0], w01.x, v2); fma2(acc[1], w01.y, v2);
            fma2(acc[2], w23.x, v2); fma2(acc[3], w23.y, v2);
            fma2(acc[4], w45.x, v2); fma2(acc[5], w45.y, v2);
            fma2(acc[6], w67.x, v2); fma2(acc[7], w67.y, v2);
        }
    }
    float* so = sout + wi * OPS;
#pragma unroll
    for (int gg = 0; gg < 8; gg++) {
        float2 f = upk(acc[gg]);
        *(float2*)(so + gg * 64 + 2 * l) = f;
    }
    __syncthreads();

    // transposed bf16 hi/lo store: avT[bz=n*8+g2][p][m*64+d]
#pragma unroll
    for (int it = 0; it < 4; it++) {
        int flat = t + it * 512;
        int dq  = flat & 15;
        int g2  = (flat >> 4) & 7;
        int pix = flat >> 7;
        const float* src = sout + pix * OPS + g2 * 64 + dq * 4;
        u64 hp = 0, lp = 0;
#pragma unroll
        for (int j = 0; j < 4; j++) {
            unsigned short h, l2; bfsplit(src[j], h, l2);
            hp |= (u64)h  << (16 * j);
            lp |= (u64)l2 << (16 * j);
        }
        int p = (h0 + (pix >> 3)) * 32 + w0 + (pix & 7);
        size_t o = (((size_t)(n * 8 + g2) * 1024) + p) * 256 + m * 64 + dq * 4;
        *(u64*)(avhiT + o) = hp;
        *(u64*)(avloT + o) = lp;
    }
}

// ---------------------------------------------------------------------------
// Fused skip + LayerNorm (unchanged).
// ---------------------------------------------------------------------------
__global__ __launch_bounds__(256) void ln_kernel(
    const float* __restrict__ X, const float* __restrict__ Y,
    const float* __restrict__ gamma, const float* __restrict__ beta,
    float* __restrict__ T)
{
    __shared__ float sx[64][33];
    int t  = threadIdx.x;
    int p0 = blockIdx.x << 5;
    int gm = blockIdx.y;
    int g  = gm >> 2, m = gm & 3;
    int n  = blockIdx.z;
    size_t base = (((size_t)(n * 8 + g) * 256) + m * 64) * 1024 + p0;
    int pp = t & 31;
#pragma unroll
    for (int pass = 0; pass < 8; pass++) {
        int d = (t >> 5) + pass * 8;
        sx[d][pp] = X[base + (size_t)d * 1024 + pp] + Y[base + (size_t)d * 1024 + pp];
    }
    __syncthreads();
    int c = t >> 3, sub = t & 7;
    float s1 = 0.f, s2 = 0.f;
#pragma unroll
    for (int u = 0; u < 8; u++) {
        float vv = sx[sub * 8 + u][c];
        s1 += vv; s2 += vv * vv;
    }
#pragma unroll
    for (int off = 1; off < 8; off <<= 1) {
        s1 += __shfl_xor_sync(0xffffffffu, s1, off);
        s2 += __shfl_xor_sync(0xffffffffu, s2, off);
    }
    float mu  = s1 * 0.015625f;
    float var = s2 * 0.015625f - mu * mu;
    float inv = rsqrtf(var + 1e-5f);
    float* op = T + ((((size_t)n * 1024 + p0 + c) * 4 + m) * 8 + g) * 64;
#pragma unroll
    for (int u = 0; u < 8; u++) {
        int d = sub * 8 + u;
        op[d] = (sx[d][c] - mu) * inv * gamma[d] + beta[d];
    }
}

// ---------------------------------------------------------------------------
extern "C" void kernel_launch(void* const* d_in, const int* in_sizes, int n_in,
                              void* d_out, int out_size)
{
    (void)in_sizes; (void)n_in; (void)out_size;
    const float* x     = (const float*)d_in[0];
    const float* wq    = (const float*)d_in[1];
    const float* wk    = (const float*)d_in[2];
    const float* wv    = (const float*)d_in[3];
    const float* hm    = (const float*)d_in[4];
    const float* wm    = (const float*)d_in[5];
    const float* wconv = (const float*)d_in[6];
    const float* bconv = (const float*)d_in[7];
    const float* wf1   = (const float*)d_in[8];
    const float* bf1   = (const float*)d_in[9];
    const float* wf2   = (const float*)d_in[10];
    const float* bf2   = (const float*)d_in[11];
    const float* g1    = (const float*)d_in[12];
    const float* b1    = (const float*)d_in[13];
    const float* g2    = (const float*)d_in[14];
    const float* b2    = (const float*)d_in[15];

    float *q, *k, *v, *y, *tb, *h1, *f;
    __nv_bfloat16 *xhiT, *xloT, *whi, *wlo;
    cudaGetSymbolAddress((void**)&q,  g_q);
    cudaGetSymbolAddress((void**)&k,  g_k);
    cudaGetSymbolAddress((void**)&v,  g_v);
    cudaGetSymbolAddress((void**)&y,  g_y);
    cudaGetSymbolAddress((void**)&tb, g_t);
    cudaGetSymbolAddress((void**)&h1, g_h1);
    cudaGetSymbolAddress((void**)&f,  g_f);
    cudaGetSymbolAddress((void**)&xhiT, g_xhiT);
    cudaGetSymbolAddress((void**)&xloT, g_xloT);
    cudaGetSymbolAddress((void**)&whi,  g_whi);
    cudaGetSymbolAddress((void**)&wlo,  g_wlo);

    const int ATTN_SMEM = (SK_F * 2 + SQ_F + REL_F * 2) * 4;   // 216960 B
    cudaFuncSetAttribute(attn_kernel,
                         cudaFuncAttributeMaxDynamicSharedMemorySize, ATTN_SMEM);
    const int GEMM_SMEM = 98304;                                // 2x 3x16KB
    cudaFuncSetAttribute(hgemm_kernel,
                         cudaFuncAttributeMaxDynamicSharedMemorySize, GEMM_SMEM);

    const size_t WS = 524288;  // per-slot W elements
    dim3 ggrid(8, 2, 32);
    dim3 cxgrid(32, 8, 32);

    convw_kernel<<<dim3(512, 6), 256>>>(wq, wk, wv, wconv, wf1, wf2, whi, wlo);
    convx_kernel<<<cxgrid, 256>>>(x, xhiT, xloT);

    hgemm_kernel<<<ggrid, 256, GEMM_SMEM>>>(whi + 0*WS, wlo + 0*WS, xhiT, xloT, nullptr, q, 0);
    hgemm_kernel<<<ggrid, 256, GEMM_SMEM>>>(whi + 1*WS, wlo + 1*WS, xhiT, xloT, nullptr, k, 0);
    hgemm_kernel<<<ggrid, 256, GEMM_SMEM>>>(whi + 2*WS, wlo + 2*WS, xhiT, xloT, nullptr, v, 0);

    // attn writes bf16 split transposed directly into xhiT/xloT
    attn_kernel<<<dim3(4, 16, 16), 512, ATTN_SMEM>>>(q, k, v, hm, wm, xhiT, xloT);

    hgemm_kernel<<<ggrid, 256, GEMM_SMEM>>>(whi + 3*WS, wlo + 3*WS, xhiT, xloT, bconv, y, 0);
    ln_kernel<<<dim3(32, 32, 4), 256>>>(x, y, g1, b1, tb);

    convx_kernel<<<cxgrid, 256>>>(tb, xhiT, xloT);
    hgemm_kernel<<<ggrid, 256, GEMM_SMEM>>>(whi + 4*WS, wlo + 4*WS, xhiT, xloT, bf1, h1, 1);

    convx_kernel<<<cxgrid, 256>>>(h1, xhiT, xloT);
    hgemm_kernel<<<ggrid, 256, GEMM_SMEM>>>(whi + 5*WS, wlo + 5*WS, xhiT, xloT, bf2, f, 0);

    ln_kernel<<<dim3(32, 32, 4), 256>>>(tb, f, g2, b2, (float*)d_out);
}

// round 8
// speedup vs baseline: 2.8145x; 1.1747x over previous
#include <cuda_runtime.h>
#include <cuda_fp16.h>
#include <cstdint>

#define HWP 1024

// fp32 scratch
__device__ float g_qkv[3*32*256*HWP];   // q,k,v contiguous slots
__device__ float g_y [4*8*256*HWP];
__device__ float g_t [4*8*256*HWP];
__device__ float g_h1[4*8*256*HWP];
__device__ float g_f [4*8*256*HWP];
// fp16 operands
__device__ __half g_xhT[32*1024*256];   // activations [bz][p][k], fp16
__device__ __half g_whi[6*8*256*256];   // weight hi [slot][g][o][k]
__device__ __half g_wlo[6*8*256*256];   // weight lo

typedef unsigned long long u64;
__device__ __forceinline__ u64 pk2(float x, float y) {
    u64 r; asm("mov.b64 %0, {%1, %2};" : "=l"(r) : "f"(x), "f"(y)); return r;
}
__device__ __forceinline__ void fma2(u64& d, u64 a, u64 b) {
    asm("fma.rn.f32x2 %0, %1, %2, %3;" : "=l"(d) : "l"(a), "l"(b), "l"(d));
}
__device__ __forceinline__ float2 upk(u64 v) {
    float2 f; asm("mov.b64 {%0, %1}, %2;" : "=f"(f.x), "=f"(f.y) : "l"(v)); return f;
}
__device__ __forceinline__ uint32_t smem_u32(const void* p) {
    uint32_t a;
    asm("{ .reg .u64 tmp; cvta.to.shared.u64 tmp, %1; cvt.u32.u64 %0, tmp; }"
        : "=r"(a) : "l"(p));
    return a;
}
__device__ __forceinline__ void ldsm4(uint32_t* r, uint32_t addr) {
    asm volatile("ldmatrix.sync.aligned.m8n8.x4.shared.b16 {%0,%1,%2,%3}, [%4];"
        : "=r"(r[0]), "=r"(r[1]), "=r"(r[2]), "=r"(r[3]) : "r"(addr));
}
__device__ __forceinline__ void mma_f16(float* c, const uint32_t* a,
                                        uint32_t b0, uint32_t b1) {
    asm volatile("mma.sync.aligned.m16n8k16.row.col.f32.f16.f16.f32 "
        "{%0,%1,%2,%3}, {%4,%5,%6,%7}, {%8,%9}, {%0,%1,%2,%3};"
        : "+f"(c[0]), "+f"(c[1]), "+f"(c[2]), "+f"(c[3])
        : "r"(a[0]), "r"(a[1]), "r"(a[2]), "r"(a[3]), "r"(b0), "r"(b1));
}
__device__ __forceinline__ void cpasync16(uint32_t saddr, const void* g) {
    asm volatile("cp.async.cg.shared.global [%0], [%1], 16;" :: "r"(saddr), "l"(g));
}
#define CP_COMMIT() asm volatile("cp.async.commit_group;" ::: "memory")

__device__ __forceinline__ void hsplit(float x, unsigned short& h, unsigned short& l2) {
    __half h0 = __float2half_rn(x);
    __half l0 = __float2half_rn(x - __half2float(h0));
    h = __half_as_ushort(h0); l2 = __half_as_ushort(l0);
}

// ---------------------------------------------------------------------------
// Split fp32 W into hi/lo fp16. grid (512, 6)
// ---------------------------------------------------------------------------
__global__ __launch_bounds__(256) void convw_kernel(
    const float* __restrict__ w0, const float* __restrict__ w1,
    const float* __restrict__ w2, const float* __restrict__ w3,
    const float* __restrict__ w4, const float* __restrict__ w5,
    __half* __restrict__ whi, __half* __restrict__ wlo)
{
    const float* srcs[6] = {w0, w1, w2, w3, w4, w5};
    int slot = blockIdx.y;
    size_t idx = ((size_t)blockIdx.x * 256 + threadIdx.x) * 4;
    float4 v = *(const float4*)(srcs[slot] + idx);
    float vv[4] = {v.x, v.y, v.z, v.w};
    u64 hp = 0, lp = 0;
#pragma unroll
    for (int j = 0; j < 4; j++) {
        unsigned short h, l2; hsplit(vv[j], h, l2);
        hp |= (u64)h  << (16 * j);
        lp |= (u64)l2 << (16 * j);
    }
    size_t o = (size_t)slot * 524288 + idx;
    *(u64*)(whi + o) = hp;
    *(u64*)(wlo + o) = lp;
}

// ---------------------------------------------------------------------------
// Transpose + fp16 convert: X [bz][k=256][p=1024] -> hT [bz][p][k].
// ---------------------------------------------------------------------------
__global__ __launch_bounds__(256) void convx_kernel(
    const float* __restrict__ X, __half* __restrict__ hT)
{
    __shared__ float s[32][33];
    int t = threadIdx.x;
    int pt = blockIdx.x, kt = blockIdx.y, bz = blockIdx.z;
    const float* Xb = X + ((size_t)bz * 256 + kt * 32) * 1024 + pt * 32;
    int kr = t >> 5, pc = t & 31;
#pragma unroll
    for (int i = 0; i < 4; i++)
        s[kr + i * 8][pc] = Xb[(size_t)(kr + i * 8) * 1024 + pc];
    __syncthreads();
    int pr = t >> 3, kq = t & 7;
    u64 hp = 0;
#pragma unroll
    for (int j = 0; j < 4; j++) {
        __half h = __float2half_rn(s[kq * 4 + j][pr]);
        hp |= (u64)__half_as_ushort(h) << (16 * j);
    }
    size_t o = ((size_t)bz * 1024 + pt * 32 + pr) * 256 + kt * 32 + kq * 4;
    *(u64*)(hT + o) = hp;
}

// ---------------------------------------------------------------------------
// HMMA GEMM, 2-pass fp16 split (A_hi*B + A_lo*B), cp.async 3-stage ring.
// grid (8, 2*nslots, 32): slot = by>>1, o-tile = by&1.
// CTA 128x128, 8 warps (2x4), warp tile 64x32, 8 stages (2 passes x 4 k64).
// smem: A ring 3x16KB @0, B ring 3x16KB @49152.
// ---------------------------------------------------------------------------
__global__ __launch_bounds__(256, 2) void hgemm_kernel(
    const __half* __restrict__ whi, const __half* __restrict__ wlo,
    const __half* __restrict__ xhT,
    const float* __restrict__ bias, float* __restrict__ C, int relu)
{
    extern __shared__ char smem[];
    uint32_t sbase = smem_u32(smem);

    int t  = threadIdx.x;
    int wi = t >> 5, l = t & 31;
    int wo = wi >> 2, wp = wi & 3;
    int slot = blockIdx.y >> 1;
    int p0 = blockIdx.x * 128, o0 = (blockIdx.y & 1) * 128;
    int bz = blockIdx.z, g = bz & 7;

    const __half* Ahi = whi + (size_t)slot * 524288 + (size_t)g * 65536;
    const __half* Alo = wlo + (size_t)slot * 524288 + (size_t)g * 65536;
    const __half* Bhi = xhT + (size_t)bz * 262144;

    float acc[4][4][4];
#pragma unroll
    for (int i = 0; i < 4; i++)
#pragma unroll
        for (int j = 0; j < 4; j++)
#pragma unroll
            for (int r = 0; r < 4; r++) acc[i][j][r] = 0.f;

    int rowi[4], kqi[4], swoff[4];
#pragma unroll
    for (int i = 0; i < 4; i++) {
        int v2 = t + i * 256;
        rowi[i] = v2 >> 3; kqi[i] = v2 & 7;
        int off = rowi[i] * 128 + kqi[i] * 16;
        swoff[i] = off ^ ((off >> 3) & 0x70);
    }

    int a_row_l = (l & 15), a_col_l = (l >> 4) << 4;
    int b_quad = l >> 3, b_lr = l & 7;
    int b_row_l = ((b_quad >> 1) << 3) + b_lr;
    int b_col_l = (b_quad & 1) << 4;

#define ISSUE_STAGE(s) do {                                                    \
        int pass_ = (s) >> 2, k0_ = ((s) & 3) * 64;                            \
        const __half* As_ = pass_ ? Alo : Ahi;                                 \
        uint32_t sa_ = sbase + ((s) % 3) * 16384;                              \
        uint32_t sb_ = sbase + 49152 + ((s) % 3) * 16384;                      \
        _Pragma("unroll")                                                      \
        for (int i_ = 0; i_ < 4; i_++) {                                       \
            cpasync16(sa_ + swoff[i_],                                         \
                As_ + ((size_t)(o0 + rowi[i_]) * 256 + k0_ + kqi[i_] * 8));    \
            cpasync16(sb_ + swoff[i_],                                         \
                Bhi + ((size_t)(p0 + rowi[i_]) * 256 + k0_ + kqi[i_] * 8));    \
        }                                                                      \
        CP_COMMIT();                                                           \
    } while (0)

    ISSUE_STAGE(0);
    ISSUE_STAGE(1);

    for (int s = 0; s < 8; s++) {
        if (s < 7) asm volatile("cp.async.wait_group 1;" ::: "memory");
        else       asm volatile("cp.async.wait_group 0;" ::: "memory");
        __syncthreads();
        if (s < 6) ISSUE_STAGE(s + 2);

        uint32_t sa = sbase + (s % 3) * 16384;
        uint32_t sb = sbase + 49152 + (s % 3) * 16384;
#pragma unroll
        for (int ks = 0; ks < 4; ks++) {
            uint32_t af[4][4];
#pragma unroll
            for (int i = 0; i < 4; i++) {
                int row = wo * 64 + i * 16 + a_row_l;
                int off = row * 128 + ks * 32 + a_col_l;
                ldsm4(af[i], sa + (off ^ ((off >> 3) & 0x70)));
            }
            uint32_t bfr[2][4];
#pragma unroll
            for (int j2 = 0; j2 < 2; j2++) {
                int n = wp * 32 + j2 * 16 + b_row_l;
                int off = n * 128 + ks * 32 + b_col_l;
                ldsm4(bfr[j2], sb + (off ^ ((off >> 3) & 0x70)));
            }
#pragma unroll
            for (int i = 0; i < 4; i++)
#pragma unroll
                for (int j = 0; j < 4; j++)
                    mma_f16(acc[i][j], af[i], bfr[j >> 1][(j & 1) * 2],
                            bfr[j >> 1][(j & 1) * 2 + 1]);
        }
    }
#undef ISSUE_STAGE

    float* Cb = C + (size_t)slot * 8388608 + (size_t)bz * 262144;
#pragma unroll
    for (int i = 0; i < 4; i++) {
        int row = o0 + wo * 64 + i * 16 + (l >> 2);
        float b0 = bias ? bias[g * 256 + row]     : 0.f;
        float b8 = bias ? bias[g * 256 + row + 8] : 0.f;
#pragma unroll
        for (int j = 0; j < 4; j++) {
            int col = p0 + wp * 32 + j * 8 + (l & 3) * 2;
            float2 v0 = make_float2(acc[i][j][0] + b0, acc[i][j][1] + b0);
            float2 v1 = make_float2(acc[i][j][2] + b8, acc[i][j][3] + b8);
            if (relu) {
                v0.x = fmaxf(v0.x, 0.f); v0.y = fmaxf(v0.y, 0.f);
                v1.x = fmaxf(v1.x, 0.f); v1.y = fmaxf(v1.y, 0.f);
            }
            *(float2*)(Cb + (size_t)row * 1024 + col)       = v0;
            *(float2*)(Cb + (size_t)(row + 8) * 1024 + col) = v1;
        }
    }
}

// ---------------------------------------------------------------------------
// Windowed attention; fp16 transposed epilogue (feeds GEMM#4 directly).
// ---------------------------------------------------------------------------
#define HPS 548
#define EPS 68
#define QPS 548
#define OPS 522
#define SK_F   (40*HPS)
#define SQ_F   (16*QPS)
#define REL_F  (12*EPS)

__global__ __launch_bounds__(512) void attn_kernel(
    const float* __restrict__ q, const float* __restrict__ k,
    const float* __restrict__ v, const float* __restrict__ hm,
    const float* __restrict__ wmm, __half* __restrict__ avhT)
{
    extern __shared__ float smemf[];
    float* sk   = smemf;
    float* sv   = sk + SK_F;
    float* sq   = sv + SK_F;
    float* srh  = sq + SQ_F;
    float* srw  = srh + REL_F;
    float* attd = sk;
    float* sout = sq;

    int t  = threadIdx.x;
    int w0 = blockIdx.x << 3;
    int h0 = blockIdx.y << 1;
    int nm = blockIdx.z;
    int n  = nm >> 2, m = nm & 3;

    for (int idx = t; idx < 20480; idx += 512) {
        int c   = idx % 10;
        int red = idx / 10;
        int d   = red & 63;
        int e   = (red >> 6) & 7;
        int r   = red >> 9;
        int h2 = h0 + r - 1, w2 = w0 + c - 1;
        float kv = 0.f, vv = 0.f;
        if (h2 >= 0 && h2 < 32 && w2 >= 0 && w2 < 32) {
            size_t gi = (((size_t)(n * 8 + e) * 256) + m * 64 + d) * 1024 + h2 * 32 + w2;
            kv = k[gi]; vv = v[gi];
        }
        int si = (r * 10 + c) * HPS + e * EPS + d;
        sk[si] = kv; sv[si] = vv;
    }
    for (int idx = t; idx < 8192; idx += 512) {
        int pix = idx & 15, gd = idx >> 4;
        int gq = gd >> 6, d = gd & 63;
        int pr = pix >> 3, pc = pix & 7;
        size_t gi = (((size_t)(n * 8 + gq) * 256) + m * 64 + d) * 1024
                    + (h0 + pr) * 32 + w0 + pc;
        sq[pix * QPS + gq * EPS + d] = q[gi];
    }
    for (int idx = t; idx < 768; idx += 512) {
        int d  = idx & 63;
        int ei = idx >> 6;
        int e  = ei / 3, i = ei % 3;
        srh[ei * EPS + d] = hm [((e * 256 + m * 64 + d) * 3) + i];
        srw[ei * EPS + d] = wmm[((e * 256 + m * 64 + d) * 3) + i];
    }
    __syncthreads();

    int wi = t >> 5, l = t & 31;
    int g  = l >> 2, e0 = l & 3;
    int pr = wi >> 3, cc = (wi & 7) + 1;
    const float* sqw = sq + wi * QPS + g * EPS;
    int eoff = e0 * EPS;

    int posoff[9];
#pragma unroll
    for (int i = 0; i < 3; i++)
#pragma unroll
        for (int j = 0; j < 3; j++)
            posoff[i * 3 + j] = ((pr + i) * 10 + cc - 1 + j) * HPS;

    u64 hA[3] = {0,0,0}, hB[3] = {0,0,0};
#pragma unroll 4
    for (int dd = 0; dd < 64; dd += 4) {
        ulonglong2 q2 = *(const ulonglong2*)(sqw + dd);
#pragma unroll
        for (int u = 0; u < 3; u++) {
            ulonglong2 r2 = *(const ulonglong2*)(srh + (e0 * 3 + u) * EPS + dd);
            ulonglong2 s2 = *(const ulonglong2*)(srw + (e0 * 3 + u) * EPS + dd);
            fma2(hA[u], q2.x, r2.x); fma2(hA[u], q2.y, r2.y);
            fma2(hB[u], q2.x, s2.x); fma2(hB[u], q2.y, s2.y);
        }
    }
    float qrA[3], qrB[3];
#pragma unroll
    for (int u = 0; u < 3; u++) {
        float2 fa = upk(hA[u]), fb = upk(hB[u]);
        qrA[u] = fa.x + fa.y; qrB[u] = fb.x + fb.y;
    }

    u64 cA[9], cB[9];
#pragma unroll
    for (int u = 0; u < 9; u++) { cA[u] = 0ull; cB[u] = 0ull; }
#pragma unroll 4
    for (int dd = 0; dd < 64; dd += 4) {
        ulonglong2 q2 = *(const ulonglong2*)(sqw + dd);
#pragma unroll
        for (int u = 0; u < 9; u++) {
            const float* kp = sk + posoff[u] + eoff + dd;
            ulonglong2 ka = *(const ulonglong2*)(kp);
            ulonglong2 kc = *(const ulonglong2*)(kp + 4 * EPS);
            fma2(cA[u], q2.x, ka.x); fma2(cA[u], q2.y, ka.y);
            fma2(cB[u], q2.x, kc.x); fma2(cB[u], q2.y, kc.y);
        }
    }
    float sA[9], sB[9];
#pragma unroll
    for (int u = 0; u < 9; u++) {
        float2 fa = upk(cA[u]), fb = upk(cB[u]);
        sA[u] = fa.x + fa.y + qrA[u / 3];
        sB[u] = fb.x + fb.y + qrB[u % 3];
    }

    float mx = -1e30f;
#pragma unroll
    for (int u = 0; u < 9; u++) mx = fmaxf(mx, fmaxf(sA[u], sB[u]));
    mx = fmaxf(mx, __shfl_xor_sync(0xffffffffu, mx, 1));
    mx = fmaxf(mx, __shfl_xor_sync(0xffffffffu, mx, 2));
    float sum = 0.f;
#pragma unroll
    for (int u = 0; u < 9; u++) {
        sA[u] = __expf(sA[u] - mx);
        sB[u] = __expf(sB[u] - mx);
        sum += sA[u] + sB[u];
    }
    sum += __shfl_xor_sync(0xffffffffu, sum, 1);
    sum += __shfl_xor_sync(0xffffffffu, sum, 2);
    float inv = 1.f / sum;

    __syncthreads();

    float* awT = attd + wi * 1152;
#pragma unroll
    for (int u = 0; u < 9; u++) {
        float wa = sA[u] * inv, wb = sB[u] * inv;
        *(float2*)(awT + ((e0 * 9 + u) * 8 + g) * 2)       = make_float2(wa, wa);
        *(float2*)(awT + (((e0 + 4) * 9 + u) * 8 + g) * 2) = make_float2(wb, wb);
    }
    __syncwarp();

    u64 acc[8];
#pragma unroll
    for (int gg = 0; gg < 8; gg++) acc[gg] = 0ull;
#pragma unroll 1
    for (int e = 0; e < 8; e++) {
        const float* vb = sv + e * EPS + 2 * l;
#pragma unroll
        for (int nb = 0; nb < 9; nb++) {
            u64 v2 = *(const u64*)(vb + posoff[nb]);
            const ulonglong2* wp2 = (const ulonglong2*)(awT + (e * 9 + nb) * 16);
            ulonglong2 w01 = wp2[0], w23 = wp2[1], w45 = wp2[2], w67 = wp2[3];
            fma2(acc[0], w01.x, v2); fma2(acc[1], w01.y, v2);
            fma2(acc[2], w23.x, v2); fma2(acc[3], w23.y, v2);
            fma2(acc[4], w45.x, v2); fma2(acc[5], w45.y, v2);
            fma2(acc[6], w67.x, v2); fma2(acc[7], w67.y, v2);
        }
    }
    float* so = sout + wi * OPS;
#pragma unroll
    for (int gg = 0; gg < 8; gg++) {
        float2 f = upk(acc[gg]);
        *(float2*)(so + gg * 64 + 2 * l) = f;
    }
    __syncthreads();

    // transposed fp16 store: avT[bz=n*8+g2][p][m*64+d]
#pragma unroll
    for (int it = 0; it < 4; it++) {
        int flat = t + it * 512;
        int dq  = flat & 15;
        int g2  = (flat >> 4) & 7;
        int pix = flat >> 7;
        const float* src = sout + pix * OPS + g2 * 64 + dq * 4;
        u64 hp = 0;
#pragma unroll
        for (int j = 0; j < 4; j++) {
            __half h = __float2half_rn(src[j]);
            hp |= (u64)__half_as_ushort(h) << (16 * j);
        }
        int p = (h0 + (pix >> 3)) * 32 + w0 + (pix & 7);
        size_t o = (((size_t)(n * 8 + g2) * 1024) + p) * 256 + m * 64 + dq * 4;
        *(u64*)(avhT + o) = hp;
    }
}

// ---------------------------------------------------------------------------
// Fused skip + LayerNorm (unchanged).
// ---------------------------------------------------------------------------
__global__ __launch_bounds__(256) void ln_kernel(
    const float* __restrict__ X, const float* __restrict__ Y,
    const float* __restrict__ gamma, const float* __restrict__ beta,
    float* __restrict__ T)
{
    __shared__ float sx[64][33];
    int t  = threadIdx.x;
    int p0 = blockIdx.x << 5;
    int gm = blockIdx.y;
    int g  = gm >> 2, m = gm & 3;
    int n  = blockIdx.z;
    size_t base = (((size_t)(n * 8 + g) * 256) + m * 64) * 1024 + p0;
    int pp = t & 31;
#pragma unroll
    for (int pass = 0; pass < 8; pass++) {
        int d = (t >> 5) + pass * 8;
        sx[d][pp] = X[base + (size_t)d * 1024 + pp] + Y[base + (size_t)d * 1024 + pp];
    }
    __syncthreads();
    int c = t >> 3, sub = t & 7;
    float s1 = 0.f, s2 = 0.f;
#pragma unroll
    for (int u = 0; u < 8; u++) {
        float vv = sx[sub * 8 + u][c];
        s1 += vv; s2 += vv * vv;
    }
#pragma unroll
    for (int off = 1; off < 8; off <<= 1) {
        s1 += __shfl_xor_sync(0xffffffffu, s1, off);
        s2 += __shfl_xor_sync(0xffffffffu, s2, off);
    }
    float mu  = s1 * 0.015625f;
    float var = s2 * 0.015625f - mu * mu;
    float inv = rsqrtf(var + 1e-5f);
    float* op = T + ((((size_t)n * 1024 + p0 + c) * 4 + m) * 8 + g) * 64;
#pragma unroll
    for (int u = 0; u < 8; u++) {
        int d = sub * 8 + u;
        op[d] = (sx[d][c] - mu) * inv * gamma[d] + beta[d];
    }
}

// ---------------------------------------------------------------------------
extern "C" void kernel_launch(void* const* d_in, const int* in_sizes, int n_in,
                              void* d_out, int out_size)
{
    (void)in_sizes; (void)n_in; (void)out_size;
    const float* x     = (const float*)d_in[0];
    const float* wq    = (const float*)d_in[1];
    const float* wk    = (const float*)d_in[2];
    const float* wv    = (const float*)d_in[3];
    const float* hm    = (const float*)d_in[4];
    const float* wm    = (const float*)d_in[5];
    const float* wconv = (const float*)d_in[6];
    const float* bconv = (const float*)d_in[7];
    const float* wf1   = (const float*)d_in[8];
    const float* bf1   = (const float*)d_in[9];
    const float* wf2   = (const float*)d_in[10];
    const float* bf2   = (const float*)d_in[11];
    const float* g1    = (const float*)d_in[12];
    const float* b1    = (const float*)d_in[13];
    const float* g2    = (const float*)d_in[14];
    const float* b2    = (const float*)d_in[15];

    float *qkv, *y, *tb, *h1, *f;
    __half *xhT, *whi, *wlo;
    cudaGetSymbolAddress((void**)&qkv, g_qkv);
    cudaGetSymbolAddress((void**)&y,   g_y);
    cudaGetSymbolAddress((void**)&tb,  g_t);
    cudaGetSymbolAddress((void**)&h1,  g_h1);
    cudaGetSymbolAddress((void**)&f,   g_f);
    cudaGetSymbolAddress((void**)&xhT, g_xhT);
    cudaGetSymbolAddress((void**)&whi, g_whi);
    cudaGetSymbolAddress((void**)&wlo, g_wlo);

    const int ATTN_SMEM = (SK_F * 2 + SQ_F + REL_F * 2) * 4;   // 216960 B
    cudaFuncSetAttribute(attn_kernel,
                         cudaFuncAttributeMaxDynamicSharedMemorySize, ATTN_SMEM);
    const int GEMM_SMEM = 98304;
    cudaFuncSetAttribute(hgemm_kernel,
                         cudaFuncAttributeMaxDynamicSharedMemorySize, GEMM_SMEM);

    const size_t WS = 524288;        // per-slot W elements
    const size_t QS = 8388608;       // per-slot qkv floats
    dim3 cxgrid(32, 8, 32);

    convw_kernel<<<dim3(512, 6), 256>>>(wq, wk, wv, wconv, wf1, wf2, whi, wlo);
    convx_kernel<<<cxgrid, 256>>>(x, xhT);

    // fused q/k/v GEMM: slots 0..2 in one launch
    hgemm_kernel<<<dim3(8, 6, 32), 256, GEMM_SMEM>>>(whi, wlo, xhT, nullptr, qkv, 0);

    attn_kernel<<<dim3(4, 16, 16), 512, ATTN_SMEM>>>(qkv, qkv + QS, qkv + 2 * QS,
                                                     hm, wm, xhT);

    hgemm_kernel<<<dim3(8, 2, 32), 256, GEMM_SMEM>>>(whi + 3*WS, wlo + 3*WS, xhT, bconv, y, 0);
    ln_kernel<<<dim3(32, 32, 4), 256>>>(x, y, g1, b1, tb);

    convx_kernel<<<cxgrid, 256>>>(tb, xhT);
    hgemm_kernel<<<dim3(8, 2, 32), 256, GEMM_SMEM>>>(whi + 4*WS, wlo + 4*WS, xhT, bf1, h1, 1);

    convx_kernel<<<cxgrid, 256>>>(h1, xhT);
    hgemm_kernel<<<dim3(8, 2, 32), 256, GEMM_SMEM>>>(whi + 5*WS, wlo + 5*WS, xhT, bf2, f, 0);

    ln_kernel<<<dim3(32, 32, 4), 256>>>(tb, f, g2, b2, (float*)d_out);
}

// round 9
// speedup vs baseline: 3.4394x; 1.2220x over previous
#include <cuda_runtime.h>
#include <cuda_fp16.h>
#include <cstdint>

#define HWP 1024

// fp32 scratch
__device__ float g_qkv[3*32*256*HWP];   // q,k,v contiguous slots
__device__ float g_y [4*8*256*HWP];
__device__ float g_t [4*8*256*HWP];
__device__ float g_h1[4*8*256*HWP];
__device__ float g_f [4*8*256*HWP];
// fp16 operands
__device__ __half g_xhT[32*1024*256];   // activations [bz][p][k], fp16
__device__ __half g_whi[6*8*256*256];   // weight hi [slot][g][o][k]
__device__ __half g_wlo[6*8*256*256];   // weight lo

typedef unsigned long long u64;
__device__ __forceinline__ uint32_t smem_u32(const void* p) {
    uint32_t a;
    asm("{ .reg .u64 tmp; cvta.to.shared.u64 tmp, %1; cvt.u32.u64 %0, tmp; }"
        : "=r"(a) : "l"(p));
    return a;
}
__device__ __forceinline__ void ldsm4(uint32_t* r, uint32_t addr) {
    asm volatile("ldmatrix.sync.aligned.m8n8.x4.shared.b16 {%0,%1,%2,%3}, [%4];"
        : "=r"(r[0]), "=r"(r[1]), "=r"(r[2]), "=r"(r[3]) : "r"(addr));
}
__device__ __forceinline__ void mma_f16(float* c, const uint32_t* a,
                                        uint32_t b0, uint32_t b1) {
    asm volatile("mma.sync.aligned.m16n8k16.row.col.f32.f16.f16.f32 "
        "{%0,%1,%2,%3}, {%4,%5,%6,%7}, {%8,%9}, {%0,%1,%2,%3};"
        : "+f"(c[0]), "+f"(c[1]), "+f"(c[2]), "+f"(c[3])
        : "r"(a[0]), "r"(a[1]), "r"(a[2]), "r"(a[3]), "r"(b0), "r"(b1));
}
__device__ __forceinline__ void cpasync16(uint32_t saddr, const void* g) {
    asm volatile("cp.async.cg.shared.global [%0], [%1], 16;" :: "r"(saddr), "l"(g));
}
#define CP_COMMIT() asm volatile("cp.async.commit_group;" ::: "memory")

__device__ __forceinline__ void hsplit(float x, unsigned short& h, unsigned short& l2) {
    __half h0 = __float2half_rn(x);
    __half l0 = __float2half_rn(x - __half2float(h0));
    h = __half_as_ushort(h0); l2 = __half_as_ushort(l0);
}
__device__ __forceinline__ __half2 h2u(uint32_t v) {
    __half2 h; *(uint32_t*)&h = v; return h;
}

// ---------------------------------------------------------------------------
// Split fp32 W into hi/lo fp16. grid (512, 6)
// ---------------------------------------------------------------------------
__global__ __launch_bounds__(256) void convw_kernel(
    const float* __restrict__ w0, const float* __restrict__ w1,
    const float* __restrict__ w2, const float* __restrict__ w3,
    const float* __restrict__ w4, const float* __restrict__ w5,
    __half* __restrict__ whi, __half* __restrict__ wlo)
{
    const float* srcs[6] = {w0, w1, w2, w3, w4, w5};
    int slot = blockIdx.y;
    size_t idx = ((size_t)blockIdx.x * 256 + threadIdx.x) * 4;
    float4 v = *(const float4*)(srcs[slot] + idx);
    float vv[4] = {v.x, v.y, v.z, v.w};
    u64 hp = 0, lp = 0;
#pragma unroll
    for (int j = 0; j < 4; j++) {
        unsigned short h, l2; hsplit(vv[j], h, l2);
        hp |= (u64)h  << (16 * j);
        lp |= (u64)l2 << (16 * j);
    }
    size_t o = (size_t)slot * 524288 + idx;
    *(u64*)(whi + o) = hp;
    *(u64*)(wlo + o) = lp;
}

// ---------------------------------------------------------------------------
// Transpose + fp16 convert: X [bz][k=256][p=1024] -> hT [bz][p][k].
// ---------------------------------------------------------------------------
__global__ __launch_bounds__(256) void convx_kernel(
    const float* __restrict__ X, __half* __restrict__ hT)
{
    __shared__ float s[32][33];
    int t = threadIdx.x;
    int pt = blockIdx.x, kt = blockIdx.y, bz = blockIdx.z;
    const float* Xb = X + ((size_t)bz * 256 + kt * 32) * 1024 + pt * 32;
    int kr = t >> 5, pc = t & 31;
#pragma unroll
    for (int i = 0; i < 4; i++)
        s[kr + i * 8][pc] = Xb[(size_t)(kr + i * 8) * 1024 + pc];
    __syncthreads();
    int pr = t >> 3, kq = t & 7;
    u64 hp = 0;
#pragma unroll
    for (int j = 0; j < 4; j++) {
        __half h = __float2half_rn(s[kq * 4 + j][pr]);
        hp |= (u64)__half_as_ushort(h) << (16 * j);
    }
    size_t o = ((size_t)bz * 1024 + pt * 32 + pr) * 256 + kt * 32 + kq * 4;
    *(u64*)(hT + o) = hp;
}

// ---------------------------------------------------------------------------
// HMMA GEMM, 2-pass fp16 split (A_hi*B + A_lo*B), cp.async 3-stage ring.
// grid (8, 2*nslots, 32): slot = by>>1, o-tile = by&1.
// ---------------------------------------------------------------------------
__global__ __launch_bounds__(256, 2) void hgemm_kernel(
    const __half* __restrict__ whi, const __half* __restrict__ wlo,
    const __half* __restrict__ xhT,
    const float* __restrict__ bias, float* __restrict__ C, int relu)
{
    extern __shared__ char smem[];
    uint32_t sbase = smem_u32(smem);

    int t  = threadIdx.x;
    int wi = t >> 5, l = t & 31;
    int wo = wi >> 2, wp = wi & 3;
    int slot = blockIdx.y >> 1;
    int p0 = blockIdx.x * 128, o0 = (blockIdx.y & 1) * 128;
    int bz = blockIdx.z, g = bz & 7;

    const __half* Ahi = whi + (size_t)slot * 524288 + (size_t)g * 65536;
    const __half* Alo = wlo + (size_t)slot * 524288 + (size_t)g * 65536;
    const __half* Bhi = xhT + (size_t)bz * 262144;

    float acc[4][4][4];
#pragma unroll
    for (int i = 0; i < 4; i++)
#pragma unroll
        for (int j = 0; j < 4; j++)
#pragma unroll
            for (int r = 0; r < 4; r++) acc[i][j][r] = 0.f;

    int rowi[4], kqi[4], swoff[4];
#pragma unroll
    for (int i = 0; i < 4; i++) {
        int v2 = t + i * 256;
        rowi[i] = v2 >> 3; kqi[i] = v2 & 7;
        int off = rowi[i] * 128 + kqi[i] * 16;
        swoff[i] = off ^ ((off >> 3) & 0x70);
    }

    int a_row_l = (l & 15), a_col_l = (l >> 4) << 4;
    int b_quad = l >> 3, b_lr = l & 7;
    int b_row_l = ((b_quad >> 1) << 3) + b_lr;
    int b_col_l = (b_quad & 1) << 4;

#define ISSUE_STAGE(s) do {                                                    \
        int pass_ = (s) >> 2, k0_ = ((s) & 3) * 64;                            \
        const __half* As_ = pass_ ? Alo : Ahi;                                 \
        uint32_t sa_ = sbase + ((s) % 3) * 16384;                              \
        uint32_t sb_ = sbase + 49152 + ((s) % 3) * 16384;                      \
        _Pragma("unroll")                                                      \
        for (int i_ = 0; i_ < 4; i_++) {                                       \
            cpasync16(sa_ + swoff[i_],                                         \
                As_ + ((size_t)(o0 + rowi[i_]) * 256 + k0_ + kqi[i_] * 8));    \
            cpasync16(sb_ + swoff[i_],                                         \
                Bhi + ((size_t)(p0 + rowi[i_]) * 256 + k0_ + kqi[i_] * 8));    \
        }                                                                      \
        CP_COMMIT();                                                           \
    } while (0)

    ISSUE_STAGE(0);
    ISSUE_STAGE(1);

    for (int s = 0; s < 8; s++) {
        if (s < 7) asm volatile("cp.async.wait_group 1;" ::: "memory");
        else       asm volatile("cp.async.wait_group 0;" ::: "memory");
        __syncthreads();
        if (s < 6) ISSUE_STAGE(s + 2);

        uint32_t sa = sbase + (s % 3) * 16384;
        uint32_t sb = sbase + 49152 + (s % 3) * 16384;
#pragma unroll
        for (int ks = 0; ks < 4; ks++) {
            uint32_t af[4][4];
#pragma unroll
            for (int i = 0; i < 4; i++) {
                int row = wo * 64 + i * 16 + a_row_l;
                int off = row * 128 + ks * 32 + a_col_l;
                ldsm4(af[i], sa + (off ^ ((off >> 3) & 0x70)));
            }
            uint32_t bfr[2][4];
#pragma unroll
            for (int j2 = 0; j2 < 2; j2++) {
                int n = wp * 32 + j2 * 16 + b_row_l;
                int off = n * 128 + ks * 32 + b_col_l;
                ldsm4(bfr[j2], sb + (off ^ ((off >> 3) & 0x70)));
            }
#pragma unroll
            for (int i = 0; i < 4; i++)
#pragma unroll
                for (int j = 0; j < 4; j++)
                    mma_f16(acc[i][j], af[i], bfr[j >> 1][(j & 1) * 2],
                            bfr[j >> 1][(j & 1) * 2 + 1]);
        }
    }
#undef ISSUE_STAGE

    float* Cb = C + (size_t)slot * 8388608 + (size_t)bz * 262144;
#pragma unroll
    for (int i = 0; i < 4; i++) {
        int row = o0 + wo * 64 + i * 16 + (l >> 2);
        float b0 = bias ? bias[g * 256 + row]     : 0.f;
        float b8 = bias ? bias[g * 256 + row + 8] : 0.f;
#pragma unroll
        for (int j = 0; j < 4; j++) {
            int col = p0 + wp * 32 + j * 8 + (l & 3) * 2;
            float2 v0 = make_float2(acc[i][j][0] + b0, acc[i][j][1] + b0);
            float2 v1 = make_float2(acc[i][j][2] + b8, acc[i][j][3] + b8);
            if (relu) {
                v0.x = fmaxf(v0.x, 0.f); v0.y = fmaxf(v0.y, 0.f);
                v1.x = fmaxf(v1.x, 0.f); v1.y = fmaxf(v1.y, 0.f);
            }
            *(float2*)(Cb + (size_t)row * 1024 + col)       = v0;
            *(float2*)(Cb + (size_t)(row + 8) * 1024 + col) = v1;
        }
    }
}

// ---------------------------------------------------------------------------
// Windowed attention, fp16 smem + HFMA2, 2 CTAs/SM (32 warps).
// smem (halves): sk[40*576] | sv[40*576] | sq[16*576] | srh[864] | srw[864]
//   = 114048 B per CTA. Overlays: attd (half2 dup weights) on sk,
//   sout (fp16 av staging) on sq.
// ---------------------------------------------------------------------------
#define EPS_H 72
#define HPS_H 576
#define QPS_H 576
#define OPS_H 520
#define SK_H (40*HPS_H)
#define SQ_H (16*QPS_H)
#define REL_H (12*EPS_H)
#define ATTN_SMEM_B ((SK_H*2 + SQ_H + REL_H*2) * 2)

__global__ __launch_bounds__(512, 2) void attn_kernel(
    const float* __restrict__ q, const float* __restrict__ k,
    const float* __restrict__ v, const float* __restrict__ hm,
    const float* __restrict__ wmm, __half* __restrict__ avhT)
{
    extern __shared__ __half smemh[];
    __half* sk  = smemh;
    __half* sv  = sk + SK_H;
    __half* sq  = sv + SK_H;
    __half* srh = sq + SQ_H;
    __half* srw = srh + REL_H;
    __half2* attd = (__half2*)sk;     // overlay: [pix][72][8] dup pairs
    __half* sout  = sq;               // overlay: [pix][OPS_H]

    int t  = threadIdx.x;
    int w0 = blockIdx.x << 3;
    int h0 = blockIdx.y << 1;
    int nm = blockIdx.z;
    int n  = nm >> 2, m = nm & 3;

    // ---- halo load (fp16 store) ----
    for (int idx = t; idx < 20480; idx += 512) {
        int c   = idx % 10;
        int red = idx / 10;
        int d   = red & 63;
        int e   = (red >> 6) & 7;
        int r   = red >> 9;
        int h2 = h0 + r - 1, w2 = w0 + c - 1;
        float kv = 0.f, vv = 0.f;
        if (h2 >= 0 && h2 < 32 && w2 >= 0 && w2 < 32) {
            size_t gi = (((size_t)(n * 8 + e) * 256) + m * 64 + d) * 1024 + h2 * 32 + w2;
            kv = k[gi]; vv = v[gi];
        }
        int si = (r * 10 + c) * HPS_H + e * EPS_H + d;
        sk[si] = __float2half_rn(kv);
        sv[si] = __float2half_rn(vv);
    }
    // ---- q ----
    for (int idx = t; idx < 8192; idx += 512) {
        int pix = idx & 15, gd = idx >> 4;
        int gq = gd >> 6, d = gd & 63;
        int pr2 = pix >> 3, pc = pix & 7;
        size_t gi = (((size_t)(n * 8 + gq) * 256) + m * 64 + d) * 1024
                    + (h0 + pr2) * 32 + w0 + pc;
        sq[pix * QPS_H + gq * EPS_H + d] = __float2half_rn(q[gi]);
    }
    // ---- rel ----
    for (int idx = t; idx < 768; idx += 512) {
        int d  = idx & 63;
        int ei = idx >> 6;
        int e  = ei / 3, i = ei % 3;
        srh[ei * EPS_H + d] = __float2half_rn(hm [((e * 256 + m * 64 + d) * 3) + i]);
        srw[ei * EPS_H + d] = __float2half_rn(wmm[((e * 256 + m * 64 + d) * 3) + i]);
    }
    __syncthreads();

    int wi = t >> 5, l = t & 31;
    int g  = l >> 2, e0 = l & 3;
    int pr = wi >> 3, cc = (wi & 7) + 1;
    const __half* sqw = sq + wi * QPS_H + g * EPS_H;
    int eoff = e0 * EPS_H;

    int posoff[9];
#pragma unroll
    for (int i = 0; i < 3; i++)
#pragma unroll
        for (int j = 0; j < 3; j++)
            posoff[i * 3 + j] = ((pr + i) * 10 + cc - 1 + j) * HPS_H;

    __half2 z2 = __float2half2_rn(0.f);

    // ---- q . rel (HFMA2, 2-way split accumulators) ----
    __half2 hA2[3][2], hB2[3][2];
#pragma unroll
    for (int u = 0; u < 3; u++) { hA2[u][0]=z2; hA2[u][1]=z2; hB2[u][0]=z2; hB2[u][1]=z2; }
#pragma unroll
    for (int hf = 0; hf < 2; hf++)
#pragma unroll
    for (int d8 = 0; d8 < 4; d8++) {
        int dd = hf * 32 + d8 * 8;
        uint4 qv = *(const uint4*)(sqw + dd);
#pragma unroll
        for (int u = 0; u < 3; u++) {
            uint4 r4 = *(const uint4*)(srh + (e0 * 3 + u) * EPS_H + dd);
            uint4 s4 = *(const uint4*)(srw + (e0 * 3 + u) * EPS_H + dd);
            hA2[u][hf] = __hfma2(h2u(qv.x), h2u(r4.x), hA2[u][hf]);
            hA2[u][hf] = __hfma2(h2u(qv.y), h2u(r4.y), hA2[u][hf]);
            hA2[u][hf] = __hfma2(h2u(qv.z), h2u(r4.z), hA2[u][hf]);
            hA2[u][hf] = __hfma2(h2u(qv.w), h2u(r4.w), hA2[u][hf]);
            hB2[u][hf] = __hfma2(h2u(qv.x), h2u(s4.x), hB2[u][hf]);
            hB2[u][hf] = __hfma2(h2u(qv.y), h2u(s4.y), hB2[u][hf]);
            hB2[u][hf] = __hfma2(h2u(qv.z), h2u(s4.z), hB2[u][hf]);
            hB2[u][hf] = __hfma2(h2u(qv.w), h2u(s4.w), hB2[u][hf]);
        }
    }
    float qrA[3], qrB[3];
#pragma unroll
    for (int u = 0; u < 3; u++) {
        float2 a0 = __half22float2(hA2[u][0]), a1 = __half22float2(hA2[u][1]);
        float2 b0 = __half22float2(hB2[u][0]), b1 = __half22float2(hB2[u][1]);
        qrA[u] = a0.x + a0.y + a1.x + a1.y;
        qrB[u] = b0.x + b0.y + b1.x + b1.y;
    }

    // ---- scores (HFMA2, 2-way split) ----
    __half2 cA2[9][2], cB2[9][2];
#pragma unroll
    for (int u = 0; u < 9; u++) { cA2[u][0]=z2; cA2[u][1]=z2; cB2[u][0]=z2; cB2[u][1]=z2; }
#pragma unroll
    for (int hf = 0; hf < 2; hf++)
#pragma unroll
    for (int d8 = 0; d8 < 4; d8++) {
        int dd = hf * 32 + d8 * 8;
        uint4 qv = *(const uint4*)(sqw + dd);
#pragma unroll
        for (int u = 0; u < 9; u++) {
            const __half* kp = sk + posoff[u] + eoff + dd;
            uint4 ka = *(const uint4*)(kp);
            uint4 kc = *(const uint4*)(kp + 4 * EPS_H);
            cA2[u][hf] = __hfma2(h2u(qv.x), h2u(ka.x), cA2[u][hf]);
            cA2[u][hf] = __hfma2(h2u(qv.y), h2u(ka.y), cA2[u][hf]);
            cA2[u][hf] = __hfma2(h2u(qv.z), h2u(ka.z), cA2[u][hf]);
            cA2[u][hf] = __hfma2(h2u(qv.w), h2u(ka.w), cA2[u][hf]);
            cB2[u][hf] = __hfma2(h2u(qv.x), h2u(kc.x), cB2[u][hf]);
            cB2[u][hf] = __hfma2(h2u(qv.y), h2u(kc.y), cB2[u][hf]);
            cB2[u][hf] = __hfma2(h2u(qv.z), h2u(kc.z), cB2[u][hf]);
            cB2[u][hf] = __hfma2(h2u(qv.w), h2u(kc.w), cB2[u][hf]);
        }
    }
    float sA[9], sB[9];
#pragma unroll
    for (int u = 0; u < 9; u++) {
        float2 a0 = __half22float2(cA2[u][0]), a1 = __half22float2(cA2[u][1]);
        float2 b0 = __half22float2(cB2[u][0]), b1 = __half22float2(cB2[u][1]);
        sA[u] = a0.x + a0.y + a1.x + a1.y + qrA[u / 3];
        sB[u] = b0.x + b0.y + b1.x + b1.y + qrB[u % 3];
    }

    // ---- softmax over 72 (fp32; 4 lanes share same g) ----
    float mx = -1e30f;
#pragma unroll
    for (int u = 0; u < 9; u++) mx = fmaxf(mx, fmaxf(sA[u], sB[u]));
    mx = fmaxf(mx, __shfl_xor_sync(0xffffffffu, mx, 1));
    mx = fmaxf(mx, __shfl_xor_sync(0xffffffffu, mx, 2));
    float sum = 0.f;
#pragma unroll
    for (int u = 0; u < 9; u++) {
        sA[u] = __expf(sA[u] - mx);
        sB[u] = __expf(sB[u] - mx);
        sum += sA[u] + sB[u];
    }
    sum += __shfl_xor_sync(0xffffffffu, sum, 1);
    sum += __shfl_xor_sync(0xffffffffu, sum, 2);
    float inv = 1.f / sum;

    __syncthreads();   // all warps done reading sk (k) and sq (q)

    // ---- store duplicated fp16 attn weights: attd[pix][(e*9+nb)*8+g] ----
    __half2* awT = attd + wi * 576;
#pragma unroll
    for (int u = 0; u < 9; u++) {
        awT[((e0 * 9 + u) * 8 + g)]       = __float2half2_rn(sA[u] * inv);
        awT[(((e0 + 4) * 9 + u) * 8 + g)] = __float2half2_rn(sB[u] * inv);
    }
    __syncwarp();

    // ---- AV: lane owns d = 2l, 2l+1 for all 8 g (HFMA2 accumulation) ----
    __half2 acc2[8];
#pragma unroll
    for (int gg = 0; gg < 8; gg++) acc2[gg] = z2;
#pragma unroll 1
    for (int e = 0; e < 8; e++) {
        const __half* vb = sv + e * EPS_H + 2 * l;
#pragma unroll
        for (int nb = 0; nb < 9; nb++) {
            __half2 v2 = *(const __half2*)(vb + posoff[nb]);
            const uint4* wp2 = (const uint4*)(awT + (e * 9 + nb) * 8);
            uint4 wa = wp2[0], wb = wp2[1];
            acc2[0] = __hfma2(h2u(wa.x), v2, acc2[0]);
            acc2[1] = __hfma2(h2u(wa.y), v2, acc2[1]);
            acc2[2] = __hfma2(h2u(wa.z), v2, acc2[2]);
            acc2[3] = __hfma2(h2u(wa.w), v2, acc2[3]);
            acc2[4] = __hfma2(h2u(wb.x), v2, acc2[4]);
            acc2[5] = __hfma2(h2u(wb.y), v2, acc2[5]);
            acc2[6] = __hfma2(h2u(wb.z), v2, acc2[6]);
            acc2[7] = __hfma2(h2u(wb.w), v2, acc2[7]);
        }
    }
    __half* so = sout + wi * OPS_H;
#pragma unroll
    for (int gg = 0; gg < 8; gg++)
        *(__half2*)(so + gg * 64 + 2 * l) = acc2[gg];
    __syncthreads();

    // ---- transposed fp16 store: avT[bz=n*8+g2][p][m*64+d] ----
#pragma unroll
    for (int it = 0; it < 4; it++) {
        int flat = t + it * 512;           // 2048 = 16pix * 8g * 16dq
        int dq  = flat & 15;
        int g2  = (flat >> 4) & 7;
        int pix = flat >> 7;
        u64 hp = *(const u64*)(sout + pix * OPS_H + g2 * 64 + dq * 4);
        int p = (h0 + (pix >> 3)) * 32 + w0 + (pix & 7);
        size_t o = (((size_t)(n * 8 + g2) * 1024) + p) * 256 + m * 64 + dq * 4;
        *(u64*)(avhT + o) = hp;
    }
}

// ---------------------------------------------------------------------------
// Fused skip + LayerNorm (unchanged).
// ---------------------------------------------------------------------------
__global__ __launch_bounds__(256) void ln_kernel(
    const float* __restrict__ X, const float* __restrict__ Y,
    const float* __restrict__ gamma, const float* __restrict__ beta,
    float* __restrict__ T)
{
    __shared__ float sx[64][33];
    int t  = threadIdx.x;
    int p0 = blockIdx.x << 5;
    int gm = blockIdx.y;
    int g  = gm >> 2, m = gm & 3;
    int n  = blockIdx.z;
    size_t base = (((size_t)(n * 8 + g) * 256) + m * 64) * 1024 + p0;
    int pp = t & 31;
#pragma unroll
    for (int pass = 0; pass < 8; pass++) {
        int d = (t >> 5) + pass * 8;
        sx[d][pp] = X[base + (size_t)d * 1024 + pp] + Y[base + (size_t)d * 1024 + pp];
    }
    __syncthreads();
    int c = t >> 3, sub = t & 7;
    float s1 = 0.f, s2 = 0.f;
#pragma unroll
    for (int u = 0; u < 8; u++) {
        float vv = sx[sub * 8 + u][c];
        s1 += vv; s2 += vv * vv;
    }
#pragma unroll
    for (int off = 1; off < 8; off <<= 1) {
        s1 += __shfl_xor_sync(0xffffffffu, s1, off);
        s2 += __shfl_xor_sync(0xffffffffu, s2, off);
    }
    float mu  = s1 * 0.015625f;
    float var = s2 * 0.015625f - mu * mu;
    float inv = rsqrtf(var + 1e-5f);
    float* op = T + ((((size_t)n * 1024 + p0 + c) * 4 + m) * 8 + g) * 64;
#pragma unroll
    for (int u = 0; u < 8; u++) {
        int d = sub * 8 + u;
        op[d] = (sx[d][c] - mu) * inv * gamma[d] + beta[d];
    }
}

// ---------------------------------------------------------------------------
extern "C" void kernel_launch(void* const* d_in, const int* in_sizes, int n_in,
                              void* d_out, int out_size)
{
    (void)in_sizes; (void)n_in; (void)out_size;
    const float* x     = (const float*)d_in[0];
    const float* wq    = (const float*)d_in[1];
    const float* wk    = (const float*)d_in[2];
    const float* wv    = (const float*)d_in[3];
    const float* hm    = (const float*)d_in[4];
    const float* wm    = (const float*)d_in[5];
    const float* wconv = (const float*)d_in[6];
    const float* bconv = (const float*)d_in[7];
    const float* wf1   = (const float*)d_in[8];
    const float* bf1   = (const float*)d_in[9];
    const float* wf2   = (const float*)d_in[10];
    const float* bf2   = (const float*)d_in[11];
    const float* g1    = (const float*)d_in[12];
    const float* b1    = (const float*)d_in[13];
    const float* g2    = (const float*)d_in[14];
    const float* b2    = (const float*)d_in[15];

    float *qkv, *y, *tb, *h1, *f;
    __half *xhT, *whi, *wlo;
    cudaGetSymbolAddress((void**)&qkv, g_qkv);
    cudaGetSymbolAddress((void**)&y,   g_y);
    cudaGetSymbolAddress((void**)&tb,  g_t);
    cudaGetSymbolAddress((void**)&h1,  g_h1);
    cudaGetSymbolAddress((void**)&f,   g_f);
    cudaGetSymbolAddress((void**)&xhT, g_xhT);
    cudaGetSymbolAddress((void**)&whi, g_whi);
    cudaGetSymbolAddress((void**)&wlo, g_wlo);

    cudaFuncSetAttribute(attn_kernel,
                         cudaFuncAttributeMaxDynamicSharedMemorySize, ATTN_SMEM_B);
    const int GEMM_SMEM = 98304;
    cudaFuncSetAttribute(hgemm_kernel,
                         cudaFuncAttributeMaxDynamicSharedMemorySize, GEMM_SMEM);

    const size_t WS = 524288;        // per-slot W elements
    const size_t QS = 8388608;       // per-slot qkv floats
    dim3 cxgrid(32, 8, 32);

    convw_kernel<<<dim3(512, 6), 256>>>(wq, wk, wv, wconv, wf1, wf2, whi, wlo);
    convx_kernel<<<cxgrid, 256>>>(x, xhT);

    // fused q/k/v GEMM: slots 0..2 in one launch
    hgemm_kernel<<<dim3(8, 6, 32), 256, GEMM_SMEM>>>(whi, wlo, xhT, nullptr, qkv, 0);

    attn_kernel<<<dim3(4, 16, 16), 512, ATTN_SMEM_B>>>(qkv, qkv + QS, qkv + 2 * QS,
                                                       hm, wm, xhT);

    hgemm_kernel<<<dim3(8, 2, 32), 256, GEMM_SMEM>>>(whi + 3*WS, wlo + 3*WS, xhT, bconv, y, 0);
    ln_kernel<<<dim3(32, 32, 4), 256>>>(x, y, g1, b1, tb);

    convx_kernel<<<cxgrid, 256>>>(tb, xhT);
    hgemm_kernel<<<dim3(8, 2, 32), 256, GEMM_SMEM>>>(whi + 4*WS, wlo + 4*WS, xhT, bf1, h1, 1);

    convx_kernel<<<cxgrid, 256>>>(h1, xhT);
    hgemm_kernel<<<dim3(8, 2, 32), 256, GEMM_SMEM>>>(whi + 5*WS, wlo + 5*WS, xhT, bf2, f, 0);

    ln_kernel<<<dim3(32, 32, 4), 256>>>(tb, f, g2, b2, (float*)d_out);
}

// round 10
// speedup vs baseline: 4.2595x; 1.2385x over previous
#include <cuda_runtime.h>
#include <cuda_fp16.h>
#include <cstdint>

#define HWP 1024

// fp32 scratch
__device__ float g_y [4*8*256*HWP];
__device__ float g_t [4*8*256*HWP];
__device__ float g_f [4*8*256*HWP];
// fp16 buffers
__device__ __half g_qkv[3*32*256*HWP];  // q,k,v fp16, plain [bz][c][p]
__device__ __half g_xhT[32*1024*256];   // activations [bz][p][k]
__device__ __half g_xh2[32*1024*256];   // second transposed buffer (h1)
__device__ __half g_whi[6*8*256*256];   // fp16 weights [slot][g][o][k]

typedef unsigned long long u64;
__device__ __forceinline__ uint32_t smem_u32(const void* p) {
    uint32_t a;
    asm("{ .reg .u64 tmp; cvta.to.shared.u64 tmp, %1; cvt.u32.u64 %0, tmp; }"
        : "=r"(a) : "l"(p));
    return a;
}
__device__ __forceinline__ void ldsm4(uint32_t* r, uint32_t addr) {
    asm volatile("ldmatrix.sync.aligned.m8n8.x4.shared.b16 {%0,%1,%2,%3}, [%4];"
        : "=r"(r[0]), "=r"(r[1]), "=r"(r[2]), "=r"(r[3]) : "r"(addr));
}
__device__ __forceinline__ void mma_f16(float* c, const uint32_t* a,
                                        uint32_t b0, uint32_t b1) {
    asm volatile("mma.sync.aligned.m16n8k16.row.col.f32.f16.f16.f32 "
        "{%0,%1,%2,%3}, {%4,%5,%6,%7}, {%8,%9}, {%0,%1,%2,%3};"
        : "+f"(c[0]), "+f"(c[1]), "+f"(c[2]), "+f"(c[3])
        : "r"(a[0]), "r"(a[1]), "r"(a[2]), "r"(a[3]), "r"(b0), "r"(b1));
}
__device__ __forceinline__ void cpasync16(uint32_t saddr, const void* g) {
    asm volatile("cp.async.cg.shared.global [%0], [%1], 16;" :: "r"(saddr), "l"(g));
}
#define CP_COMMIT() asm volatile("cp.async.commit_group;" ::: "memory")
__device__ __forceinline__ __half2 h2u(uint32_t v) {
    __half2 h; *(uint32_t*)&h = v; return h;
}

// ---------------------------------------------------------------------------
// fp32 W -> fp16. grid (512, 6)
// ---------------------------------------------------------------------------
__global__ __launch_bounds__(256) void convw_kernel(
    const float* __restrict__ w0, const float* __restrict__ w1,
    const float* __restrict__ w2, const float* __restrict__ w3,
    const float* __restrict__ w4, const float* __restrict__ w5,
    __half* __restrict__ whi)
{
    const float* srcs[6] = {w0, w1, w2, w3, w4, w5};
    int slot = blockIdx.y;
    size_t idx = ((size_t)blockIdx.x * 256 + threadIdx.x) * 4;
    float4 v = *(const float4*)(srcs[slot] + idx);
    float vv[4] = {v.x, v.y, v.z, v.w};
    u64 hp = 0;
#pragma unroll
    for (int j = 0; j < 4; j++)
        hp |= (u64)__half_as_ushort(__float2half_rn(vv[j])) << (16 * j);
    *(u64*)(whi + (size_t)slot * 524288 + idx) = hp;
}

// ---------------------------------------------------------------------------
// Transpose + fp16: X [bz][k=256][p=1024] fp32 -> hT [bz][p][k].
// ---------------------------------------------------------------------------
__global__ __launch_bounds__(256) void convx_kernel(
    const float* __restrict__ X, __half* __restrict__ hT)
{
    __shared__ float s[32][33];
    int t = threadIdx.x;
    int pt = blockIdx.x, kt = blockIdx.y, bz = blockIdx.z;
    const float* Xb = X + ((size_t)bz * 256 + kt * 32) * 1024 + pt * 32;
    int kr = t >> 5, pc = t & 31;
#pragma unroll
    for (int i = 0; i < 4; i++)
        s[kr + i * 8][pc] = Xb[(size_t)(kr + i * 8) * 1024 + pc];
    __syncthreads();
    int pr = t >> 3, kq = t & 7;
    u64 hp = 0;
#pragma unroll
    for (int j = 0; j < 4; j++)
        hp |= (u64)__half_as_ushort(__float2half_rn(s[kq * 4 + j][pr])) << (16 * j);
    size_t o = ((size_t)bz * 1024 + pt * 32 + pr) * 256 + kt * 32 + kq * 4;
    *(u64*)(hT + o) = hp;
}

// ---------------------------------------------------------------------------
// HMMA GEMM, single-pass fp16, cp.async 3-stage ring over 4 k-chunks.
// grid (8, 2*nslots, 32): slot = by>>1, o-tile = by&1.
// mode: 0 = fp32 plain -> Cf ; 1 = fp16 plain -> Ch ; 2 = fp16 transposed -> Ch
// ---------------------------------------------------------------------------
__global__ __launch_bounds__(256, 2) void hgemm_kernel(
    const __half* __restrict__ whi, const __half* __restrict__ xhT,
    const float* __restrict__ bias, float* __restrict__ Cf,
    __half* __restrict__ Ch, int mode, int relu)
{
    extern __shared__ char smem[];
    uint32_t sbase = smem_u32(smem);

    int t  = threadIdx.x;
    int wi = t >> 5, l = t & 31;
    int wo = wi >> 2, wp = wi & 3;
    int slot = blockIdx.y >> 1;
    int p0 = blockIdx.x * 128, o0 = (blockIdx.y & 1) * 128;
    int bz = blockIdx.z, g = bz & 7;

    const __half* Ahi = whi + (size_t)slot * 524288 + (size_t)g * 65536;
    const __half* Bhi = xhT + (size_t)bz * 262144;

    float acc[4][4][4];
#pragma unroll
    for (int i = 0; i < 4; i++)
#pragma unroll
        for (int j = 0; j < 4; j++)
#pragma unroll
            for (int r = 0; r < 4; r++) acc[i][j][r] = 0.f;

    int rowi[4], kqi[4], swoff[4];
#pragma unroll
    for (int i = 0; i < 4; i++) {
        int v2 = t + i * 256;
        rowi[i] = v2 >> 3; kqi[i] = v2 & 7;
        int off = rowi[i] * 128 + kqi[i] * 16;
        swoff[i] = off ^ ((off >> 3) & 0x70);
    }

    int a_row_l = (l & 15), a_col_l = (l >> 4) << 4;
    int b_quad = l >> 3, b_lr = l & 7;
    int b_row_l = ((b_quad >> 1) << 3) + b_lr;
    int b_col_l = (b_quad & 1) << 4;

#define ISSUE_STAGE(s) do {                                                    \
        int k0_ = (s) * 64;                                                    \
        uint32_t sa_ = sbase + ((s) % 3) * 16384;                              \
        uint32_t sb_ = sbase + 49152 + ((s) % 3) * 16384;                      \
        _Pragma("unroll")                                                      \
        for (int i_ = 0; i_ < 4; i_++) {                                       \
            cpasync16(sa_ + swoff[i_],                                         \
                Ahi + ((size_t)(o0 + rowi[i_]) * 256 + k0_ + kqi[i_] * 8));    \
            cpasync16(sb_ + swoff[i_],                                         \
                Bhi + ((size_t)(p0 + rowi[i_]) * 256 + k0_ + kqi[i_] * 8));    \
        }                                                                      \
        CP_COMMIT();                                                           \
    } while (0)

    ISSUE_STAGE(0);
    ISSUE_STAGE(1);

    for (int s = 0; s < 4; s++) {
        if (s < 3) asm volatile("cp.async.wait_group 1;" ::: "memory");
        else       asm volatile("cp.async.wait_group 0;" ::: "memory");
        __syncthreads();
        if (s < 2) ISSUE_STAGE(s + 2);

        uint32_t sa = sbase + (s % 3) * 16384;
        uint32_t sb = sbase + 49152 + (s % 3) * 16384;
#pragma unroll
        for (int ks = 0; ks < 4; ks++) {
            uint32_t af[4][4];
#pragma unroll
            for (int i = 0; i < 4; i++) {
                int row = wo * 64 + i * 16 + a_row_l;
                int off = row * 128 + ks * 32 + a_col_l;
                ldsm4(af[i], sa + (off ^ ((off >> 3) & 0x70)));
            }
            uint32_t bfr[2][4];
#pragma unroll
            for (int j2 = 0; j2 < 2; j2++) {
                int n = wp * 32 + j2 * 16 + b_row_l;
                int off = n * 128 + ks * 32 + b_col_l;
                ldsm4(bfr[j2], sb + (off ^ ((off >> 3) & 0x70)));
            }
#pragma unroll
            for (int i = 0; i < 4; i++)
#pragma unroll
                for (int j = 0; j < 4; j++)
                    mma_f16(acc[i][j], af[i], bfr[j >> 1][(j & 1) * 2],
                            bfr[j >> 1][(j & 1) * 2 + 1]);
        }
    }
#undef ISSUE_STAGE

    if (mode == 2) {
        // fp16 transposed epilogue via smem stage: out[bz][p][k=o]
        __syncthreads();
        __half* st = (__half*)smem;   // [col(p_local)][row(o_local)], stride 136
#pragma unroll
        for (int i = 0; i < 4; i++) {
            int row = wo * 64 + i * 16 + (l >> 2);
            float b0 = bias ? bias[g * 256 + o0 + row]     : 0.f;
            float b8 = bias ? bias[g * 256 + o0 + row + 8] : 0.f;
#pragma unroll
            for (int j = 0; j < 4; j++) {
                int col = wp * 32 + j * 8 + (l & 3) * 2;
                float v0 = acc[i][j][0] + b0, v1 = acc[i][j][1] + b0;
                float v2 = acc[i][j][2] + b8, v3 = acc[i][j][3] + b8;
                if (relu) {
                    v0 = fmaxf(v0, 0.f); v1 = fmaxf(v1, 0.f);
                    v2 = fmaxf(v2, 0.f); v3 = fmaxf(v3, 0.f);
                }
                st[col * 136 + row]           = __float2half_rn(v0);
                st[(col + 1) * 136 + row]     = __float2half_rn(v1);
                st[col * 136 + row + 8]       = __float2half_rn(v2);
                st[(col + 1) * 136 + row + 8] = __float2half_rn(v3);
            }
        }
        __syncthreads();
#pragma unroll
        for (int it = 0; it < 8; it++) {
            int idx = t + it * 256;
            int col = idx >> 4, ch = idx & 15;
            uint4 vls = *(const uint4*)(st + col * 136 + ch * 8);
            *(uint4*)(Ch + ((size_t)bz * 1024 + p0 + col) * 256 + o0 + ch * 8) = vls;
        }
        return;
    }

    if (mode == 1) {
        __half* Cb = Ch + (size_t)slot * 8388608 + (size_t)bz * 262144;
#pragma unroll
        for (int i = 0; i < 4; i++) {
            int row = o0 + wo * 64 + i * 16 + (l >> 2);
#pragma unroll
            for (int j = 0; j < 4; j++) {
                int col = p0 + wp * 32 + j * 8 + (l & 3) * 2;
                __half2 h0 = __floats2half2_rn(acc[i][j][0], acc[i][j][1]);
                __half2 h1 = __floats2half2_rn(acc[i][j][2], acc[i][j][3]);
                *(__half2*)(Cb + (size_t)row * 1024 + col)       = h0;
                *(__half2*)(Cb + (size_t)(row + 8) * 1024 + col) = h1;
            }
        }
        return;
    }

    float* Cb = Cf + (size_t)bz * 262144;
#pragma unroll
    for (int i = 0; i < 4; i++) {
        int row = o0 + wo * 64 + i * 16 + (l >> 2);
        float b0 = bias ? bias[g * 256 + row]     : 0.f;
        float b8 = bias ? bias[g * 256 + row + 8] : 0.f;
#pragma unroll
        for (int j = 0; j < 4; j++) {
            int col = p0 + wp * 32 + j * 8 + (l & 3) * 2;
            float2 v0 = make_float2(acc[i][j][0] + b0, acc[i][j][1] + b0);
            float2 v1 = make_float2(acc[i][j][2] + b8, acc[i][j][3] + b8);
            if (relu) {
                v0.x = fmaxf(v0.x, 0.f); v0.y = fmaxf(v0.y, 0.f);
                v1.x = fmaxf(v1.x, 0.f); v1.y = fmaxf(v1.y, 0.f);
            }
            *(float2*)(Cb + (size_t)row * 1024 + col)       = v0;
            *(float2*)(Cb + (size_t)(row + 8) * 1024 + col) = v1;
        }
    }
}

// ---------------------------------------------------------------------------
// Windowed attention, fp16 in/out, fp16 smem + HFMA2, 2 CTAs/SM.
// ---------------------------------------------------------------------------
#define EPS_H 72
#define HPS_H 576
#define QPS_H 576
#define OPS_H 520
#define SK_H (40*HPS_H)
#define SQ_H (16*QPS_H)
#define REL_H (12*EPS_H)
#define ATTN_SMEM_B ((SK_H*2 + SQ_H + REL_H*2) * 2)

__global__ __launch_bounds__(512, 2) void attn_kernel(
    const __half* __restrict__ q, const __half* __restrict__ k,
    const __half* __restrict__ v, const float* __restrict__ hm,
    const float* __restrict__ wmm, __half* __restrict__ avhT)
{
    extern __shared__ __half smemh[];
    __half* sk  = smemh;
    __half* sv  = sk + SK_H;
    __half* sq  = sv + SK_H;
    __half* srh = sq + SQ_H;
    __half* srw = srh + REL_H;
    __half2* attd = (__half2*)sk;
    __half* sout  = sq;

    int t  = threadIdx.x;
    int w0 = blockIdx.x << 3;
    int h0 = blockIdx.y << 1;
    int nm = blockIdx.z;
    int n  = nm >> 2, m = nm & 3;

    for (int idx = t; idx < 20480; idx += 512) {
        int c   = idx % 10;
        int red = idx / 10;
        int d   = red & 63;
        int e   = (red >> 6) & 7;
        int r   = red >> 9;
        int h2 = h0 + r - 1, w2 = w0 + c - 1;
        __half kv = __ushort_as_half(0), vv = __ushort_as_half(0);
        if (h2 >= 0 && h2 < 32 && w2 >= 0 && w2 < 32) {
            size_t gi = (((size_t)(n * 8 + e) * 256) + m * 64 + d) * 1024 + h2 * 32 + w2;
            kv = k[gi]; vv = v[gi];
        }
        int si = (r * 10 + c) * HPS_H + e * EPS_H + d;
        sk[si] = kv; sv[si] = vv;
    }
    for (int idx = t; idx < 8192; idx += 512) {
        int pix = idx & 15, gd = idx >> 4;
        int gq = gd >> 6, d = gd & 63;
        int pr2 = pix >> 3, pc = pix & 7;
        size_t gi = (((size_t)(n * 8 + gq) * 256) + m * 64 + d) * 1024
                    + (h0 + pr2) * 32 + w0 + pc;
        sq[pix * QPS_H + gq * EPS_H + d] = q[gi];
    }
    for (int idx = t; idx < 768; idx += 512) {
        int d  = idx & 63;
        int ei = idx >> 6;
        int e  = ei / 3, i = ei % 3;
        srh[ei * EPS_H + d] = __float2half_rn(hm [((e * 256 + m * 64 + d) * 3) + i]);
        srw[ei * EPS_H + d] = __float2half_rn(wmm[((e * 256 + m * 64 + d) * 3) + i]);
    }
    __syncthreads();

    int wi = t >> 5, l = t & 31;
    int g  = l >> 2, e0 = l & 3;
    int pr = wi >> 3, cc = (wi & 7) + 1;
    const __half* sqw = sq + wi * QPS_H + g * EPS_H;
    int eoff = e0 * EPS_H;

    int posoff[9];
#pragma unroll
    for (int i = 0; i < 3; i++)
#pragma unroll
        for (int j = 0; j < 3; j++)
            posoff[i * 3 + j] = ((pr + i) * 10 + cc - 1 + j) * HPS_H;

    __half2 z2 = __float2half2_rn(0.f);

    __half2 hA2[3][2], hB2[3][2];
#pragma unroll
    for (int u = 0; u < 3; u++) { hA2[u][0]=z2; hA2[u][1]=z2; hB2[u][0]=z2; hB2[u][1]=z2; }
#pragma unroll
    for (int hf = 0; hf < 2; hf++)
#pragma unroll
    for (int d8 = 0; d8 < 4; d8++) {
        int dd = hf * 32 + d8 * 8;
        uint4 qv = *(const uint4*)(sqw + dd);
#pragma unroll
        for (int u = 0; u < 3; u++) {
            uint4 r4 = *(const uint4*)(srh + (e0 * 3 + u) * EPS_H + dd);
            uint4 s4 = *(const uint4*)(srw + (e0 * 3 + u) * EPS_H + dd);
            hA2[u][hf] = __hfma2(h2u(qv.x), h2u(r4.x), hA2[u][hf]);
            hA2[u][hf] = __hfma2(h2u(qv.y), h2u(r4.y), hA2[u][hf]);
            hA2[u][hf] = __hfma2(h2u(qv.z), h2u(r4.z), hA2[u][hf]);
            hA2[u][hf] = __hfma2(h2u(qv.w), h2u(r4.w), hA2[u][hf]);
            hB2[u][hf] = __hfma2(h2u(qv.x), h2u(s4.x), hB2[u][hf]);
            hB2[u][hf] = __hfma2(h2u(qv.y), h2u(s4.y), hB2[u][hf]);
            hB2[u][hf] = __hfma2(h2u(qv.z), h2u(s4.z), hB2[u][hf]);
            hB2[u][hf] = __hfma2(h2u(qv.w), h2u(s4.w), hB2[u][hf]);
        }
    }
    float qrA[3], qrB[3];
#pragma unroll
    for (int u = 0; u < 3; u++) {
        float2 a0 = __half22float2(hA2[u][0]), a1 = __half22float2(hA2[u][1]);
        float2 b0 = __half22float2(hB2[u][0]), b1 = __half22float2(hB2[u][1]);
        qrA[u] = a0.x + a0.y + a1.x + a1.y;
        qrB[u] = b0.x + b0.y + b1.x + b1.y;
    }

    __half2 cA2[9][2], cB2[9][2];
#pragma unroll
    for (int u = 0; u < 9; u++) { cA2[u][0]=z2; cA2[u][1]=z2; cB2[u][0]=z2; cB2[u][1]=z2; }
#pragma unroll
    for (int hf = 0; hf < 2; hf++)
#pragma unroll
    for (int d8 = 0; d8 < 4; d8++) {
        int dd = hf * 32 + d8 * 8;
        uint4 qv = *(const uint4*)(sqw + dd);
#pragma unroll
        for (int u = 0; u < 9; u++) {
            const __half* kp = sk + posoff[u] + eoff + dd;
            uint4 ka = *(const uint4*)(kp);
            uint4 kc = *(const uint4*)(kp + 4 * EPS_H);
            cA2[u][hf] = __hfma2(h2u(qv.x), h2u(ka.x), cA2[u][hf]);
            cA2[u][hf] = __hfma2(h2u(qv.y), h2u(ka.y), cA2[u][hf]);
            cA2[u][hf] = __hfma2(h2u(qv.z), h2u(ka.z), cA2[u][hf]);
            cA2[u][hf] = __hfma2(h2u(qv.w), h2u(ka.w), cA2[u][hf]);
            cB2[u][hf] = __hfma2(h2u(qv.x), h2u(kc.x), cB2[u][hf]);
            cB2[u][hf] = __hfma2(h2u(qv.y), h2u(kc.y), cB2[u][hf]);
            cB2[u][hf] = __hfma2(h2u(qv.z), h2u(kc.z), cB2[u][hf]);
            cB2[u][hf] = __hfma2(h2u(qv.w), h2u(kc.w), cB2[u][hf]);
        }
    }
    float sA[9], sB[9];
#pragma unroll
    for (int u = 0; u < 9; u++) {
        float2 a0 = __half22float2(cA2[u][0]), a1 = __half22float2(cA2[u][1]);
        float2 b0 = __half22float2(cB2[u][0]), b1 = __half22float2(cB2[u][1]);
        sA[u] = a0.x + a0.y + a1.x + a1.y + qrA[u / 3];
        sB[u] = b0.x + b0.y + b1.x + b1.y + qrB[u % 3];
    }

    float mx = -1e30f;
#pragma unroll
    for (int u = 0; u < 9; u++) mx = fmaxf(mx, fmaxf(sA[u], sB[u]));
    mx = fmaxf(mx, __shfl_xor_sync(0xffffffffu, mx, 1));
    mx = fmaxf(mx, __shfl_xor_sync(0xffffffffu, mx, 2));
    float sum = 0.f;
#pragma unroll
    for (int u = 0; u < 9; u++) {
        sA[u] = __expf(sA[u] - mx);
        sB[u] = __expf(sB[u] - mx);
        sum += sA[u] + sB[u];
    }
    sum += __shfl_xor_sync(0xffffffffu, sum, 1);
    sum += __shfl_xor_sync(0xffffffffu, sum, 2);
    float inv = 1.f / sum;

    __syncthreads();

    __half2* awT = attd + wi * 576;
#pragma unroll
    for (int u = 0; u < 9; u++) {
        awT[((e0 * 9 + u) * 8 + g)]       = __float2half2_rn(sA[u] * inv);
        awT[(((e0 + 4) * 9 + u) * 8 + g)] = __float2half2_rn(sB[u] * inv);
    }
    __syncwarp();

    __half2 acc2[8];
#pragma unroll
    for (int gg = 0; gg < 8; gg++) acc2[gg] = z2;
#pragma unroll 1
    for (int e = 0; e < 8; e++) {
        const __half* vb = sv + e * EPS_H + 2 * l;
#pragma unroll
        for (int nb = 0; nb < 9; nb++) {
            __half2 v2 = *(const __half2*)(vb + posoff[nb]);
            const uint4* wp2 = (const uint4*)(awT + (e * 9 + nb) * 8);
            uint4 wa = wp2[0], wb = wp2[1];
            acc2[0] = __hfma2(h2u(wa.x), v2, acc2[0]);
            acc2[1] = __hfma2(h2u(wa.y), v2, acc2[1]);
            acc2[2] = __hfma2(h2u(wa.z), v2, acc2[2]);
            acc2[3] = __hfma2(h2u(wa.w), v2, acc2[3]);
            acc2[4] = __hfma2(h2u(wb.x), v2, acc2[4]);
            acc2[5] = __hfma2(h2u(wb.y), v2, acc2[5]);
            acc2[6] = __hfma2(h2u(wb.z), v2, acc2[6]);
            acc2[7] = __hfma2(h2u(wb.w), v2, acc2[7]);
        }
    }
    __half* so = sout + wi * OPS_H;
#pragma unroll
    for (int gg = 0; gg < 8; gg++)
        *(__half2*)(so + gg * 64 + 2 * l) = acc2[gg];
    __syncthreads();

#pragma unroll
    for (int it = 0; it < 4; it++) {
        int flat = t + it * 512;
        int dq  = flat & 15;
        int g2  = (flat >> 4) & 7;
        int pix = flat >> 7;
        u64 hp = *(const u64*)(sout + pix * OPS_H + g2 * 64 + dq * 4);
        int p = (h0 + (pix >> 3)) * 32 + w0 + (pix & 7);
        size_t o = (((size_t)(n * 8 + g2) * 1024) + p) * 256 + m * 64 + dq * 4;
        *(u64*)(avhT + o) = hp;
    }
}

// ---------------------------------------------------------------------------
// Fused skip + LayerNorm (unchanged).
// ---------------------------------------------------------------------------
__global__ __launch_bounds__(256) void ln_kernel(
    const float* __restrict__ X, const float* __restrict__ Y,
    const float* __restrict__ gamma, const float* __restrict__ beta,
    float* __restrict__ T)
{
    __shared__ float sx[64][33];
    int t  = threadIdx.x;
    int p0 = blockIdx.x << 5;
    int gm = blockIdx.y;
    int g  = gm >> 2, m = gm & 3;
    int n  = blockIdx.z;
    size_t base = (((size_t)(n * 8 + g) * 256) + m * 64) * 1024 + p0;
    int pp = t & 31;
#pragma unroll
    for (int pass = 0; pass < 8; pass++) {
        int d = (t >> 5) + pass * 8;
        sx[d][pp] = X[base + (size_t)d * 1024 + pp] + Y[base + (size_t)d * 1024 + pp];
    }
    __syncthreads();
    int c = t >> 3, sub = t & 7;
    float s1 = 0.f, s2 = 0.f;
#pragma unroll
    for (int u = 0; u < 8; u++) {
        float vv = sx[sub * 8 + u][c];
        s1 += vv; s2 += vv * vv;
    }
#pragma unroll
    for (int off = 1; off < 8; off <<= 1) {
        s1 += __shfl_xor_sync(0xffffffffu, s1, off);
        s2 += __shfl_xor_sync(0xffffffffu, s2, off);
    }
    float mu  = s1 * 0.015625f;
    float var = s2 * 0.015625f - mu * mu;
    float inv = rsqrtf(var + 1e-5f);
    float* op = T + ((((size_t)n * 1024 + p0 + c) * 4 + m) * 8 + g) * 64;
#pragma unroll
    for (int u = 0; u < 8; u++) {
        int d = sub * 8 + u;
        op[d] = (sx[d][c] - mu) * inv * gamma[d] + beta[d];
    }
}

// ---------------------------------------------------------------------------
extern "C" void kernel_launch(void* const* d_in, const int* in_sizes, int n_in,
                              void* d_out, int out_size)
{
    (void)in_sizes; (void)n_in; (void)out_size;
    const float* x     = (const float*)d_in[0];
    const float* wq    = (const float*)d_in[1];
    const float* wk    = (const float*)d_in[2];
    const float* wv    = (const float*)d_in[3];
    const float* hm    = (const float*)d_in[4];
    const float* wm    = (const float*)d_in[5];
    const float* wconv = (const float*)d_in[6];
    const float* bconv = (const float*)d_in[7];
    const float* wf1   = (const float*)d_in[8];
    const float* bf1   = (const float*)d_in[9];
    const float* wf2   = (const float*)d_in[10];
    const float* bf2   = (const float*)d_in[11];
    const float* g1    = (const float*)d_in[12];
    const float* b1    = (const float*)d_in[13];
    const float* g2    = (const float*)d_in[14];
    const float* b2    = (const float*)d_in[15];

    float *y, *tb, *f;
    __half *qkvh, *xhT, *xh2, *whi;
    cudaGetSymbolAddress((void**)&y,    g_y);
    cudaGetSymbolAddress((void**)&tb,   g_t);
    cudaGetSymbolAddress((void**)&f,    g_f);
    cudaGetSymbolAddress((void**)&qkvh, g_qkv);
    cudaGetSymbolAddress((void**)&xhT,  g_xhT);
    cudaGetSymbolAddress((void**)&xh2,  g_xh2);
    cudaGetSymbolAddress((void**)&whi,  g_whi);

    cudaFuncSetAttribute(attn_kernel,
                         cudaFuncAttributeMaxDynamicSharedMemorySize, ATTN_SMEM_B);
    const int GEMM_SMEM = 98304;
    cudaFuncSetAttribute(hgemm_kernel,
                         cudaFuncAttributeMaxDynamicSharedMemorySize, GEMM_SMEM);

    const size_t WS = 524288;        // per-slot W elements
    const size_t QS = 8388608;       // per-slot qkv halves
    dim3 cxgrid(32, 8, 32);

    convw_kernel<<<dim3(512, 6), 256>>>(wq, wk, wv, wconv, wf1, wf2, whi);
    convx_kernel<<<cxgrid, 256>>>(x, xhT);

    // fused q/k/v GEMM -> fp16 plain
    hgemm_kernel<<<dim3(8, 6, 32), 256, GEMM_SMEM>>>(whi, xhT, nullptr,
                                                     nullptr, qkvh, 1, 0);

    attn_kernel<<<dim3(4, 16, 16), 512, ATTN_SMEM_B>>>(qkvh, qkvh + QS, qkvh + 2 * QS,
                                                       hm, wm, xhT);

    // w_conv GEMM -> fp32 y
    hgemm_kernel<<<dim3(8, 2, 32), 256, GEMM_SMEM>>>(whi + 3*WS, xhT, bconv,
                                                     y, nullptr, 0, 0);
    ln_kernel<<<dim3(32, 32, 4), 256>>>(x, y, g1, b1, tb);

    convx_kernel<<<cxgrid, 256>>>(tb, xhT);
    // f1 GEMM (relu) -> fp16 transposed into xh2 (feeds f2 directly)
    hgemm_kernel<<<dim3(8, 2, 32), 256, GEMM_SMEM>>>(whi + 4*WS, xhT, bf1,
                                                     nullptr, xh2, 2, 1);
    // f2 GEMM -> fp32 f
    hgemm_kernel<<<dim3(8, 2, 32), 256, GEMM_SMEM>>>(whi + 5*WS, xh2, bf2,
                                                     f, nullptr, 0, 0);

    ln_kernel<<<dim3(32, 32, 4), 256>>>(tb, f, g2, b2, (float*)d_out);
}

// round 12
// speedup vs baseline: 5.2940x; 1.2428x over previous
#include <cuda_runtime.h>
#include <cuda_fp16.h>
#include <cstdint>

#define HWP 1024

// fp32 scratch
__device__ float g_y [4*8*256*HWP];
__device__ float g_t [4*8*256*HWP];
__device__ float g_f [4*8*256*HWP];
// fp16 buffers
__device__ __half g_qkv[3*32*256*HWP];  // q,k,v fp16 TRANSPOSED [bz][p][c]
__device__ __half g_xhT[32*1024*256];   // activations [bz][p][k]
__device__ __half g_xh2[32*1024*256];   // second transposed buffer (h1)
__device__ __half g_whi[6*8*256*256];   // fp16 weights [slot][g][o][k]

typedef unsigned long long u64;
__device__ __forceinline__ uint32_t smem_u32(const void* p) {
    uint32_t a;
    asm("{ .reg .u64 tmp; cvta.to.shared.u64 tmp, %1; cvt.u32.u64 %0, tmp; }"
        : "=r"(a) : "l"(p));
    return a;
}
__device__ __forceinline__ void ldsm4(uint32_t* r, uint32_t addr) {
    asm volatile("ldmatrix.sync.aligned.m8n8.x4.shared.b16 {%0,%1,%2,%3}, [%4];"
        : "=r"(r[0]), "=r"(r[1]), "=r"(r[2]), "=r"(r[3]) : "r"(addr));
}
__device__ __forceinline__ void mma_f16(float* c, const uint32_t* a,
                                        uint32_t b0, uint32_t b1) {
    asm volatile("mma.sync.aligned.m16n8k16.row.col.f32.f16.f16.f32 "
        "{%0,%1,%2,%3}, {%4,%5,%6,%7}, {%8,%9}, {%0,%1,%2,%3};"
        : "+f"(c[0]), "+f"(c[1]), "+f"(c[2]), "+f"(c[3])
        : "r"(a[0]), "r"(a[1]), "r"(a[2]), "r"(a[3]), "r"(b0), "r"(b1));
}
__device__ __forceinline__ void cpasync16(uint32_t saddr, const void* g) {
    asm volatile("cp.async.cg.shared.global [%0], [%1], 16;" :: "r"(saddr), "l"(g));
}
#define CP_COMMIT() asm volatile("cp.async.commit_group;" ::: "memory")
__device__ __forceinline__ __half2 h2u(uint32_t v) {
    __half2 h; *(uint32_t*)&h = v; return h;
}

// ---------------------------------------------------------------------------
// fp32 W -> fp16. grid (512, 6)
// ---------------------------------------------------------------------------
__global__ __launch_bounds__(256) void convw_kernel(
    const float* __restrict__ w0, const float* __restrict__ w1,
    const float* __restrict__ w2, const float* __restrict__ w3,
    const float* __restrict__ w4, const float* __restrict__ w5,
    __half* __restrict__ whi)
{
    const float* srcs[6] = {w0, w1, w2, w3, w4, w5};
    int slot = blockIdx.y;
    size_t idx = ((size_t)blockIdx.x * 256 + threadIdx.x) * 4;
    float4 v = *(const float4*)(srcs[slot] + idx);
    float vv[4] = {v.x, v.y, v.z, v.w};
    u64 hp = 0;
#pragma unroll
    for (int j = 0; j < 4; j++)
        hp |= (u64)__half_as_ushort(__float2half_rn(vv[j])) << (16 * j);
    *(u64*)(whi + (size_t)slot * 524288 + idx) = hp;
}

// ---------------------------------------------------------------------------
// Transpose + fp16: X [bz][k=256][p=1024] fp32 -> hT [bz][p][k].
// ---------------------------------------------------------------------------
__global__ __launch_bounds__(256) void convx_kernel(
    const float* __restrict__ X, __half* __restrict__ hT)
{
    __shared__ float s[32][33];
    int t = threadIdx.x;
    int pt = blockIdx.x, kt = blockIdx.y, bz = blockIdx.z;
    const float* Xb = X + ((size_t)bz * 256 + kt * 32) * 1024 + pt * 32;
    int kr = t >> 5, pc = t & 31;
#pragma unroll
    for (int i = 0; i < 4; i++)
        s[kr + i * 8][pc] = Xb[(size_t)(kr + i * 8) * 1024 + pc];
    __syncthreads();
    int pr = t >> 3, kq = t & 7;
    u64 hp = 0;
#pragma unroll
    for (int j = 0; j < 4; j++)
        hp |= (u64)__half_as_ushort(__float2half_rn(s[kq * 4 + j][pr])) << (16 * j);
    size_t o = ((size_t)bz * 1024 + pt * 32 + pr) * 256 + kt * 32 + kq * 4;
    *(u64*)(hT + o) = hp;
}

// ---------------------------------------------------------------------------
// HMMA GEMM, single-pass fp16, cp.async 3-stage ring over 4 k-chunks.
// grid (8, 2*nslots, 32): slot = by>>1, o-tile = by&1.
// mode: 0 = fp32 plain -> Cf ; 2 = fp16 transposed [bz][p][o] -> Ch (+slot)
// ---------------------------------------------------------------------------
__global__ __launch_bounds__(256, 2) void hgemm_kernel(
    const __half* __restrict__ whi, const __half* __restrict__ xhT,
    const float* __restrict__ bias, float* __restrict__ Cf,
    __half* __restrict__ Ch, int mode, int relu)
{
    extern __shared__ char smem[];
    uint32_t sbase = smem_u32(smem);

    int t  = threadIdx.x;
    int wi = t >> 5, l = t & 31;
    int wo = wi >> 2, wp = wi & 3;
    int slot = blockIdx.y >> 1;
    int p0 = blockIdx.x * 128, o0 = (blockIdx.y & 1) * 128;
    int bz = blockIdx.z, g = bz & 7;

    const __half* Ahi = whi + (size_t)slot * 524288 + (size_t)g * 65536;
    const __half* Bhi = xhT + (size_t)bz * 262144;

    float acc[4][4][4];
#pragma unroll
    for (int i = 0; i < 4; i++)
#pragma unroll
        for (int j = 0; j < 4; j++)
#pragma unroll
            for (int r = 0; r < 4; r++) acc[i][j][r] = 0.f;

    int rowi[4], kqi[4], swoff[4];
#pragma unroll
    for (int i = 0; i < 4; i++) {
        int v2 = t + i * 256;
        rowi[i] = v2 >> 3; kqi[i] = v2 & 7;
        int off = rowi[i] * 128 + kqi[i] * 16;
        swoff[i] = off ^ ((off >> 3) & 0x70);
    }

    int a_row_l = (l & 15), a_col_l = (l >> 4) << 4;
    int b_quad = l >> 3, b_lr = l & 7;
    int b_row_l = ((b_quad >> 1) << 3) + b_lr;
    int b_col_l = (b_quad & 1) << 4;

#define ISSUE_STAGE(s) do {                                                    \
        int k0_ = (s) * 64;                                                    \
        uint32_t sa_ = sbase + ((s) % 3) * 16384;                              \
        uint32_t sb_ = sbase + 49152 + ((s) % 3) * 16384;                      \
        _Pragma("unroll")                                                      \
        for (int i_ = 0; i_ < 4; i_++) {                                       \
            cpasync16(sa_ + swoff[i_],                                         \
                Ahi + ((size_t)(o0 + rowi[i_]) * 256 + k0_ + kqi[i_] * 8));    \
            cpasync16(sb_ + swoff[i_],                                         \
                Bhi + ((size_t)(p0 + rowi[i_]) * 256 + k0_ + kqi[i_] * 8));    \
        }                                                                      \
        CP_COMMIT();                                                           \
    } while (0)

    ISSUE_STAGE(0);
    ISSUE_STAGE(1);

    for (int s = 0; s < 4; s++) {
        if (s < 3) asm volatile("cp.async.wait_group 1;" ::: "memory");
        else       asm volatile("cp.async.wait_group 0;" ::: "memory");
        __syncthreads();
        if (s < 2) ISSUE_STAGE(s + 2);

        uint32_t sa = sbase + (s % 3) * 16384;
        uint32_t sb = sbase + 49152 + (s % 3) * 16384;
#pragma unroll
        for (int ks = 0; ks < 4; ks++) {
            uint32_t af[4][4];
#pragma unroll
            for (int i = 0; i < 4; i++) {
                int row = wo * 64 + i * 16 + a_row_l;
                int off = row * 128 + ks * 32 + a_col_l;
                ldsm4(af[i], sa + (off ^ ((off >> 3) & 0x70)));
            }
            uint32_t bfr[2][4];
#pragma unroll
            for (int j2 = 0; j2 < 2; j2++) {
                int n = wp * 32 + j2 * 16 + b_row_l;
                int off = n * 128 + ks * 32 + b_col_l;
                ldsm4(bfr[j2], sb + (off ^ ((off >> 3) & 0x70)));
            }
#pragma unroll
            for (int i = 0; i < 4; i++)
#pragma unroll
                for (int j = 0; j < 4; j++)
                    mma_f16(acc[i][j], af[i], bfr[j >> 1][(j & 1) * 2],
                            bfr[j >> 1][(j & 1) * 2 + 1]);
        }
    }
#undef ISSUE_STAGE

    if (mode == 2) {
        // fp16 transposed epilogue via smem stage: out[bz][p][o]
        __syncthreads();
        __half* st = (__half*)smem;   // [col(p_local)][row(o_local)], stride 136
#pragma unroll
        for (int i = 0; i < 4; i++) {
            int row = wo * 64 + i * 16 + (l >> 2);
            float b0 = bias ? bias[g * 256 + o0 + row]     : 0.f;
            float b8 = bias ? bias[g * 256 + o0 + row + 8] : 0.f;
#pragma unroll
            for (int j = 0; j < 4; j++) {
                int col = wp * 32 + j * 8 + (l & 3) * 2;
                float v0 = acc[i][j][0] + b0, v1 = acc[i][j][1] + b0;
                float v2 = acc[i][j][2] + b8, v3 = acc[i][j][3] + b8;
                if (relu) {
                    v0 = fmaxf(v0, 0.f); v1 = fmaxf(v1, 0.f);
                    v2 = fmaxf(v2, 0.f); v3 = fmaxf(v3, 0.f);
                }
                st[col * 136 + row]           = __float2half_rn(v0);
                st[(col + 1) * 136 + row]     = __float2half_rn(v1);
                st[col * 136 + row + 8]       = __float2half_rn(v2);
                st[(col + 1) * 136 + row + 8] = __float2half_rn(v3);
            }
        }
        __syncthreads();
        __half* Cb = Ch + (size_t)slot * 8388608;
#pragma unroll
        for (int it = 0; it < 8; it++) {
            int idx = t + it * 256;
            int col = idx >> 4, ch = idx & 15;
            uint4 vls = *(const uint4*)(st + col * 136 + ch * 8);
            *(uint4*)(Cb + ((size_t)bz * 1024 + p0 + col) * 256 + o0 + ch * 8) = vls;
        }
        return;
    }

    float* Cb = Cf + (size_t)bz * 262144;
#pragma unroll
    for (int i = 0; i < 4; i++) {
        int row = o0 + wo * 64 + i * 16 + (l >> 2);
        float b0 = bias ? bias[g * 256 + row]     : 0.f;
        float b8 = bias ? bias[g * 256 + row + 8] : 0.f;
#pragma unroll
        for (int j = 0; j < 4; j++) {
            int col = p0 + wp * 32 + j * 8 + (l & 3) * 2;
            float2 v0 = make_float2(acc[i][j][0] + b0, acc[i][j][1] + b0);
            float2 v1 = make_float2(acc[i][j][2] + b8, acc[i][j][3] + b8);
            if (relu) {
                v0.x = fmaxf(v0.x, 0.f); v0.y = fmaxf(v0.y, 0.f);
                v1.x = fmaxf(v1.x, 0.f); v1.y = fmaxf(v1.y, 0.f);
            }
            *(float2*)(Cb + (size_t)row * 1024 + col)       = v0;
            *(float2*)(Cb + (size_t)(row + 8) * 1024 + col) = v1;
        }
    }
}

// ---------------------------------------------------------------------------
// Windowed attention; q/k/v read from TRANSPOSED fp16 [bz][p][c] with
// vectorized u64 loads. fp16 smem + HFMA2, 2 CTAs/SM.
// ---------------------------------------------------------------------------
#define EPS_H 72
#define HPS_H 576
#define QPS_H 576
#define OPS_H 520
#define SK_H (40*HPS_H)
#define SQ_H (16*QPS_H)
#define REL_H (12*EPS_H)
#define ATTN_SMEM_B ((SK_H*2 + SQ_H + REL_H*2) * 2)

__global__ __launch_bounds__(512, 2) void attn_kernel(
    const __half* __restrict__ q, const __half* __restrict__ k,
    const __half* __restrict__ v, const float* __restrict__ hm,
    const float* __restrict__ wmm, __half* __restrict__ avhT)
{
    extern __shared__ __half smemh[];
    __half* sk  = smemh;
    __half* sv  = sk + SK_H;
    __half* sq  = sv + SK_H;
    __half* srh = sq + SQ_H;
    __half* srw = srh + REL_H;
    __half2* attd = (__half2*)sk;
    __half* sout  = sq;

    int t  = threadIdx.x;
    int w0 = blockIdx.x << 3;
    int h0 = blockIdx.y << 1;
    int nm = blockIdx.z;
    int n  = nm >> 2, m = nm & 3;

    // ---- halo load: 40 pos x 8 e x 16 d-quads, u64 vectors ----
    for (int idx = t; idx < 5120; idx += 512) {
        int d4  = idx & 15;
        int e   = (idx >> 4) & 7;
        int pos = idx >> 7;                 // 0..39
        int r = pos / 10, c = pos % 10;
        int h2 = h0 + r - 1, w2 = w0 + c - 1;
        u64 kv = 0, vv = 0;
        if (h2 >= 0 && h2 < 32 && w2 >= 0 && w2 < 32) {
            size_t gi = (((size_t)(n * 8 + e) * 1024) + h2 * 32 + w2) * 256
                        + m * 64 + d4 * 4;
            kv = *(const u64*)(k + gi);
            vv = *(const u64*)(v + gi);
        }
        int si = pos * HPS_H + e * EPS_H + d4 * 4;
        *(u64*)(sk + si) = kv;
        *(u64*)(sv + si) = vv;
    }
    // ---- q: 16 pix x 8 g x 16 d-quads ----
    for (int idx = t; idx < 2048; idx += 512) {
        int d4  = idx & 15;
        int gq  = (idx >> 4) & 7;
        int pix = idx >> 7;
        int p = (h0 + (pix >> 3)) * 32 + w0 + (pix & 7);
        size_t gi = (((size_t)(n * 8 + gq) * 1024) + p) * 256 + m * 64 + d4 * 4;
        *(u64*)(sq + pix * QPS_H + gq * EPS_H + d4 * 4) = *(const u64*)(q + gi);
    }
    // ---- rel ----
    for (int idx = t; idx < 768; idx += 512) {
        int d  = idx & 63;
        int ei = idx >> 6;
        int e  = ei / 3, i = ei % 3;
        srh[ei * EPS_H + d] = __float2half_rn(hm [((e * 256 + m * 64 + d) * 3) + i]);
        srw[ei * EPS_H + d] = __float2half_rn(wmm[((e * 256 + m * 64 + d) * 3) + i]);
    }
    __syncthreads();

    int wi = t >> 5, l = t & 31;
    int g  = l >> 2, e0 = l & 3;
    int pr = wi >> 3, cc = (wi & 7) + 1;
    const __half* sqw = sq + wi * QPS_H + g * EPS_H;
    int eoff = e0 * EPS_H;

    int posoff[9];
#pragma unroll
    for (int i = 0; i < 3; i++)
#pragma unroll
        for (int j = 0; j < 3; j++)
            posoff[i * 3 + j] = ((pr + i) * 10 + cc - 1 + j) * HPS_H;

    __half2 z2 = __float2half2_rn(0.f);

    __half2 hA2[3][2], hB2[3][2];
#pragma unroll
    for (int u = 0; u < 3; u++) { hA2[u][0]=z2; hA2[u][1]=z2; hB2[u][0]=z2; hB2[u][1]=z2; }
#pragma unroll
    for (int hf = 0; hf < 2; hf++)
#pragma unroll
    for (int d8 = 0; d8 < 4; d8++) {
        int dd = hf * 32 + d8 * 8;
        uint4 qv = *(const uint4*)(sqw + dd);
#pragma unroll
        for (int u = 0; u < 3; u++) {
            uint4 r4 = *(const uint4*)(srh + (e0 * 3 + u) * EPS_H + dd);
            uint4 s4 = *(const uint4*)(srw + (e0 * 3 + u) * EPS_H + dd);
            hA2[u][hf] = __hfma2(h2u(qv.x), h2u(r4.x), hA2[u][hf]);
            hA2[u][hf] = __hfma2(h2u(qv.y), h2u(r4.y), hA2[u][hf]);
            hA2[u][hf] = __hfma2(h2u(qv.z), h2u(r4.z), hA2[u][hf]);
            hA2[u][hf] = __hfma2(h2u(qv.w), h2u(r4.w), hA2[u][hf]);
            hB2[u][hf] = __hfma2(h2u(qv.x), h2u(s4.x), hB2[u][hf]);
            hB2[u][hf] = __hfma2(h2u(qv.y), h2u(s4.y), hB2[u][hf]);
            hB2[u][hf] = __hfma2(h2u(qv.z), h2u(s4.z), hB2[u][hf]);
            hB2[u][hf] = __hfma2(h2u(qv.w), h2u(s4.w), hB2[u][hf]);
        }
    }
    float qrA[3], qrB[3];
#pragma unroll
    for (int u = 0; u < 3; u++) {
        float2 a0 = __half22float2(hA2[u][0]), a1 = __half22float2(hA2[u][1]);
        float2 b0 = __half22float2(hB2[u][0]), b1 = __half22float2(hB2[u][1]);
        qrA[u] = a0.x + a0.y + a1.x + a1.y;
        qrB[u] = b0.x + b0.y + b1.x + b1.y;
    }

    __half2 cA2[9][2], cB2[9][2];
#pragma unroll
    for (int u = 0; u < 9; u++) { cA2[u][0]=z2; cA2[u][1]=z2; cB2[u][0]=z2; cB2[u][1]=z2; }
#pragma unroll
    for (int hf = 0; hf < 2; hf++)
#pragma unroll
    for (int d8 = 0; d8 < 4; d8++) {
        int dd = hf * 32 + d8 * 8;
        uint4 qv = *(const uint4*)(sqw + dd);
#pragma unroll
        for (int u = 0; u < 9; u++) {
            const __half* kp = sk + posoff[u] + eoff + dd;
            uint4 ka = *(const uint4*)(kp);
            uint4 kc = *(const uint4*)(kp + 4 * EPS_H);
            cA2[u][hf] = __hfma2(h2u(qv.x), h2u(ka.x), cA2[u][hf]);
            cA2[u][hf] = __hfma2(h2u(qv.y), h2u(ka.y), cA2[u][hf]);
            cA2[u][hf] = __hfma2(h2u(qv.z), h2u(ka.z), cA2[u][hf]);
            cA2[u][hf] = __hfma2(h2u(qv.w), h2u(ka.w), cA2[u][hf]);
            cB2[u][hf] = __hfma2(h2u(qv.x), h2u(kc.x), cB2[u][hf]);
            cB2[u][hf] = __hfma2(h2u(qv.y), h2u(kc.y), cB2[u][hf]);
            cB2[u][hf] = __hfma2(h2u(qv.z), h2u(kc.z), cB2[u][hf]);
            cB2[u][hf] = __hfma2(h2u(qv.w), h2u(kc.w), cB2[u][hf]);
        }
    }
    float sA[9], sB[9];
#pragma unroll
    for (int u = 0; u < 9; u++) {
        float2 a0 = __half22float2(cA2[u][0]), a1 = __half22float2(cA2[u][1]);
        float2 b0 = __half22float2(cB2[u][0]), b1 = __half22float2(cB2[u][1]);
        sA[u] = a0.x + a0.y + a1.x + a1.y + qrA[u / 3];
        sB[u] = b0.x + b0.y + b1.x + b1.y + qrB[u % 3];
    }

    float mx = -1e30f;
#pragma unroll
    for (int u = 0; u < 9; u++) mx = fmaxf(mx, fmaxf(sA[u], sB[u]));
    mx = fmaxf(mx, __shfl_xor_sync(0xffffffffu, mx, 1));
    mx = fmaxf(mx, __shfl_xor_sync(0xffffffffu, mx, 2));
    float sum = 0.f;
#pragma unroll
    for (int u = 0; u < 9; u++) {
        sA[u] = __expf(sA[u] - mx);
        sB[u] = __expf(sB[u] - mx);
        sum += sA[u] + sB[u];
    }
    sum += __shfl_xor_sync(0xffffffffu, sum, 1);
    sum += __shfl_xor_sync(0xffffffffu, sum, 2);
    float inv = 1.f / sum;

    __syncthreads();

    __half2* awT = attd + wi * 576;
#pragma unroll
    for (int u = 0; u < 9; u++) {
        awT[((e0 * 9 + u) * 8 + g)]       = __float2half2_rn(sA[u] * inv);
        awT[(((e0 + 4) * 9 + u) * 8 + g)] = __float2half2_rn(sB[u] * inv);
    }
    __syncwarp();

    __half2 acc2[8];
#pragma unroll
    for (int gg = 0; gg < 8; gg++) acc2[gg] = z2;
#pragma unroll 1
    for (int e = 0; e < 8; e++) {
        const __half* vb = sv + e * EPS_H + 2 * l;
#pragma unroll
        for (int nb = 0; nb < 9; nb++) {
            __half2 v2 = *(const __half2*)(vb + posoff[nb]);
            const uint4* wp2 = (const uint4*)(awT + (e * 9 + nb) * 8);
            uint4 wa = wp2[0], wb = wp2[1];
            acc2[0] = __hfma2(h2u(wa.x), v2, acc2[0]);
            acc2[1] = __hfma2(h2u(wa.y), v2, acc2[1]);
            acc2[2] = __hfma2(h2u(wa.z), v2, acc2[2]);
            acc2[3] = __hfma2(h2u(wa.w), v2, acc2[3]);
            acc2[4] = __hfma2(h2u(wb.x), v2, acc2[4]);
            acc2[5] = __hfma2(h2u(wb.y), v2, acc2[5]);
            acc2[6] = __hfma2(h2u(wb.z), v2, acc2[6]);
            acc2[7] = __hfma2(h2u(wb.w), v2, acc2[7]);
        }
    }
    __half* so = sout + wi * OPS_H;
#pragma unroll
    for (int gg = 0; gg < 8; gg++)
        *(__half2*)(so + gg * 64 + 2 * l) = acc2[gg];
    __syncthreads();

#pragma unroll
    for (int it = 0; it < 4; it++) {
        int flat = t + it * 512;
        int dq  = flat & 15;
        int g2  = (flat >> 4) & 7;
        int pix = flat >> 7;
        u64 hp = *(const u64*)(sout + pix * OPS_H + g2 * 64 + dq * 4);
        int p = (h0 + (pix >> 3)) * 32 + w0 + (pix & 7);
        size_t o = (((size_t)(n * 8 + g2) * 1024) + p) * 256 + m * 64 + dq * 4;
        *(u64*)(avhT + o) = hp;
    }
}

// ---------------------------------------------------------------------------
// Fused skip + LayerNorm (fp32 scrambled-layout output only).
// ---------------------------------------------------------------------------
__global__ __launch_bounds__(256) void ln_kernel(
    const float* __restrict__ X, const float* __restrict__ Y,
    const float* __restrict__ gamma, const float* __restrict__ beta,
    float* __restrict__ T)
{
    __shared__ float sx[64][33];
    int t  = threadIdx.x;
    int p0 = blockIdx.x << 5;
    int gm = blockIdx.y;
    int g  = gm >> 2, m = gm & 3;
    int n  = blockIdx.z;
    size_t base = (((size_t)(n * 8 + g) * 256) + m * 64) * 1024 + p0;
    int pp = t & 31;
#pragma unroll
    for (int pass = 0; pass < 8; pass++) {
        int d = (t >> 5) + pass * 8;
        sx[d][pp] = X[base + (size_t)d * 1024 + pp] + Y[base + (size_t)d * 1024 + pp];
    }
    __syncthreads();
    int c = t >> 3, sub = t & 7;
    float s1 = 0.f, s2 = 0.f;
#pragma unroll
    for (int u = 0; u < 8; u++) {
        float vv = sx[sub * 8 + u][c];
        s1 += vv; s2 += vv * vv;
    }
#pragma unroll
    for (int off = 1; off < 8; off <<= 1) {
        s1 += __shfl_xor_sync(0xffffffffu, s1, off);
        s2 += __shfl_xor_sync(0xffffffffu, s2, off);
    }
    float mu  = s1 * 0.015625f;
    float var = s2 * 0.015625f - mu * mu;
    float inv = rsqrtf(var + 1e-5f);
    float* op = T + ((((size_t)n * 1024 + p0 + c) * 4 + m) * 8 + g) * 64;
#pragma unroll
    for (int u = 0; u < 8; u++) {
        int d = sub * 8 + u;
        op[d] = (sx[d][c] - mu) * inv * gamma[d] + beta[d];
    }
}

// ---------------------------------------------------------------------------
extern "C" void kernel_launch(void* const* d_in, const int* in_sizes, int n_in,
                              void* d_out, int out_size)
{
    (void)in_sizes; (void)n_in; (void)out_size;
    const float* x     = (const float*)d_in[0];
    const float* wq    = (const float*)d_in[1];
    const float* wk    = (const float*)d_in[2];
    const float* wv    = (const float*)d_in[3];
    const float* hm    = (const float*)d_in[4];
    const float* wm    = (const float*)d_in[5];
    const float* wconv = (const float*)d_in[6];
    const float* bconv = (const float*)d_in[7];
    const float* wf1   = (const float*)d_in[8];
    const float* bf1   = (const float*)d_in[9];
    const float* wf2   = (const float*)d_in[10];
    const float* bf2   = (const float*)d_in[11];
    const float* g1    = (const float*)d_in[12];
    const float* b1    = (const float*)d_in[13];
    const float* g2    = (const float*)d_in[14];
    const float* b2    = (const float*)d_in[15];

    float *y, *tb, *f;
    __half *qkvh, *xhT, *xh2, *whi;
    cudaGetSymbolAddress((void**)&y,    g_y);
    cudaGetSymbolAddress((void**)&tb,   g_t);
    cudaGetSymbolAddress((void**)&f,    g_f);
    cudaGetSymbolAddress((void**)&qkvh, g_qkv);
    cudaGetSymbolAddress((void**)&xhT,  g_xhT);
    cudaGetSymbolAddress((void**)&xh2,  g_xh2);
    cudaGetSymbolAddress((void**)&whi,  g_whi);

    cudaFuncSetAttribute(attn_kernel,
                         cudaFuncAttributeMaxDynamicSharedMemorySize, ATTN_SMEM_B);
    const int GEMM_SMEM = 98304;
    cudaFuncSetAttribute(hgemm_kernel,
                         cudaFuncAttributeMaxDynamicSharedMemorySize, GEMM_SMEM);

    const size_t WS = 524288;        // per-slot W elements
    const size_t QS = 8388608;       // per-slot qkv halves
    dim3 cxgrid(32, 8, 32);

    convw_kernel<<<dim3(512, 6), 256>>>(wq, wk, wv, wconv, wf1, wf2, whi);
    convx_kernel<<<cxgrid, 256>>>(x, xhT);

    // fused q/k/v GEMM -> fp16 TRANSPOSED [bz][p][c] per slot
    hgemm_kernel<<<dim3(8, 6, 32), 256, GEMM_SMEM>>>(whi, xhT, nullptr,
                                                     nullptr, qkvh, 2, 0);

    attn_kernel<<<dim3(4, 16, 16), 512, ATTN_SMEM_B>>>(qkvh, qkvh + QS, qkvh + 2 * QS,
                                                       hm, wm, xhT);

    // w_conv GEMM -> fp32 y
    hgemm_kernel<<<dim3(8, 2, 32), 256, GEMM_SMEM>>>(whi + 3*WS, xhT, bconv,
                                                     y, nullptr, 0, 0);
    // ln1 -> fp32 tb (scrambled layout)
    ln_kernel<<<dim3(32, 32, 4), 256>>>(x, y, g1, b1, tb);

    // transpose+convert tb for f1 GEMM
    convx_kernel<<<cxgrid, 256>>>(tb, xhT);
    // f1 GEMM (relu) -> fp16 transposed into xh2 (feeds f2 directly)
    hgemm_kernel<<<dim3(8, 2, 32), 256, GEMM_SMEM>>>(whi + 4*WS, xhT, bf1,
                                                     nullptr, xh2, 2, 1);
    // f2 GEMM -> fp32 f
    hgemm_kernel<<<dim3(8, 2, 32), 256, GEMM_SMEM>>>(whi + 5*WS, xh2, bf2,
                                                     f, nullptr, 0, 0);

    ln_kernel<<<dim3(32, 32, 4), 256>>>(tb, f, g2, b2, (float*)d_out);
}

// round 13
// speedup vs baseline: 6.1006x; 1.1524x over previous
#include <cuda_runtime.h>
#include <cuda_fp16.h>
#include <cstdint>

#define HWP 1024

// fp32 scratch
__device__ float g_t [4*8*256*HWP];     // tb (scrambled layout)
// fp16 buffers
__device__ __half g_qkv[3*32*256*HWP];  // q,k,v fp16 TRANSPOSED [bz][p][c]
__device__ __half g_xhT[32*1024*256];   // activations [bz][p][k]
__device__ __half g_xh2[32*1024*256];   // second transposed buffer (h1)
__device__ __half g_whi[6*8*256*256];   // fp16 weights [slot][g][o][k]

typedef unsigned long long u64;
__device__ __forceinline__ uint32_t smem_u32(const void* p) {
    uint32_t a;
    asm("{ .reg .u64 tmp; cvta.to.shared.u64 tmp, %1; cvt.u32.u64 %0, tmp; }"
        : "=r"(a) : "l"(p));
    return a;
}
__device__ __forceinline__ void ldsm4(uint32_t* r, uint32_t addr) {
    asm volatile("ldmatrix.sync.aligned.m8n8.x4.shared.b16 {%0,%1,%2,%3}, [%4];"
        : "=r"(r[0]), "=r"(r[1]), "=r"(r[2]), "=r"(r[3]) : "r"(addr));
}
__device__ __forceinline__ void mma_f16(float* c, const uint32_t* a,
                                        uint32_t b0, uint32_t b1) {
    asm volatile("mma.sync.aligned.m16n8k16.row.col.f32.f16.f16.f32 "
        "{%0,%1,%2,%3}, {%4,%5,%6,%7}, {%8,%9}, {%0,%1,%2,%3};"
        : "+f"(c[0]), "+f"(c[1]), "+f"(c[2]), "+f"(c[3])
        : "r"(a[0]), "r"(a[1]), "r"(a[2]), "r"(a[3]), "r"(b0), "r"(b1));
}
__device__ __forceinline__ void cpasync16(uint32_t saddr, const void* g) {
    asm volatile("cp.async.cg.shared.global [%0], [%1], 16;" :: "r"(saddr), "l"(g));
}
#define CP_COMMIT() asm volatile("cp.async.commit_group;" ::: "memory")
__device__ __forceinline__ __half2 h2u(uint32_t v) {
    __half2 h; *(uint32_t*)&h = v; return h;
}

// ---------------------------------------------------------------------------
// fp32 W -> fp16. grid (512, 6)
// ---------------------------------------------------------------------------
__global__ __launch_bounds__(256) void convw_kernel(
    const float* __restrict__ w0, const float* __restrict__ w1,
    const float* __restrict__ w2, const float* __restrict__ w3,
    const float* __restrict__ w4, const float* __restrict__ w5,
    __half* __restrict__ whi)
{
    const float* srcs[6] = {w0, w1, w2, w3, w4, w5};
    int slot = blockIdx.y;
    size_t idx = ((size_t)blockIdx.x * 256 + threadIdx.x) * 4;
    float4 v = *(const float4*)(srcs[slot] + idx);
    float vv[4] = {v.x, v.y, v.z, v.w};
    u64 hp = 0;
#pragma unroll
    for (int j = 0; j < 4; j++)
        hp |= (u64)__half_as_ushort(__float2half_rn(vv[j])) << (16 * j);
    *(u64*)(whi + (size_t)slot * 524288 + idx) = hp;
}

// ---------------------------------------------------------------------------
// Transpose + fp16: X [bz][k=256][p=1024] fp32 -> hT [bz][p][k].
// ---------------------------------------------------------------------------
__global__ __launch_bounds__(256) void convx_kernel(
    const float* __restrict__ X, __half* __restrict__ hT)
{
    __shared__ float s[32][33];
    int t = threadIdx.x;
    int pt = blockIdx.x, kt = blockIdx.y, bz = blockIdx.z;
    const float* Xb = X + ((size_t)bz * 256 + kt * 32) * 1024 + pt * 32;
    int kr = t >> 5, pc = t & 31;
#pragma unroll
    for (int i = 0; i < 4; i++)
        s[kr + i * 8][pc] = Xb[(size_t)(kr + i * 8) * 1024 + pc];
    __syncthreads();
    int pr = t >> 3, kq = t & 7;
    u64 hp = 0;
#pragma unroll
    for (int j = 0; j < 4; j++)
        hp |= (u64)__half_as_ushort(__float2half_rn(s[kq * 4 + j][pr])) << (16 * j);
    size_t o = ((size_t)bz * 1024 + pt * 32 + pr) * 256 + kt * 32 + kq * 4;
    *(u64*)(hT + o) = hp;
}

// ---------------------------------------------------------------------------
// HMMA GEMM, single-pass fp16, cp.async 3-stage ring over 4 k-chunks.
// grid (8, 2*nslots, 32): slot = by>>1, o-tile = by&1.
// mode 2: fp16 transposed [bz][p][o] -> Ch (+slot offset), bias+relu.
// mode 3: fused skip+LayerNorm -> Cf in SCRAMBLED layout
//         ((n*1024+p)*4+m)*8+g)*64+d. Xskip fp32 plain [bz][o][p].
// ---------------------------------------------------------------------------
__global__ __launch_bounds__(256, 2) void hgemm_kernel(
    const __half* __restrict__ whi, const __half* __restrict__ xhT,
    const float* __restrict__ bias, float* __restrict__ Cf,
    __half* __restrict__ Ch, const float* __restrict__ Xskip,
    const float* __restrict__ gam, const float* __restrict__ bet,
    int mode, int relu)
{
    extern __shared__ char smem[];
    uint32_t sbase = smem_u32(smem);

    int t  = threadIdx.x;
    int wi = t >> 5, l = t & 31;
    int wo = wi >> 2, wp = wi & 3;
    int slot = blockIdx.y >> 1;
    int p0 = blockIdx.x * 128, o0 = (blockIdx.y & 1) * 128;
    int bz = blockIdx.z, g = bz & 7;

    const __half* Ahi = whi + (size_t)slot * 524288 + (size_t)g * 65536;
    const __half* Bhi = xhT + (size_t)bz * 262144;

    float acc[4][4][4];
#pragma unroll
    for (int i = 0; i < 4; i++)
#pragma unroll
        for (int j = 0; j < 4; j++)
#pragma unroll
            for (int r = 0; r < 4; r++) acc[i][j][r] = 0.f;

    int rowi[4], kqi[4], swoff[4];
#pragma unroll
    for (int i = 0; i < 4; i++) {
        int v2 = t + i * 256;
        rowi[i] = v2 >> 3; kqi[i] = v2 & 7;
        int off = rowi[i] * 128 + kqi[i] * 16;
        swoff[i] = off ^ ((off >> 3) & 0x70);
    }

    int a_row_l = (l & 15), a_col_l = (l >> 4) << 4;
    int b_quad = l >> 3, b_lr = l & 7;
    int b_row_l = ((b_quad >> 1) << 3) + b_lr;
    int b_col_l = (b_quad & 1) << 4;

#define ISSUE_STAGE(s) do {                                                    \
        int k0_ = (s) * 64;                                                    \
        uint32_t sa_ = sbase + ((s) % 3) * 16384;                              \
        uint32_t sb_ = sbase + 49152 + ((s) % 3) * 16384;                      \
        _Pragma("unroll")                                                      \
        for (int i_ = 0; i_ < 4; i_++) {                                       \
            cpasync16(sa_ + swoff[i_],                                         \
                Ahi + ((size_t)(o0 + rowi[i_]) * 256 + k0_ + kqi[i_] * 8));    \
            cpasync16(sb_ + swoff[i_],                                         \
                Bhi + ((size_t)(p0 + rowi[i_]) * 256 + k0_ + kqi[i_] * 8));    \
        }                                                                      \
        CP_COMMIT();                                                           \
    } while (0)

    ISSUE_STAGE(0);
    ISSUE_STAGE(1);

    for (int s = 0; s < 4; s++) {
        if (s < 3) asm volatile("cp.async.wait_group 1;" ::: "memory");
        else       asm volatile("cp.async.wait_group 0;" ::: "memory");
        __syncthreads();
        if (s < 2) ISSUE_STAGE(s + 2);

        uint32_t sa = sbase + (s % 3) * 16384;
        uint32_t sb = sbase + 49152 + (s % 3) * 16384;
#pragma unroll
        for (int ks = 0; ks < 4; ks++) {
            uint32_t af[4][4];
#pragma unroll
            for (int i = 0; i < 4; i++) {
                int row = wo * 64 + i * 16 + a_row_l;
                int off = row * 128 + ks * 32 + a_col_l;
                ldsm4(af[i], sa + (off ^ ((off >> 3) & 0x70)));
            }
            uint32_t bfr[2][4];
#pragma unroll
            for (int j2 = 0; j2 < 2; j2++) {
                int n = wp * 32 + j2 * 16 + b_row_l;
                int off = n * 128 + ks * 32 + b_col_l;
                ldsm4(bfr[j2], sb + (off ^ ((off >> 3) & 0x70)));
            }
#pragma unroll
            for (int i = 0; i < 4; i++)
#pragma unroll
                for (int j = 0; j < 4; j++)
                    mma_f16(acc[i][j], af[i], bfr[j >> 1][(j & 1) * 2],
                            bfr[j >> 1][(j & 1) * 2 + 1]);
        }
    }
#undef ISSUE_STAGE

    if (mode == 2) {
        // fp16 transposed epilogue via smem stage: out[bz][p][o]
        __syncthreads();
        __half* st = (__half*)smem;   // [col][row], stride 136
#pragma unroll
        for (int i = 0; i < 4; i++) {
            int row = wo * 64 + i * 16 + (l >> 2);
            float b0 = bias ? bias[g * 256 + o0 + row]     : 0.f;
            float b8 = bias ? bias[g * 256 + o0 + row + 8] : 0.f;
#pragma unroll
            for (int j = 0; j < 4; j++) {
                int col = wp * 32 + j * 8 + (l & 3) * 2;
                float v0 = acc[i][j][0] + b0, v1 = acc[i][j][1] + b0;
                float v2 = acc[i][j][2] + b8, v3 = acc[i][j][3] + b8;
                if (relu) {
                    v0 = fmaxf(v0, 0.f); v1 = fmaxf(v1, 0.f);
                    v2 = fmaxf(v2, 0.f); v3 = fmaxf(v3, 0.f);
                }
                st[col * 136 + row]           = __float2half_rn(v0);
                st[(col + 1) * 136 + row]     = __float2half_rn(v1);
                st[col * 136 + row + 8]       = __float2half_rn(v2);
                st[(col + 1) * 136 + row + 8] = __float2half_rn(v3);
            }
        }
        __syncthreads();
        __half* Cb = Ch + (size_t)slot * 8388608;
#pragma unroll
        for (int it = 0; it < 8; it++) {
            int idx = t + it * 256;
            int col = idx >> 4, ch = idx & 15;
            uint4 vls = *(const uint4*)(st + col * 136 + ch * 8);
            *(uint4*)(Cb + ((size_t)bz * 1024 + p0 + col) * 256 + o0 + ch * 8) = vls;
        }
        return;
    }

    // ---- mode 3: fused skip + LayerNorm -> scrambled fp32 ----
    // rows all within one m-group per thread (wo selects the 64-row group).
    const float* Xb = Xskip + (size_t)bz * 262144;
    float s1[4][2], s2[4][2];
#pragma unroll
    for (int j = 0; j < 4; j++) { s1[j][0]=0.f; s1[j][1]=0.f; s2[j][0]=0.f; s2[j][1]=0.f; }
#pragma unroll
    for (int i = 0; i < 4; i++) {
        int row = o0 + wo * 64 + i * 16 + (l >> 2);
        float b0 = bias ? bias[g * 256 + row]     : 0.f;
        float b8 = bias ? bias[g * 256 + row + 8] : 0.f;
#pragma unroll
        for (int j = 0; j < 4; j++) {
            int col = p0 + wp * 32 + j * 8 + (l & 3) * 2;
            float2 x0 = *(const float2*)(Xb + (size_t)row * 1024 + col);
            float2 x1 = *(const float2*)(Xb + (size_t)(row + 8) * 1024 + col);
            acc[i][j][0] += b0 + x0.x;
            acc[i][j][1] += b0 + x0.y;
            acc[i][j][2] += b8 + x1.x;
            acc[i][j][3] += b8 + x1.y;
            s1[j][0] += acc[i][j][0] + acc[i][j][2];
            s1[j][1] += acc[i][j][1] + acc[i][j][3];
            s2[j][0] += acc[i][j][0]*acc[i][j][0] + acc[i][j][2]*acc[i][j][2];
            s2[j][1] += acc[i][j][1]*acc[i][j][1] + acc[i][j][3]*acc[i][j][3];
        }
    }
    // reduce across the 8 lanes sharing (l&3): full 64-row column sums
#pragma unroll
    for (int mk = 4; mk < 32; mk <<= 1) {
#pragma unroll
        for (int j = 0; j < 4; j++) {
            s1[j][0] += __shfl_xor_sync(0xffffffffu, s1[j][0], mk);
            s1[j][1] += __shfl_xor_sync(0xffffffffu, s1[j][1], mk);
            s2[j][0] += __shfl_xor_sync(0xffffffffu, s2[j][0], mk);
            s2[j][1] += __shfl_xor_sync(0xffffffffu, s2[j][1], mk);
        }
    }
    float mu[4][2], rs[4][2];
#pragma unroll
    for (int j = 0; j < 4; j++)
#pragma unroll
        for (int c2 = 0; c2 < 2; c2++) {
            mu[j][c2] = s1[j][c2] * 0.015625f;
            float var = s2[j][c2] * 0.015625f - mu[j][c2] * mu[j][c2];
            rs[j][c2] = rsqrtf(var + 1e-5f);
        }
    __syncthreads();
    float* st = (float*)smem;   // [col][row], stride 132 (67584 B)
#pragma unroll
    for (int i = 0; i < 4; i++) {
        int d0 = i * 16 + (l >> 2);
        int row = wo * 64 + d0;
        float g0 = gam[d0], be0 = bet[d0];
        float g8 = gam[d0 + 8], be8 = bet[d0 + 8];
#pragma unroll
        for (int j = 0; j < 4; j++) {
            int col = wp * 32 + j * 8 + (l & 3) * 2;
            st[col * 132 + row]           = (acc[i][j][0] - mu[j][0]) * rs[j][0] * g0 + be0;
            st[(col + 1) * 132 + row]     = (acc[i][j][1] - mu[j][1]) * rs[j][1] * g0 + be0;
            st[col * 132 + row + 8]       = (acc[i][j][2] - mu[j][0]) * rs[j][0] * g8 + be8;
            st[(col + 1) * 132 + row + 8] = (acc[i][j][3] - mu[j][1]) * rs[j][1] * g8 + be8;
        }
    }
    __syncthreads();
    int n = bz >> 3;
#pragma unroll
    for (int it = 0; it < 16; it++) {
        int idx = t + it * 256;               // 4096 float4s
        int col = idx >> 5, quad = idx & 31;
        float4 vls = *(const float4*)(st + col * 132 + quad * 4);
        int o = o0 + quad * 4;                // m*64+d, d quad-aligned
        size_t ga = ((size_t)(n * 1024 + p0 + col) * 2048)
                    + (size_t)(o >> 6) * 512 + g * 64 + (o & 63);
        *(float4*)(Cf + ga) = vls;
    }
}

// ---------------------------------------------------------------------------
// Windowed attention; q/k/v read from TRANSPOSED fp16 [bz][p][c] with
// vectorized u64 loads. fp16 smem + HFMA2, 2 CTAs/SM.
// ---------------------------------------------------------------------------
#define EPS_H 72
#define HPS_H 576
#define QPS_H 576
#define OPS_H 520
#define SK_H (40*HPS_H)
#define SQ_H (16*QPS_H)
#define REL_H (12*EPS_H)
#define ATTN_SMEM_B ((SK_H*2 + SQ_H + REL_H*2) * 2)

__global__ __launch_bounds__(512, 2) void attn_kernel(
    const __half* __restrict__ q, const __half* __restrict__ k,
    const __half* __restrict__ v, const float* __restrict__ hm,
    const float* __restrict__ wmm, __half* __restrict__ avhT)
{
    extern __shared__ __half smemh[];
    __half* sk  = smemh;
    __half* sv  = sk + SK_H;
    __half* sq  = sv + SK_H;
    __half* srh = sq + SQ_H;
    __half* srw = srh + REL_H;
    __half2* attd = (__half2*)sk;
    __half* sout  = sq;

    int t  = threadIdx.x;
    int w0 = blockIdx.x << 3;
    int h0 = blockIdx.y << 1;
    int nm = blockIdx.z;
    int n  = nm >> 2, m = nm & 3;

    for (int idx = t; idx < 5120; idx += 512) {
        int d4  = idx & 15;
        int e   = (idx >> 4) & 7;
        int pos = idx >> 7;
        int r = pos / 10, c = pos % 10;
        int h2 = h0 + r - 1, w2 = w0 + c - 1;
        u64 kv = 0, vv = 0;
        if (h2 >= 0 && h2 < 32 && w2 >= 0 && w2 < 32) {
            size_t gi = (((size_t)(n * 8 + e) * 1024) + h2 * 32 + w2) * 256
                        + m * 64 + d4 * 4;
            kv = *(const u64*)(k + gi);
            vv = *(const u64*)(v + gi);
        }
        int si = pos * HPS_H + e * EPS_H + d4 * 4;
        *(u64*)(sk + si) = kv;
        *(u64*)(sv + si) = vv;
    }
    for (int idx = t; idx < 2048; idx += 512) {
        int d4  = idx & 15;
        int gq  = (idx >> 4) & 7;
        int pix = idx >> 7;
        int p = (h0 + (pix >> 3)) * 32 + w0 + (pix & 7);
        size_t gi = (((size_t)(n * 8 + gq) * 1024) + p) * 256 + m * 64 + d4 * 4;
        *(u64*)(sq + pix * QPS_H + gq * EPS_H + d4 * 4) = *(const u64*)(q + gi);
    }
    for (int idx = t; idx < 768; idx += 512) {
        int d  = idx & 63;
        int ei = idx >> 6;
        int e  = ei / 3, i = ei % 3;
        srh[ei * EPS_H + d] = __float2half_rn(hm [((e * 256 + m * 64 + d) * 3) + i]);
        srw[ei * EPS_H + d] = __float2half_rn(wmm[((e * 256 + m * 64 + d) * 3) + i]);
    }
    __syncthreads();

    int wi = t >> 5, l = t & 31;
    int g  = l >> 2, e0 = l & 3;
    int pr = wi >> 3, cc = (wi & 7) + 1;
    const __half* sqw = sq + wi * QPS_H + g * EPS_H;
    int eoff = e0 * EPS_H;

    int posoff[9];
#pragma unroll
    for (int i = 0; i < 3; i++)
#pragma unroll
        for (int j = 0; j < 3; j++)
            posoff[i * 3 + j] = ((pr + i) * 10 + cc - 1 + j) * HPS_H;

    __half2 z2 = __float2half2_rn(0.f);

    __half2 hA2[3][2], hB2[3][2];
#pragma unroll
    for (int u = 0; u < 3; u++) { hA2[u][0]=z2; hA2[u][1]=z2; hB2[u][0]=z2; hB2[u][1]=z2; }
#pragma unroll
    for (int hf = 0; hf < 2; hf++)
#pragma unroll
    for (int d8 = 0; d8 < 4; d8++) {
        int dd = hf * 32 + d8 * 8;
        uint4 qv = *(const uint4*)(sqw + dd);
#pragma unroll
        for (int u = 0; u < 3; u++) {
            uint4 r4 = *(const uint4*)(srh + (e0 * 3 + u) * EPS_H + dd);
            uint4 s4 = *(const uint4*)(srw + (e0 * 3 + u) * EPS_H + dd);
            hA2[u][hf] = __hfma2(h2u(qv.x), h2u(r4.x), hA2[u][hf]);
            hA2[u][hf] = __hfma2(h2u(qv.y), h2u(r4.y), hA2[u][hf]);
            hA2[u][hf] = __hfma2(h2u(qv.z), h2u(r4.z), hA2[u][hf]);
            hA2[u][hf] = __hfma2(h2u(qv.w), h2u(r4.w), hA2[u][hf]);
            hB2[u][hf] = __hfma2(h2u(qv.x), h2u(s4.x), hB2[u][hf]);
            hB2[u][hf] = __hfma2(h2u(qv.y), h2u(s4.y), hB2[u][hf]);
            hB2[u][hf] = __hfma2(h2u(qv.z), h2u(s4.z), hB2[u][hf]);
            hB2[u][hf] = __hfma2(h2u(qv.w), h2u(s4.w), hB2[u][hf]);
        }
    }
    float qrA[3], qrB[3];
#pragma unroll
    for (int u = 0; u < 3; u++) {
        float2 a0 = __half22float2(hA2[u][0]), a1 = __half22float2(hA2[u][1]);
        float2 b0 = __half22float2(hB2[u][0]), b1 = __half22float2(hB2[u][1]);
        qrA[u] = a0.x + a0.y + a1.x + a1.y;
        qrB[u] = b0.x + b0.y + b1.x + b1.y;
    }

    __half2 cA2[9][2], cB2[9][2];
#pragma unroll
    for (int u = 0; u < 9; u++) { cA2[u][0]=z2; cA2[u][1]=z2; cB2[u][0]=z2; cB2[u][1]=z2; }
#pragma unroll
    for (int hf = 0; hf < 2; hf++)
#pragma unroll
    for (int d8 = 0; d8 < 4; d8++) {
        int dd = hf * 32 + d8 * 8;
        uint4 qv = *(const uint4*)(sqw + dd);
#pragma unroll
        for (int u = 0; u < 9; u++) {
            const __half* kp = sk + posoff[u] + eoff + dd;
            uint4 ka = *(const uint4*)(kp);
            uint4 kc = *(const uint4*)(kp + 4 * EPS_H);
            cA2[u][hf] = __hfma2(h2u(qv.x), h2u(ka.x), cA2[u][hf]);
            cA2[u][hf] = __hfma2(h2u(qv.y), h2u(ka.y), cA2[u][hf]);
            cA2[u][hf] = __hfma2(h2u(qv.z), h2u(ka.z), cA2[u][hf]);
            cA2[u][hf] = __hfma2(h2u(qv.w), h2u(ka.w), cA2[u][hf]);
            cB2[u][hf] = __hfma2(h2u(qv.x), h2u(kc.x), cB2[u][hf]);
            cB2[u][hf] = __hfma2(h2u(qv.y), h2u(kc.y), cB2[u][hf]);
            cB2[u][hf] = __hfma2(h2u(qv.z), h2u(kc.z), cB2[u][hf]);
            cB2[u][hf] = __hfma2(h2u(qv.w), h2u(kc.w), cB2[u][hf]);
        }
    }
    float sA[9], sB[9];
#pragma unroll
    for (int u = 0; u < 9; u++) {
        float2 a0 = __half22float2(cA2[u][0]), a1 = __half22float2(cA2[u][1]);
        float2 b0 = __half22float2(cB2[u][0]), b1 = __half22float2(cB2[u][1]);
        sA[u] = a0.x + a0.y + a1.x + a1.y + qrA[u / 3];
        sB[u] = b0.x + b0.y + b1.x + b1.y + qrB[u % 3];
    }

    float mx = -1e30f;
#pragma unroll
    for (int u = 0; u < 9; u++) mx = fmaxf(mx, fmaxf(sA[u], sB[u]));
    mx = fmaxf(mx, __shfl_xor_sync(0xffffffffu, mx, 1));
    mx = fmaxf(mx, __shfl_xor_sync(0xffffffffu, mx, 2));
    float sum = 0.f;
#pragma unroll
    for (int u = 0; u < 9; u++) {
        sA[u] = __expf(sA[u] - mx);
        sB[u] = __expf(sB[u] - mx);
        sum += sA[u] + sB[u];
    }
    sum += __shfl_xor_sync(0xffffffffu, sum, 1);
    sum += __shfl_xor_sync(0xffffffffu, sum, 2);
    float inv = 1.f / sum;

    __syncthreads();

    __half2* awT = attd + wi * 576;
#pragma unroll
    for (int u = 0; u < 9; u++) {
        awT[((e0 * 9 + u) * 8 + g)]       = __float2half2_rn(sA[u] * inv);
        awT[(((e0 + 4) * 9 + u) * 8 + g)] = __float2half2_rn(sB[u] * inv);
    }
    __syncwarp();

    __half2 acc2[8];
#pragma unroll
    for (int gg = 0; gg < 8; gg++) acc2[gg] = z2;
#pragma unroll 1
    for (int e = 0; e < 8; e++) {
        const __half* vb = sv + e * EPS_H + 2 * l;
#pragma unroll
        for (int nb = 0; nb < 9; nb++) {
            __half2 v2 = *(const __half2*)(vb + posoff[nb]);
            const uint4* wp2 = (const uint4*)(awT + (e * 9 + nb) * 8);
            uint4 wa = wp2[0], wb = wp2[1];
            acc2[0] = __hfma2(h2u(wa.x), v2, acc2[0]);
            acc2[1] = __hfma2(h2u(wa.y), v2, acc2[1]);
            acc2[2] = __hfma2(h2u(wa.z), v2, acc2[2]);
            acc2[3] = __hfma2(h2u(wa.w), v2, acc2[3]);
            acc2[4] = __hfma2(h2u(wb.x), v2, acc2[4]);
            acc2[5] = __hfma2(h2u(wb.y), v2, acc2[5]);
            acc2[6] = __hfma2(h2u(wb.z), v2, acc2[6]);
            acc2[7] = __hfma2(h2u(wb.w), v2, acc2[7]);
        }
    }
    __half* so = sout + wi * OPS_H;
#pragma unroll
    for (int gg = 0; gg < 8; gg++)
        *(__half2*)(so + gg * 64 + 2 * l) = acc2[gg];
    __syncthreads();

#pragma unroll
    for (int it = 0; it < 4; it++) {
        int flat = t + it * 512;
        int dq  = flat & 15;
        int g2  = (flat >> 4) & 7;
        int pix = flat >> 7;
        u64 hp = *(const u64*)(sout + pix * OPS_H + g2 * 64 + dq * 4);
        int p = (h0 + (pix >> 3)) * 32 + w0 + (pix & 7);
        size_t o = (((size_t)(n * 8 + g2) * 1024) + p) * 256 + m * 64 + dq * 4;
        *(u64*)(avhT + o) = hp;
    }
}

// ---------------------------------------------------------------------------
extern "C" void kernel_launch(void* const* d_in, const int* in_sizes, int n_in,
                              void* d_out, int out_size)
{
    (void)in_sizes; (void)n_in; (void)out_size;
    const float* x     = (const float*)d_in[0];
    const float* wq    = (const float*)d_in[1];
    const float* wk    = (const float*)d_in[2];
    const float* wv    = (const float*)d_in[3];
    const float* hm    = (const float*)d_in[4];
    const float* wm    = (const float*)d_in[5];
    const float* wconv = (const float*)d_in[6];
    const float* bconv = (const float*)d_in[7];
    const float* wf1   = (const float*)d_in[8];
    const float* bf1   = (const float*)d_in[9];
    const float* wf2   = (const float*)d_in[10];
    const float* bf2   = (const float*)d_in[11];
    const float* g1    = (const float*)d_in[12];
    const float* b1    = (const float*)d_in[13];
    const float* g2    = (const float*)d_in[14];
    const float* b2    = (const float*)d_in[15];

    float *tb;
    __half *qkvh, *xhT, *xh2, *whi;
    cudaGetSymbolAddress((void**)&tb,   g_t);
    cudaGetSymbolAddress((void**)&qkvh, g_qkv);
    cudaGetSymbolAddress((void**)&xhT,  g_xhT);
    cudaGetSymbolAddress((void**)&xh2,  g_xh2);
    cudaGetSymbolAddress((void**)&whi,  g_whi);

    cudaFuncSetAttribute(attn_kernel,
                         cudaFuncAttributeMaxDynamicSharedMemorySize, ATTN_SMEM_B);
    const int GEMM_SMEM = 98304;
    cudaFuncSetAttribute(hgemm_kernel,
                         cudaFuncAttributeMaxDynamicSharedMemorySize, GEMM_SMEM);

    const size_t WS = 524288;        // per-slot W elements
    const size_t QS = 8388608;       // per-slot qkv halves
    dim3 cxgrid(32, 8, 32);

    convw_kernel<<<dim3(512, 6), 256>>>(wq, wk, wv, wconv, wf1, wf2, whi);
    convx_kernel<<<cxgrid, 256>>>(x, xhT);

    // fused q/k/v GEMM -> fp16 TRANSPOSED [bz][p][c] per slot
    hgemm_kernel<<<dim3(8, 6, 32), 256, GEMM_SMEM>>>(whi, xhT, nullptr,
        nullptr, qkvh, nullptr, nullptr, nullptr, 2, 0);

    attn_kernel<<<dim3(4, 16, 16), 512, ATTN_SMEM_B>>>(qkvh, qkvh + QS, qkvh + 2 * QS,
                                                       hm, wm, xhT);

    // w_conv GEMM with fused skip(x)+LN1 -> tb (scrambled fp32)
    hgemm_kernel<<<dim3(8, 2, 32), 256, GEMM_SMEM>>>(whi + 3*WS, xhT, bconv,
        tb, nullptr, x, g1, b1, 3, 0);

    // transpose+convert tb for f1 GEMM
    convx_kernel<<<cxgrid, 256>>>(tb, xhT);
    // f1 GEMM (relu) -> fp16 transposed into xh2 (feeds f2 directly)
    hgemm_kernel<<<dim3(8, 2, 32), 256, GEMM_SMEM>>>(whi + 4*WS, xhT, bf1,
        nullptr, xh2, nullptr, nullptr, nullptr, 2, 1);
    // f2 GEMM with fused skip(tb)+LN2 -> d_out (scrambled fp32)
    hgemm_kernel<<<dim3(8, 2, 32), 256, GEMM_SMEM>>>(whi + 5*WS, xh2, bf2,
        (float*)d_out, nullptr, tb, g2, b2, 3, 0);
}

// round 14
// speedup vs baseline: 6.2965x; 1.0321x over previous
#include <cuda_runtime.h>
#include <cuda_fp16.h>
#include <cstdint>

#define HWP 1024

// fp32 scratch
__device__ float g_t [4*8*256*HWP];     // tb (scrambled layout)
// fp16 buffers
__device__ __half g_qkv[3*32*256*HWP];  // q,k,v fp16 TRANSPOSED [bz][p][c]
__device__ __half g_xhT[32*1024*256];   // activations [bz][p][k]
__device__ __half g_xh2[32*1024*256];   // second transposed buffer (h1)
__device__ __half g_whi[6*8*256*256];   // fp16 weights [slot][g][o][k]

typedef unsigned long long u64;
__device__ __forceinline__ uint32_t smem_u32(const void* p) {
    uint32_t a;
    asm("{ .reg .u64 tmp; cvta.to.shared.u64 tmp, %1; cvt.u32.u64 %0, tmp; }"
        : "=r"(a) : "l"(p));
    return a;
}
__device__ __forceinline__ void ldsm4(uint32_t* r, uint32_t addr) {
    asm volatile("ldmatrix.sync.aligned.m8n8.x4.shared.b16 {%0,%1,%2,%3}, [%4];"
        : "=r"(r[0]), "=r"(r[1]), "=r"(r[2]), "=r"(r[3]) : "r"(addr));
}
__device__ __forceinline__ void mma_f16(float* c, const uint32_t* a,
                                        uint32_t b0, uint32_t b1) {
    asm volatile("mma.sync.aligned.m16n8k16.row.col.f32.f16.f16.f32 "
        "{%0,%1,%2,%3}, {%4,%5,%6,%7}, {%8,%9}, {%0,%1,%2,%3};"
        : "+f"(c[0]), "+f"(c[1]), "+f"(c[2]), "+f"(c[3])
        : "r"(a[0]), "r"(a[1]), "r"(a[2]), "r"(a[3]), "r"(b0), "r"(b1));
}
__device__ __forceinline__ void cpasync16(uint32_t saddr, const void* g) {
    asm volatile("cp.async.cg.shared.global [%0], [%1], 16;" :: "r"(saddr), "l"(g));
}
#define CP_COMMIT() asm volatile("cp.async.commit_group;" ::: "memory")
__device__ __forceinline__ __half2 h2u(uint32_t v) {
    __half2 h; *(uint32_t*)&h = v; return h;
}

// ---------------------------------------------------------------------------
// Fused prep: blocks [0,3072) = W fp32->fp16; blocks [3072,11264) = x
// transpose+convert [bz][k][p] fp32 -> [bz][p][k] fp16.
// ---------------------------------------------------------------------------
__global__ __launch_bounds__(256) void prep_kernel(
    const float* __restrict__ w0, const float* __restrict__ w1,
    const float* __restrict__ w2, const float* __restrict__ w3,
    const float* __restrict__ w4, const float* __restrict__ w5,
    __half* __restrict__ whi,
    const float* __restrict__ X, __half* __restrict__ hT)
{
    int b = blockIdx.x;
    int t = threadIdx.x;
    if (b < 3072) {
        const float* srcs[6] = {w0, w1, w2, w3, w4, w5};
        int slot = b >> 9, bx = b & 511;
        size_t idx = ((size_t)bx * 256 + t) * 4;
        float4 v = *(const float4*)(srcs[slot] + idx);
        float vv[4] = {v.x, v.y, v.z, v.w};
        u64 hp = 0;
#pragma unroll
        for (int j = 0; j < 4; j++)
            hp |= (u64)__half_as_ushort(__float2half_rn(vv[j])) << (16 * j);
        *(u64*)(whi + (size_t)slot * 524288 + idx) = hp;
        return;
    }
    __shared__ float s[32][33];
    int b2 = b - 3072;
    int pt = b2 & 31, kt = (b2 >> 5) & 7, bz = b2 >> 8;
    const float* Xb = X + ((size_t)bz * 256 + kt * 32) * 1024 + pt * 32;
    int kr = t >> 5, pc = t & 31;
#pragma unroll
    for (int i = 0; i < 4; i++)
        s[kr + i * 8][pc] = Xb[(size_t)(kr + i * 8) * 1024 + pc];
    __syncthreads();
    int pr = t >> 3, kq = t & 7;
    u64 hp = 0;
#pragma unroll
    for (int j = 0; j < 4; j++)
        hp |= (u64)__half_as_ushort(__float2half_rn(s[kq * 4 + j][pr])) << (16 * j);
    size_t o = ((size_t)bz * 1024 + pt * 32 + pr) * 256 + kt * 32 + kq * 4;
    *(u64*)(hT + o) = hp;
}

// ---------------------------------------------------------------------------
// Standalone transpose+convert (for tb).
// ---------------------------------------------------------------------------
__global__ __launch_bounds__(256) void convx_kernel(
    const float* __restrict__ X, __half* __restrict__ hT)
{
    __shared__ float s[32][33];
    int t = threadIdx.x;
    int pt = blockIdx.x, kt = blockIdx.y, bz = blockIdx.z;
    const float* Xb = X + ((size_t)bz * 256 + kt * 32) * 1024 + pt * 32;
    int kr = t >> 5, pc = t & 31;
#pragma unroll
    for (int i = 0; i < 4; i++)
        s[kr + i * 8][pc] = Xb[(size_t)(kr + i * 8) * 1024 + pc];
    __syncthreads();
    int pr = t >> 3, kq = t & 7;
    u64 hp = 0;
#pragma unroll
    for (int j = 0; j < 4; j++)
        hp |= (u64)__half_as_ushort(__float2half_rn(s[kq * 4 + j][pr])) << (16 * j);
    size_t o = ((size_t)bz * 1024 + pt * 32 + pr) * 256 + kt * 32 + kq * 4;
    *(u64*)(hT + o) = hp;
}

// ---------------------------------------------------------------------------
// HMMA GEMM, single-pass fp16, cp.async 3-stage ring over 4 k-chunks.
// grid (8, 2*nslots, 32): slot = by>>1, o-tile = by&1.
// mode 2: fp16 transposed [bz][p][o] -> Ch (+slot offset), bias+relu.
// mode 3: fused skip+LayerNorm -> Cf in SCRAMBLED layout.
// ---------------------------------------------------------------------------
__global__ __launch_bounds__(256, 2) void hgemm_kernel(
    const __half* __restrict__ whi, const __half* __restrict__ xhT,
    const float* __restrict__ bias, float* __restrict__ Cf,
    __half* __restrict__ Ch, const float* __restrict__ Xskip,
    const float* __restrict__ gam, const float* __restrict__ bet,
    int mode, int relu)
{
    extern __shared__ char smem[];
    uint32_t sbase = smem_u32(smem);

    int t  = threadIdx.x;
    int wi = t >> 5, l = t & 31;
    int wo = wi >> 2, wp = wi & 3;
    int slot = blockIdx.y >> 1;
    int p0 = blockIdx.x * 128, o0 = (blockIdx.y & 1) * 128;
    int bz = blockIdx.z, g = bz & 7;

    const __half* Ahi = whi + (size_t)slot * 524288 + (size_t)g * 65536;
    const __half* Bhi = xhT + (size_t)bz * 262144;

    float acc[4][4][4];
#pragma unroll
    for (int i = 0; i < 4; i++)
#pragma unroll
        for (int j = 0; j < 4; j++)
#pragma unroll
            for (int r = 0; r < 4; r++) acc[i][j][r] = 0.f;

    int rowi[4], kqi[4], swoff[4];
#pragma unroll
    for (int i = 0; i < 4; i++) {
        int v2 = t + i * 256;
        rowi[i] = v2 >> 3; kqi[i] = v2 & 7;
        int off = rowi[i] * 128 + kqi[i] * 16;
        swoff[i] = off ^ ((off >> 3) & 0x70);
    }

    int a_row_l = (l & 15), a_col_l = (l >> 4) << 4;
    int b_quad = l >> 3, b_lr = l & 7;
    int b_row_l = ((b_quad >> 1) << 3) + b_lr;
    int b_col_l = (b_quad & 1) << 4;

#define ISSUE_STAGE(s) do {                                                    \
        int k0_ = (s) * 64;                                                    \
        uint32_t sa_ = sbase + ((s) % 3) * 16384;                              \
        uint32_t sb_ = sbase + 49152 + ((s) % 3) * 16384;                      \
        _Pragma("unroll")                                                      \
        for (int i_ = 0; i_ < 4; i_++) {                                       \
            cpasync16(sa_ + swoff[i_],                                         \
                Ahi + ((size_t)(o0 + rowi[i_]) * 256 + k0_ + kqi[i_] * 8));    \
            cpasync16(sb_ + swoff[i_],                                         \
                Bhi + ((size_t)(p0 + rowi[i_]) * 256 + k0_ + kqi[i_] * 8));    \
        }                                                                      \
        CP_COMMIT();                                                           \
    } while (0)

    ISSUE_STAGE(0);
    ISSUE_STAGE(1);

    for (int s = 0; s < 4; s++) {
        if (s < 3) asm volatile("cp.async.wait_group 1;" ::: "memory");
        else       asm volatile("cp.async.wait_group 0;" ::: "memory");
        __syncthreads();
        if (s < 2) ISSUE_STAGE(s + 2);

        uint32_t sa = sbase + (s % 3) * 16384;
        uint32_t sb = sbase + 49152 + (s % 3) * 16384;
#pragma unroll
        for (int ks = 0; ks < 4; ks++) {
            uint32_t af[4][4];
#pragma unroll
            for (int i = 0; i < 4; i++) {
                int row = wo * 64 + i * 16 + a_row_l;
                int off = row * 128 + ks * 32 + a_col_l;
                ldsm4(af[i], sa + (off ^ ((off >> 3) & 0x70)));
            }
            uint32_t bfr[2][4];
#pragma unroll
            for (int j2 = 0; j2 < 2; j2++) {
                int n = wp * 32 + j2 * 16 + b_row_l;
                int off = n * 128 + ks * 32 + b_col_l;
                ldsm4(bfr[j2], sb + (off ^ ((off >> 3) & 0x70)));
            }
#pragma unroll
            for (int i = 0; i < 4; i++)
#pragma unroll
                for (int j = 0; j < 4; j++)
                    mma_f16(acc[i][j], af[i], bfr[j >> 1][(j & 1) * 2],
                            bfr[j >> 1][(j & 1) * 2 + 1]);
        }
    }
#undef ISSUE_STAGE

    if (mode == 2) {
        __syncthreads();
        __half* st = (__half*)smem;   // [col][row], stride 136
#pragma unroll
        for (int i = 0; i < 4; i++) {
            int row = wo * 64 + i * 16 + (l >> 2);
            float b0 = bias ? bias[g * 256 + o0 + row]     : 0.f;
            float b8 = bias ? bias[g * 256 + o0 + row + 8] : 0.f;
#pragma unroll
            for (int j = 0; j < 4; j++) {
                int col = wp * 32 + j * 8 + (l & 3) * 2;
                float v0 = acc[i][j][0] + b0, v1 = acc[i][j][1] + b0;
                float v2 = acc[i][j][2] + b8, v3 = acc[i][j][3] + b8;
                if (relu) {
                    v0 = fmaxf(v0, 0.f); v1 = fmaxf(v1, 0.f);
                    v2 = fmaxf(v2, 0.f); v3 = fmaxf(v3, 0.f);
                }
                st[col * 136 + row]           = __float2half_rn(v0);
                st[(col + 1) * 136 + row]     = __float2half_rn(v1);
                st[col * 136 + row + 8]       = __float2half_rn(v2);
                st[(col + 1) * 136 + row + 8] = __float2half_rn(v3);
            }
        }
        __syncthreads();
        __half* Cb = Ch + (size_t)slot * 8388608;
#pragma unroll
        for (int it = 0; it < 8; it++) {
            int idx = t + it * 256;
            int col = idx >> 4, ch = idx & 15;
            uint4 vls = *(const uint4*)(st + col * 136 + ch * 8);
            *(uint4*)(Cb + ((size_t)bz * 1024 + p0 + col) * 256 + o0 + ch * 8) = vls;
        }
        return;
    }

    // ---- mode 3: fused skip + LayerNorm -> scrambled fp32 ----
    const float* Xb = Xskip + (size_t)bz * 262144;
    float s1[4][2], s2[4][2];
#pragma unroll
    for (int j = 0; j < 4; j++) { s1[j][0]=0.f; s1[j][1]=0.f; s2[j][0]=0.f; s2[j][1]=0.f; }
#pragma unroll
    for (int i = 0; i < 4; i++) {
        int row = o0 + wo * 64 + i * 16 + (l >> 2);
        float b0 = bias ? bias[g * 256 + row]     : 0.f;
        float b8 = bias ? bias[g * 256 + row + 8] : 0.f;
#pragma unroll
        for (int j = 0; j < 4; j++) {
            int col = p0 + wp * 32 + j * 8 + (l & 3) * 2;
            float2 x0 = *(const float2*)(Xb + (size_t)row * 1024 + col);
            float2 x1 = *(const float2*)(Xb + (size_t)(row + 8) * 1024 + col);
            acc[i][j][0] += b0 + x0.x;
            acc[i][j][1] += b0 + x0.y;
            acc[i][j][2] += b8 + x1.x;
            acc[i][j][3] += b8 + x1.y;
            s1[j][0] += acc[i][j][0] + acc[i][j][2];
            s1[j][1] += acc[i][j][1] + acc[i][j][3];
            s2[j][0] += acc[i][j][0]*acc[i][j][0] + acc[i][j][2]*acc[i][j][2];
            s2[j][1] += acc[i][j][1]*acc[i][j][1] + acc[i][j][3]*acc[i][j][3];
        }
    }
#pragma unroll
    for (int mk = 4; mk < 32; mk <<= 1) {
#pragma unroll
        for (int j = 0; j < 4; j++) {
            s1[j][0] += __shfl_xor_sync(0xffffffffu, s1[j][0], mk);
            s1[j][1] += __shfl_xor_sync(0xffffffffu, s1[j][1], mk);
            s2[j][0] += __shfl_xor_sync(0xffffffffu, s2[j][0], mk);
            s2[j][1] += __shfl_xor_sync(0xffffffffu, s2[j][1], mk);
        }
    }
    float mu[4][2], rs[4][2];
#pragma unroll
    for (int j = 0; j < 4; j++)
#pragma unroll
        for (int c2 = 0; c2 < 2; c2++) {
            mu[j][c2] = s1[j][c2] * 0.015625f;
            float var = s2[j][c2] * 0.015625f - mu[j][c2] * mu[j][c2];
            rs[j][c2] = rsqrtf(var + 1e-5f);
        }
    __syncthreads();
    float* st = (float*)smem;   // [col][row], stride 132
#pragma unroll
    for (int i = 0; i < 4; i++) {
        int d0 = i * 16 + (l >> 2);
        int row = wo * 64 + d0;
        float g0 = gam[d0], be0 = bet[d0];
        float g8 = gam[d0 + 8], be8 = bet[d0 + 8];
#pragma unroll
        for (int j = 0; j < 4; j++) {
            int col = wp * 32 + j * 8 + (l & 3) * 2;
            st[col * 132 + row]           = (acc[i][j][0] - mu[j][0]) * rs[j][0] * g0 + be0;
            st[(col + 1) * 132 + row]     = (acc[i][j][1] - mu[j][1]) * rs[j][1] * g0 + be0;
            st[col * 132 + row + 8]       = (acc[i][j][2] - mu[j][0]) * rs[j][0] * g8 + be8;
            st[(col + 1) * 132 + row + 8] = (acc[i][j][3] - mu[j][1]) * rs[j][1] * g8 + be8;
        }
    }
    __syncthreads();
    int n = bz >> 3;
#pragma unroll
    for (int it = 0; it < 16; it++) {
        int idx = t + it * 256;
        int col = idx >> 5, quad = idx & 31;
        float4 vls = *(const float4*)(st + col * 132 + quad * 4);
        int o = o0 + quad * 4;
        size_t ga = ((size_t)(n * 1024 + p0 + col) * 2048)
                    + (size_t)(o >> 6) * 512 + g * 64 + (o & 63);
        *(float4*)(Cf + ga) = vls;
    }
}

// ---------------------------------------------------------------------------
// Windowed attention; single-chain fp16 score accumulators (lower reg
// pressure under the 64-reg/2-CTA cap). q/k/v from TRANSPOSED fp16 [bz][p][c].
// ---------------------------------------------------------------------------
#define EPS_H 72
#define HPS_H 576
#define QPS_H 576
#define OPS_H 520
#define SK_H (40*HPS_H)
#define SQ_H (16*QPS_H)
#define REL_H (12*EPS_H)
#define ATTN_SMEM_B ((SK_H*2 + SQ_H + REL_H*2) * 2)

__global__ __launch_bounds__(512, 2) void attn_kernel(
    const __half* __restrict__ q, const __half* __restrict__ k,
    const __half* __restrict__ v, const float* __restrict__ hm,
    const float* __restrict__ wmm, __half* __restrict__ avhT)
{
    extern __shared__ __half smemh[];
    __half* sk  = smemh;
    __half* sv  = sk + SK_H;
    __half* sq  = sv + SK_H;
    __half* srh = sq + SQ_H;
    __half* srw = srh + REL_H;
    __half2* attd = (__half2*)sk;
    __half* sout  = sq;

    int t  = threadIdx.x;
    int w0 = blockIdx.x << 3;
    int h0 = blockIdx.y << 1;
    int nm = blockIdx.z;
    int n  = nm >> 2, m = nm & 3;

    for (int idx = t; idx < 5120; idx += 512) {
        int d4  = idx & 15;
        int e   = (idx >> 4) & 7;
        int pos = idx >> 7;
        int r = pos / 10, c = pos % 10;
        int h2 = h0 + r - 1, w2 = w0 + c - 1;
        u64 kv = 0, vv = 0;
        if (h2 >= 0 && h2 < 32 && w2 >= 0 && w2 < 32) {
            size_t gi = (((size_t)(n * 8 + e) * 1024) + h2 * 32 + w2) * 256
                        + m * 64 + d4 * 4;
            kv = *(const u64*)(k + gi);
            vv = *(const u64*)(v + gi);
        }
        int si = pos * HPS_H + e * EPS_H + d4 * 4;
        *(u64*)(sk + si) = kv;
        *(u64*)(sv + si) = vv;
    }
    for (int idx = t; idx < 2048; idx += 512) {
        int d4  = idx & 15;
        int gq  = (idx >> 4) & 7;
        int pix = idx >> 7;
        int p = (h0 + (pix >> 3)) * 32 + w0 + (pix & 7);
        size_t gi = (((size_t)(n * 8 + gq) * 1024) + p) * 256 + m * 64 + d4 * 4;
        *(u64*)(sq + pix * QPS_H + gq * EPS_H + d4 * 4) = *(const u64*)(q + gi);
    }
    for (int idx = t; idx < 768; idx += 512) {
        int d  = idx & 63;
        int ei = idx >> 6;
        int e  = ei / 3, i = ei % 3;
        srh[ei * EPS_H + d] = __float2half_rn(hm [((e * 256 + m * 64 + d) * 3) + i]);
        srw[ei * EPS_H + d] = __float2half_rn(wmm[((e * 256 + m * 64 + d) * 3) + i]);
    }
    __syncthreads();

    int wi = t >> 5, l = t & 31;
    int g  = l >> 2, e0 = l & 3;
    int pr = wi >> 3, cc = (wi & 7) + 1;
    const __half* sqw = sq + wi * QPS_H + g * EPS_H;
    int eoff = e0 * EPS_H;

    int posoff[9];
#pragma unroll
    for (int i = 0; i < 3; i++)
#pragma unroll
        for (int j = 0; j < 3; j++)
            posoff[i * 3 + j] = ((pr + i) * 10 + cc - 1 + j) * HPS_H;

    __half2 z2 = __float2half2_rn(0.f);

    // ---- q . rel: single-chain half2 accumulators ----
    __half2 hA2[3], hB2[3];
#pragma unroll
    for (int u = 0; u < 3; u++) { hA2[u] = z2; hB2[u] = z2; }
#pragma unroll
    for (int d8 = 0; d8 < 8; d8++) {
        int dd = d8 * 8;
        uint4 qv = *(const uint4*)(sqw + dd);
#pragma unroll
        for (int u = 0; u < 3; u++) {
            uint4 r4 = *(const uint4*)(srh + (e0 * 3 + u) * EPS_H + dd);
            uint4 s4 = *(const uint4*)(srw + (e0 * 3 + u) * EPS_H + dd);
            hA2[u] = __hfma2(h2u(qv.x), h2u(r4.x), hA2[u]);
            hA2[u] = __hfma2(h2u(qv.y), h2u(r4.y), hA2[u]);
            hA2[u] = __hfma2(h2u(qv.z), h2u(r4.z), hA2[u]);
            hA2[u] = __hfma2(h2u(qv.w), h2u(r4.w), hA2[u]);
            hB2[u] = __hfma2(h2u(qv.x), h2u(s4.x), hB2[u]);
            hB2[u] = __hfma2(h2u(qv.y), h2u(s4.y), hB2[u]);
            hB2[u] = __hfma2(h2u(qv.z), h2u(s4.z), hB2[u]);
            hB2[u] = __hfma2(h2u(qv.w), h2u(s4.w), hB2[u]);
        }
    }
    float qrA[3], qrB[3];
#pragma unroll
    for (int u = 0; u < 3; u++) {
        float2 fa = __half22float2(hA2[u]), fb = __half22float2(hB2[u]);
        qrA[u] = fa.x + fa.y; qrB[u] = fb.x + fb.y;
    }

    // ---- scores: single-chain half2 accumulators ----
    __half2 cA2[9], cB2[9];
#pragma unroll
    for (int u = 0; u < 9; u++) { cA2[u] = z2; cB2[u] = z2; }
#pragma unroll
    for (int d8 = 0; d8 < 8; d8++) {
        int dd = d8 * 8;
        uint4 qv = *(const uint4*)(sqw + dd);
#pragma unroll
        for (int u = 0; u < 9; u++) {
            const __half* kp = sk + posoff[u] + eoff + dd;
            uint4 ka = *(const uint4*)(kp);
            uint4 kc = *(const uint4*)(kp + 4 * EPS_H);
            cA2[u] = __hfma2(h2u(qv.x), h2u(ka.x), cA2[u]);
            cA2[u] = __hfma2(h2u(qv.y), h2u(ka.y), cA2[u]);
            cA2[u] = __hfma2(h2u(qv.z), h2u(ka.z), cA2[u]);
            cA2[u] = __hfma2(h2u(qv.w), h2u(ka.w), cA2[u]);
            cB2[u] = __hfma2(h2u(qv.x), h2u(kc.x), cB2[u]);
            cB2[u] = __hfma2(h2u(qv.y), h2u(kc.y), cB2[u]);
            cB2[u] = __hfma2(h2u(qv.z), h2u(kc.z), cB2[u]);
            cB2[u] = __hfma2(h2u(qv.w), h2u(kc.w), cB2[u]);
        }
    }
    float sA[9], sB[9];
#pragma unroll
    for (int u = 0; u < 9; u++) {
        float2 fa = __half22float2(cA2[u]), fb = __half22float2(cB2[u]);
        sA[u] = fa.x + fa.y + qrA[u / 3];
        sB[u] = fb.x + fb.y + qrB[u % 3];
    }

    float mx = -1e30f;
#pragma unroll
    for (int u = 0; u < 9; u++) mx = fmaxf(mx, fmaxf(sA[u], sB[u]));
    mx = fmaxf(mx, __shfl_xor_sync(0xffffffffu, mx, 1));
    mx = fmaxf(mx, __shfl_xor_sync(0xffffffffu, mx, 2));
    float sum = 0.f;
#pragma unroll
    for (int u = 0; u < 9; u++) {
        sA[u] = __expf(sA[u] - mx);
        sB[u] = __expf(sB[u] - mx);
        sum += sA[u] + sB[u];
    }
    sum += __shfl_xor_sync(0xffffffffu, sum, 1);
    sum += __shfl_xor_sync(0xffffffffu, sum, 2);
    float inv = 1.f / sum;

    __syncthreads();

    __half2* awT = attd + wi * 576;
#pragma unroll
    for (int u = 0; u < 9; u++) {
        awT[((e0 * 9 + u) * 8 + g)]       = __float2half2_rn(sA[u] * inv);
        awT[(((e0 + 4) * 9 + u) * 8 + g)] = __float2half2_rn(sB[u] * inv);
    }
    __syncwarp();

    __half2 acc2[8];
#pragma unroll
    for (int gg = 0; gg < 8; gg++) acc2[gg] = z2;
#pragma unroll 1
    for (int e = 0; e < 8; e++) {
        const __half* vb = sv + e * EPS_H + 2 * l;
#pragma unroll
        for (int nb = 0; nb < 9; nb++) {
            __half2 v2 = *(const __half2*)(vb + posoff[nb]);
            const uint4* wp2 = (const uint4*)(awT + (e * 9 + nb) * 8);
            uint4 wa = wp2[0], wb = wp2[1];
            acc2[0] = __hfma2(h2u(wa.x), v2, acc2[0]);
            acc2[1] = __hfma2(h2u(wa.y), v2, acc2[1]);
            acc2[2] = __hfma2(h2u(wa.z), v2, acc2[2]);
            acc2[3] = __hfma2(h2u(wa.w), v2, acc2[3]);
            acc2[4] = __hfma2(h2u(wb.x), v2, acc2[4]);
            acc2[5] = __hfma2(h2u(wb.y), v2, acc2[5]);
            acc2[6] = __hfma2(h2u(wb.z), v2, acc2[6]);
            acc2[7] = __hfma2(h2u(wb.w), v2, acc2[7]);
        }
    }
    __half* so = sout + wi * OPS_H;
#pragma unroll
    for (int gg = 0; gg < 8; gg++)
        *(__half2*)(so + gg * 64 + 2 * l) = acc2[gg];
    __syncthreads();

#pragma unroll
    for (int it = 0; it < 4; it++) {
        int flat = t + it * 512;
        int dq  = flat & 15;
        int g2  = (flat >> 4) & 7;
        int pix = flat >> 7;
        u64 hp = *(const u64*)(sout + pix * OPS_H + g2 * 64 + dq * 4);
        int p = (h0 + (pix >> 3)) * 32 + w0 + (pix & 7);
        size_t o = (((size_t)(n * 8 + g2) * 1024) + p) * 256 + m * 64 + dq * 4;
        *(u64*)(avhT + o) = hp;
    }
}

// ---------------------------------------------------------------------------
extern "C" void kernel_launch(void* const* d_in, const int* in_sizes, int n_in,
                              void* d_out, int out_size)
{
    (void)in_sizes; (void)n_in; (void)out_size;
    const float* x     = (const float*)d_in[0];
    const float* wq    = (const float*)d_in[1];
    const float* wk    = (const float*)d_in[2];
    const float* wv    = (const float*)d_in[3];
    const float* hm    = (const float*)d_in[4];
    const float* wm    = (const float*)d_in[5];
    const float* wconv = (const float*)d_in[6];
    const float* bconv = (const float*)d_in[7];
    const float* wf1   = (const float*)d_in[8];
    const float* bf1   = (const float*)d_in[9];
    const float* wf2   = (const float*)d_in[10];
    const float* bf2   = (const float*)d_in[11];
    const float* g1    = (const float*)d_in[12];
    const float* b1    = (const float*)d_in[13];
    const float* g2    = (const float*)d_in[14];
    const float* b2    = (const float*)d_in[15];

    float *tb;
    __half *qkvh, *xhT, *xh2, *whi;
    cudaGetSymbolAddress((void**)&tb,   g_t);
    cudaGetSymbolAddress((void**)&qkvh, g_qkv);
    cudaGetSymbolAddress((void**)&xhT,  g_xhT);
    cudaGetSymbolAddress((void**)&xh2,  g_xh2);
    cudaGetSymbolAddress((void**)&whi,  g_whi);

    cudaFuncSetAttribute(attn_kernel,
                         cudaFuncAttributeMaxDynamicSharedMemorySize, ATTN_SMEM_B);
    const int GEMM_SMEM = 98304;
    cudaFuncSetAttribute(hgemm_kernel,
                         cudaFuncAttributeMaxDynamicSharedMemorySize, GEMM_SMEM);

    const size_t WS = 524288;        // per-slot W elements
    const size_t QS = 8388608;       // per-slot qkv halves

    // fused weight-convert + x transpose-convert
    prep_kernel<<<11264, 256>>>(wq, wk, wv, wconv, wf1, wf2, whi, x, xhT);

    // fused q/k/v GEMM -> fp16 TRANSPOSED [bz][p][c] per slot
    hgemm_kernel<<<dim3(8, 6, 32), 256, GEMM_SMEM>>>(whi, xhT, nullptr,
        nullptr, qkvh, nullptr, nullptr, nullptr, 2, 0);

    attn_kernel<<<dim3(4, 16, 16), 512, ATTN_SMEM_B>>>(qkvh, qkvh + QS, qkvh + 2 * QS,
                                                       hm, wm, xhT);

    // w_conv GEMM with fused skip(x)+LN1 -> tb (scrambled fp32)
    hgemm_kernel<<<dim3(8, 2, 32), 256, GEMM_SMEM>>>(whi + 3*WS, xhT, bconv,
        tb, nullptr, x, g1, b1, 3, 0);

    // transpose+convert tb for f1 GEMM
    convx_kernel<<<dim3(32, 8, 32), 256>>>(tb, xhT);
    // f1 GEMM (relu) -> fp16 transposed into xh2 (feeds f2 directly)
    hgemm_kernel<<<dim3(8, 2, 32), 256, GEMM_SMEM>>>(whi + 4*WS, xhT, bf1,
        nullptr, xh2, nullptr, nullptr, nullptr, 2, 1);
    // f2 GEMM with fused skip(tb)+LN2 -> d_out (scrambled fp32)
    hgemm_kernel<<<dim3(8, 2, 32), 256, GEMM_SMEM>>>(whi + 5*WS, xh2, bf2,
        (float*)d_out, nullptr, tb, g2, b2, 3, 0);
}

// round 15
// speedup vs baseline: 6.4716x; 1.0278x over previous
#include <cuda_runtime.h>
#include <cuda_fp16.h>
#include <cstdint>

// fp16 buffers
__device__ __half g_qkv[3*32*256*1024]; // qkv transposed; slot0 reused as tbh
__device__ __half g_xhT[32*1024*256];   // activations [bz][p][k]
__device__ __half g_xh2[32*1024*256];   // h1 transposed
__device__ __half g_whi[6*8*256*256];   // fp16 weights [slot][g][o][k]

typedef unsigned long long u64;
__device__ __forceinline__ uint32_t smem_u32(const void* p) {
    uint32_t a;
    asm("{ .reg .u64 tmp; cvta.to.shared.u64 tmp, %1; cvt.u32.u64 %0, tmp; }"
        : "=r"(a) : "l"(p));
    return a;
}
__device__ __forceinline__ void ldsm4(uint32_t* r, uint32_t addr) {
    asm volatile("ldmatrix.sync.aligned.m8n8.x4.shared.b16 {%0,%1,%2,%3}, [%4];"
        : "=r"(r[0]), "=r"(r[1]), "=r"(r[2]), "=r"(r[3]) : "r"(addr));
}
__device__ __forceinline__ void mma_f16(float* c, const uint32_t* a,
                                        uint32_t b0, uint32_t b1) {
    asm volatile("mma.sync.aligned.m16n8k16.row.col.f32.f16.f16.f32 "
        "{%0,%1,%2,%3}, {%4,%5,%6,%7}, {%8,%9}, {%0,%1,%2,%3};"
        : "+f"(c[0]), "+f"(c[1]), "+f"(c[2]), "+f"(c[3])
        : "r"(a[0]), "r"(a[1]), "r"(a[2]), "r"(a[3]), "r"(b0), "r"(b1));
}
__device__ __forceinline__ void cpasync16(uint32_t saddr, const void* g) {
    asm volatile("cp.async.cg.shared.global [%0], [%1], 16;" :: "r"(saddr), "l"(g));
}
#define CP_COMMIT() asm volatile("cp.async.commit_group;" ::: "memory")
__device__ __forceinline__ __half2 h2u(uint32_t v) {
    __half2 h; *(uint32_t*)&h = v; return h;
}

// ---------------------------------------------------------------------------
// Fused prep: blocks [0,3072) = W fp32->fp16 (slot 4 gets k-permutation
// kc = 2*(k'&127) + (k'>>7)); blocks [3072,11264) = x transpose+convert.
// ---------------------------------------------------------------------------
__global__ __launch_bounds__(256) void prep_kernel(
    const float* __restrict__ w0, const float* __restrict__ w1,
    const float* __restrict__ w2, const float* __restrict__ w3,
    const float* __restrict__ w4, const float* __restrict__ w5,
    __half* __restrict__ whi,
    const float* __restrict__ X, __half* __restrict__ hT)
{
    int b = blockIdx.x;
    int t = threadIdx.x;
    if (b < 3072) {
        const float* srcs[6] = {w0, w1, w2, w3, w4, w5};
        int slot = b >> 9, bx = b & 511;
        size_t idx = ((size_t)bx * 256 + t) * 4;
        u64 hp = 0;
        if (slot == 4) {
            int go = (int)(idx >> 8);          // g*256 + o
            int kq = (int)(idx & 255);         // k' quad base
#pragma unroll
            for (int j = 0; j < 4; j++) {
                int kp = kq + j;
                int kc = 2 * (kp & 127) + (kp >> 7);
                float vv = srcs[4][(size_t)go * 256 + kc];
                hp |= (u64)__half_as_ushort(__float2half_rn(vv)) << (16 * j);
            }
        } else {
            float4 v = *(const float4*)(srcs[slot] + idx);
            float vv[4] = {v.x, v.y, v.z, v.w};
#pragma unroll
            for (int j = 0; j < 4; j++)
                hp |= (u64)__half_as_ushort(__float2half_rn(vv[j])) << (16 * j);
        }
        *(u64*)(whi + (size_t)slot * 524288 + idx) = hp;
        return;
    }
    __shared__ float s[32][33];
    int b2 = b - 3072;
    int pt = b2 & 31, kt = (b2 >> 5) & 7, bz = b2 >> 8;
    const float* Xb = X + ((size_t)bz * 256 + kt * 32) * 1024 + pt * 32;
    int kr = t >> 5, pc = t & 31;
#pragma unroll
    for (int i = 0; i < 4; i++)
        s[kr + i * 8][pc] = Xb[(size_t)(kr + i * 8) * 1024 + pc];
    __syncthreads();
    int pr = t >> 3, kq = t & 7;
    u64 hp = 0;
#pragma unroll
    for (int j = 0; j < 4; j++)
        hp |= (u64)__half_as_ushort(__float2half_rn(s[kq * 4 + j][pr])) << (16 * j);
    size_t o = ((size_t)bz * 1024 + pt * 32 + pr) * 256 + kt * 32 + kq * 4;
    *(u64*)(hT + o) = hp;
}

// ---------------------------------------------------------------------------
// HMMA GEMM, single-pass fp16, cp.async 3-stage ring over 4 k-chunks.
// grid (8, 2*nslots, 32): slot = by>>1, o-tile = by&1.
// mode 2: fp16 transposed [bz][p][o] -> Ch (+slot), bias+relu.
// mode 4: skip(fp32 Xskip)+LN -> fp16 k-permuted tbh layout -> Ch.
// mode 5: skip(fp16 tbh via Ch)+LN -> scrambled fp32 -> Cf.
// ---------------------------------------------------------------------------
__global__ __launch_bounds__(256, 2) void hgemm_kernel(
    const __half* __restrict__ whi, const __half* __restrict__ xhT,
    const float* __restrict__ bias, float* __restrict__ Cf,
    __half* __restrict__ Ch, const float* __restrict__ Xskip,
    const float* __restrict__ gam, const float* __restrict__ bet,
    int mode, int relu)
{
    extern __shared__ char smem[];
    uint32_t sbase = smem_u32(smem);

    int t  = threadIdx.x;
    int wi = t >> 5, l = t & 31;
    int wo = wi >> 2, wp = wi & 3;
    int slot = blockIdx.y >> 1;
    int p0 = blockIdx.x * 128, o0 = (blockIdx.y & 1) * 128;
    int bz = blockIdx.z, g = bz & 7;

    const __half* Ahi = whi + (size_t)slot * 524288 + (size_t)g * 65536;
    const __half* Bhi = xhT + (size_t)bz * 262144;

    float acc[4][4][4];
#pragma unroll
    for (int i = 0; i < 4; i++)
#pragma unroll
        for (int j = 0; j < 4; j++)
#pragma unroll
            for (int r = 0; r < 4; r++) acc[i][j][r] = 0.f;

    int rowi[4], kqi[4], swoff[4];
#pragma unroll
    for (int i = 0; i < 4; i++) {
        int v2 = t + i * 256;
        rowi[i] = v2 >> 3; kqi[i] = v2 & 7;
        int off = rowi[i] * 128 + kqi[i] * 16;
        swoff[i] = off ^ ((off >> 3) & 0x70);
    }

    int a_row_l = (l & 15), a_col_l = (l >> 4) << 4;
    int b_quad = l >> 3, b_lr = l & 7;
    int b_row_l = ((b_quad >> 1) << 3) + b_lr;
    int b_col_l = (b_quad & 1) << 4;

#define ISSUE_STAGE(s) do {                                                    \
        int k0_ = (s) * 64;                                                    \
        uint32_t sa_ = sbase + ((s) % 3) * 16384;                              \
        uint32_t sb_ = sbase + 49152 + ((s) % 3) * 16384;                      \
        _Pragma("unroll")                                                      \
        for (int i_ = 0; i_ < 4; i_++) {                                       \
            cpasync16(sa_ + swoff[i_],                                         \
                Ahi + ((size_t)(o0 + rowi[i_]) * 256 + k0_ + kqi[i_] * 8));    \
            cpasync16(sb_ + swoff[i_],                                         \
                Bhi + ((size_t)(p0 + rowi[i_]) * 256 + k0_ + kqi[i_] * 8));    \
        }                                                                      \
        CP_COMMIT();                                                           \
    } while (0)

    ISSUE_STAGE(0);
    ISSUE_STAGE(1);

    for (int s = 0; s < 4; s++) {
        if (s < 3) asm volatile("cp.async.wait_group 1;" ::: "memory");
        else       asm volatile("cp.async.wait_group 0;" ::: "memory");
        __syncthreads();
        if (s < 2) ISSUE_STAGE(s + 2);

        uint32_t sa = sbase + (s % 3) * 16384;
        uint32_t sb = sbase + 49152 + (s % 3) * 16384;
#pragma unroll
        for (int ks = 0; ks < 4; ks++) {
            uint32_t af[4][4];
#pragma unroll
            for (int i = 0; i < 4; i++) {
                int row = wo * 64 + i * 16 + a_row_l;
                int off = row * 128 + ks * 32 + a_col_l;
                ldsm4(af[i], sa + (off ^ ((off >> 3) & 0x70)));
            }
            uint32_t bfr[2][4];
#pragma unroll
            for (int j2 = 0; j2 < 2; j2++) {
                int n2 = wp * 32 + j2 * 16 + b_row_l;
                int off = n2 * 128 + ks * 32 + b_col_l;
                ldsm4(bfr[j2], sb + (off ^ ((off >> 3) & 0x70)));
            }
#pragma unroll
            for (int i = 0; i < 4; i++)
#pragma unroll
                for (int j = 0; j < 4; j++)
                    mma_f16(acc[i][j], af[i], bfr[j >> 1][(j & 1) * 2],
                            bfr[j >> 1][(j & 1) * 2 + 1]);
        }
    }
#undef ISSUE_STAGE

    if (mode == 2) {
        __syncthreads();
        __half* st = (__half*)smem;   // [col][row], stride 136
#pragma unroll
        for (int i = 0; i < 4; i++) {
            int row = wo * 64 + i * 16 + (l >> 2);
            float b0 = bias ? bias[g * 256 + o0 + row]     : 0.f;
            float b8 = bias ? bias[g * 256 + o0 + row + 8] : 0.f;
#pragma unroll
            for (int j = 0; j < 4; j++) {
                int col = wp * 32 + j * 8 + (l & 3) * 2;
                float v0 = acc[i][j][0] + b0, v1 = acc[i][j][1] + b0;
                float v2 = acc[i][j][2] + b8, v3 = acc[i][j][3] + b8;
                if (relu) {
                    v0 = fmaxf(v0, 0.f); v1 = fmaxf(v1, 0.f);
                    v2 = fmaxf(v2, 0.f); v3 = fmaxf(v3, 0.f);
                }
                st[col * 136 + row]           = __float2half_rn(v0);
                st[(col + 1) * 136 + row]     = __float2half_rn(v1);
                st[col * 136 + row + 8]       = __float2half_rn(v2);
                st[(col + 1) * 136 + row + 8] = __float2half_rn(v3);
            }
        }
        __syncthreads();
        __half* Cb = Ch + (size_t)slot * 8388608;
#pragma unroll
        for (int it = 0; it < 8; it++) {
            int idx = t + it * 256;
            int col = idx >> 4, ch = idx & 15;
            uint4 vls = *(const uint4*)(st + col * 136 + ch * 8);
            *(uint4*)(Cb + ((size_t)bz * 1024 + p0 + col) * 256 + o0 + ch * 8) = vls;
        }
        return;
    }

    // ---- modes 4 / 5: fused skip + LayerNorm ----
    __half* sk2 = (__half*)smem;   // mode 5 skip tile [pl][ocol], stride 136
    if (mode == 5) {
        __syncthreads();
        const __half* Tb = (const __half*)Ch + (size_t)bz * 262144;
#pragma unroll
        for (int it = 0; it < 8; it++) {
            int idx = t + it * 256;          // 2048 = 128 rows x 2 blk x 8 q
            int pl = idx >> 4, rest = idx & 15;
            int blk = rest >> 3, qd = rest & 7;
            uint4 vls = *(const uint4*)(Tb + (size_t)(p0 + pl) * 256
                                        + blk * 128 + (o0 >> 1) + qd * 8);
            *(uint4*)(sk2 + pl * 136 + blk * 64 + qd * 8) = vls;
        }
        __syncthreads();
    }

    float s1[4][2], s2[4][2];
#pragma unroll
    for (int j = 0; j < 4; j++) { s1[j][0]=0.f; s1[j][1]=0.f; s2[j][0]=0.f; s2[j][1]=0.f; }
    const float* Xb = Xskip ? Xskip + (size_t)bz * 262144 : nullptr;
#pragma unroll
    for (int i = 0; i < 4; i++) {
        int row = o0 + wo * 64 + i * 16 + (l >> 2);
        float b0 = bias ? bias[g * 256 + row]     : 0.f;
        float b8 = bias ? bias[g * 256 + row + 8] : 0.f;
#pragma unroll
        for (int j = 0; j < 4; j++) {
            int col = p0 + wp * 32 + j * 8 + (l & 3) * 2;
            float x00, x01, x10, x11;
            if (mode == 4) {
                float2 x0 = *(const float2*)(Xb + (size_t)row * 1024 + col);
                float2 x1 = *(const float2*)(Xb + (size_t)(row + 8) * 1024 + col);
                x00 = x0.x; x01 = x0.y; x10 = x1.x; x11 = x1.y;
            } else {
                int pl0 = wp * 32 + j * 8 + (l & 3) * 2;
                int ca  = ((row & 1) * 64) + ((row - o0) >> 1);
                x00 = __half2float(sk2[pl0 * 136 + ca]);
                x01 = __half2float(sk2[(pl0 + 1) * 136 + ca]);
                x10 = __half2float(sk2[pl0 * 136 + ca + 4]);
                x11 = __half2float(sk2[(pl0 + 1) * 136 + ca + 4]);
            }
            acc[i][j][0] += b0 + x00;
            acc[i][j][1] += b0 + x01;
            acc[i][j][2] += b8 + x10;
            acc[i][j][3] += b8 + x11;
            s1[j][0] += acc[i][j][0] + acc[i][j][2];
            s1[j][1] += acc[i][j][1] + acc[i][j][3];
            s2[j][0] += acc[i][j][0]*acc[i][j][0] + acc[i][j][2]*acc[i][j][2];
            s2[j][1] += acc[i][j][1]*acc[i][j][1] + acc[i][j][3]*acc[i][j][3];
        }
    }
#pragma unroll
    for (int mk = 4; mk < 32; mk <<= 1) {
#pragma unroll
        for (int j = 0; j < 4; j++) {
            s1[j][0] += __shfl_xor_sync(0xffffffffu, s1[j][0], mk);
            s1[j][1] += __shfl_xor_sync(0xffffffffu, s1[j][1], mk);
            s2[j][0] += __shfl_xor_sync(0xffffffffu, s2[j][0], mk);
            s2[j][1] += __shfl_xor_sync(0xffffffffu, s2[j][1], mk);
        }
    }
    float mu[4][2], rs[4][2];
#pragma unroll
    for (int j = 0; j < 4; j++)
#pragma unroll
        for (int c2 = 0; c2 < 2; c2++) {
            mu[j][c2] = s1[j][c2] * 0.015625f;
            float var = s2[j][c2] * 0.015625f - mu[j][c2] * mu[j][c2];
            rs[j][c2] = rsqrtf(var + 1e-5f);
        }
    __syncthreads();
    float* st = (float*)smem;

    if (mode == 4) {
        // stage [row=o_local][col=pl], stride 132
#pragma unroll
        for (int i = 0; i < 4; i++) {
            int d0 = i * 16 + (l >> 2);
            int row = wo * 64 + d0;
            float g0 = gam[d0], be0 = bet[d0];
            float g8 = gam[d0 + 8], be8 = bet[d0 + 8];
#pragma unroll
            for (int j = 0; j < 4; j++) {
                int col = wp * 32 + j * 8 + (l & 3) * 2;
                st[row * 132 + col]           = (acc[i][j][0] - mu[j][0]) * rs[j][0] * g0 + be0;
                st[row * 132 + col + 1]       = (acc[i][j][1] - mu[j][1]) * rs[j][1] * g0 + be0;
                st[(row + 8) * 132 + col]     = (acc[i][j][2] - mu[j][0]) * rs[j][0] * g8 + be8;
                st[(row + 8) * 132 + col + 1] = (acc[i][j][3] - mu[j][1]) * rs[j][1] * g8 + be8;
            }
        }
        __syncthreads();
        int n = bz >> 3, bx = blockIdx.x, par = o0 >> 7;
#pragma unroll
        for (int it = 0; it < 8; it++) {
            int idx = t + it * 256;           // 2048 = 128 rows x 16 chunks
            int row = idx >> 4, ch = idx & 15;
            int o = o0 + row;
            float4 a4 = *(const float4*)(st + row * 132 + ch * 8);
            float4 b4 = *(const float4*)(st + row * 132 + ch * 8 + 4);
            u64 hp = 0;
            hp |= (u64)__half_as_ushort(__float2half_rn(a4.x));
            hp |= (u64)__half_as_ushort(__float2half_rn(a4.y)) << 16;
            hp |= (u64)__half_as_ushort(__float2half_rn(a4.z)) << 32;
            hp |= (u64)__half_as_ushort(__float2half_rn(a4.w)) << 48;
            u64 hq = 0;
            hq |= (u64)__half_as_ushort(__float2half_rn(b4.x));
            hq |= (u64)__half_as_ushort(__float2half_rn(b4.y)) << 16;
            hq |= (u64)__half_as_ushort(__float2half_rn(b4.z)) << 32;
            hq |= (u64)__half_as_ushort(__float2half_rn(b4.w)) << 48;
            int pp = ((o >> 6) & 1) * 512 + g * 64 + (o & 63);
            __half* dst = Ch + ((size_t)(n * 8 + bx) * 1024 + pp) * 256
                          + par * 128 + ch * 8;
            *(u64*)(dst)     = hp;
            *(u64*)(dst + 4) = hq;
        }
        return;
    }

    // mode 5: stage [col][row] stride 132, then scrambled fp32 out
#pragma unroll
    for (int i = 0; i < 4; i++) {
        int d0 = i * 16 + (l >> 2);
        int row = wo * 64 + d0;
        float g0 = gam[d0], be0 = bet[d0];
        float g8 = gam[d0 + 8], be8 = bet[d0 + 8];
#pragma unroll
        for (int j = 0; j < 4; j++) {
            int col = wp * 32 + j * 8 + (l & 3) * 2;
            st[col * 132 + row]           = (acc[i][j][0] - mu[j][0]) * rs[j][0] * g0 + be0;
            st[(col + 1) * 132 + row]     = (acc[i][j][1] - mu[j][1]) * rs[j][1] * g0 + be0;
            st[col * 132 + row + 8]       = (acc[i][j][2] - mu[j][0]) * rs[j][0] * g8 + be8;
            st[(col + 1) * 132 + row + 8] = (acc[i][j][3] - mu[j][1]) * rs[j][1] * g8 + be8;
        }
    }
    __syncthreads();
    int n = bz >> 3;
#pragma unroll
    for (int it = 0; it < 16; it++) {
        int idx = t + it * 256;
        int col = idx >> 5, quad = idx & 31;
        float4 vls = *(const float4*)(st + col * 132 + quad * 4);
        int o = o0 + quad * 4;
        size_t ga = ((size_t)(n * 1024 + p0 + col) * 2048)
                    + (size_t)(o >> 6) * 512 + g * 64 + (o & 63);
        *(float4*)(Cf + ga) = vls;
    }
}

// ---------------------------------------------------------------------------
// Windowed attention (R14 version, unchanged).
// ---------------------------------------------------------------------------
#define EPS_H 72
#define HPS_H 576
#define QPS_H 576
#define OPS_H 520
#define SK_H (40*HPS_H)
#define SQ_H (16*QPS_H)
#define REL_H (12*EPS_H)
#define ATTN_SMEM_B ((SK_H*2 + SQ_H + REL_H*2) * 2)

__global__ __launch_bounds__(512, 2) void attn_kernel(
    const __half* __restrict__ q, const __half* __restrict__ k,
    const __half* __restrict__ v, const float* __restrict__ hm,
    const float* __restrict__ wmm, __half* __restrict__ avhT)
{
    extern __shared__ __half smemh[];
    __half* sk  = smemh;
    __half* sv  = sk + SK_H;
    __half* sq  = sv + SK_H;
    __half* srh = sq + SQ_H;
    __half* srw = srh + REL_H;
    __half2* attd = (__half2*)sk;
    __half* sout  = sq;

    int t  = threadIdx.x;
    int w0 = blockIdx.x << 3;
    int h0 = blockIdx.y << 1;
    int nm = blockIdx.z;
    int n  = nm >> 2, m = nm & 3;

    for (int idx = t; idx < 5120; idx += 512) {
        int d4  = idx & 15;
        int e   = (idx >> 4) & 7;
        int pos = idx >> 7;
        int r = pos / 10, c = pos % 10;
        int h2 = h0 + r - 1, w2 = w0 + c - 1;
        u64 kv = 0, vv = 0;
        if (h2 >= 0 && h2 < 32 && w2 >= 0 && w2 < 32) {
            size_t gi = (((size_t)(n * 8 + e) * 1024) + h2 * 32 + w2) * 256
                        + m * 64 + d4 * 4;
            kv = *(const u64*)(k + gi);
            vv = *(const u64*)(v + gi);
        }
        int si = pos * HPS_H + e * EPS_H + d4 * 4;
        *(u64*)(sk + si) = kv;
        *(u64*)(sv + si) = vv;
    }
    for (int idx = t; idx < 2048; idx += 512) {
        int d4  = idx & 15;
        int gq  = (idx >> 4) & 7;
        int pix = idx >> 7;
        int p = (h0 + (pix >> 3)) * 32 + w0 + (pix & 7);
        size_t gi = (((size_t)(n * 8 + gq) * 1024) + p) * 256 + m * 64 + d4 * 4;
        *(u64*)(sq + pix * QPS_H + gq * EPS_H + d4 * 4) = *(const u64*)(q + gi);
    }
    for (int idx = t; idx < 768; idx += 512) {
        int d  = idx & 63;
        int ei = idx >> 6;
        int e  = ei / 3, i = ei % 3;
        srh[ei * EPS_H + d] = __float2half_rn(hm [((e * 256 + m * 64 + d) * 3) + i]);
        srw[ei * EPS_H + d] = __float2half_rn(wmm[((e * 256 + m * 64 + d) * 3) + i]);
    }
    __syncthreads();

    int wi = t >> 5, l = t & 31;
    int g  = l >> 2, e0 = l & 3;
    int pr = wi >> 3, cc = (wi & 7) + 1;
    const __half* sqw = sq + wi * QPS_H + g * EPS_H;
    int eoff = e0 * EPS_H;

    int posoff[9];
#pragma unroll
    for (int i = 0; i < 3; i++)
#pragma unroll
        for (int j = 0; j < 3; j++)
            posoff[i * 3 + j] = ((pr + i) * 10 + cc - 1 + j) * HPS_H;

    __half2 z2 = __float2half2_rn(0.f);

    __half2 hA2[3], hB2[3];
#pragma unroll
    for (int u = 0; u < 3; u++) { hA2[u] = z2; hB2[u] = z2; }
#pragma unroll
    for (int d8 = 0; d8 < 8; d8++) {
        int dd = d8 * 8;
        uint4 qv = *(const uint4*)(sqw + dd);
#pragma unroll
        for (int u = 0; u < 3; u++) {
            uint4 r4 = *(const uint4*)(srh + (e0 * 3 + u) * EPS_H + dd);
            uint4 s4 = *(const uint4*)(srw + (e0 * 3 + u) * EPS_H + dd);
            hA2[u] = __hfma2(h2u(qv.x), h2u(r4.x), hA2[u]);
            hA2[u] = __hfma2(h2u(qv.y), h2u(r4.y), hA2[u]);
            hA2[u] = __hfma2(h2u(qv.z), h2u(r4.z), hA2[u]);
            hA2[u] = __hfma2(h2u(qv.w), h2u(r4.w), hA2[u]);
            hB2[u] = __hfma2(h2u(qv.x), h2u(s4.x), hB2[u]);
            hB2[u] = __hfma2(h2u(qv.y), h2u(s4.y), hB2[u]);
            hB2[u] = __hfma2(h2u(qv.z), h2u(s4.z), hB2[u]);
            hB2[u] = __hfma2(h2u(qv.w), h2u(s4.w), hB2[u]);
        }
    }
    float qrA[3], qrB[3];
#pragma unroll
    for (int u = 0; u < 3; u++) {
        float2 fa = __half22float2(hA2[u]), fb = __half22float2(hB2[u]);
        qrA[u] = fa.x + fa.y; qrB[u] = fb.x + fb.y;
    }

    __half2 cA2[9], cB2[9];
#pragma unroll
    for (int u = 0; u < 9; u++) { cA2[u] = z2; cB2[u] = z2; }
#pragma unroll
    for (int d8 = 0; d8 < 8; d8++) {
        int dd = d8 * 8;
        uint4 qv = *(const uint4*)(sqw + dd);
#pragma unroll
        for (int u = 0; u < 9; u++) {
            const __half* kp = sk + posoff[u] + eoff + dd;
            uint4 ka = *(const uint4*)(kp);
            uint4 kc = *(const uint4*)(kp + 4 * EPS_H);
            cA2[u] = __hfma2(h2u(qv.x), h2u(ka.x), cA2[u]);
            cA2[u] = __hfma2(h2u(qv.y), h2u(ka.y), cA2[u]);
            cA2[u] = __hfma2(h2u(qv.z), h2u(ka.z), cA2[u]);
            cA2[u] = __hfma2(h2u(qv.w), h2u(ka.w), cA2[u]);
            cB2[u] = __hfma2(h2u(qv.x), h2u(kc.x), cB2[u]);
            cB2[u] = __hfma2(h2u(qv.y), h2u(kc.y), cB2[u]);
            cB2[u] = __hfma2(h2u(qv.z), h2u(kc.z), cB2[u]);
            cB2[u] = __hfma2(h2u(qv.w), h2u(kc.w), cB2[u]);
        }
    }
    float sA[9], sB[9];
#pragma unroll
    for (int u = 0; u < 9; u++) {
        float2 fa = __half22float2(cA2[u]), fb = __half22float2(cB2[u]);
        sA[u] = fa.x + fa.y + qrA[u / 3];
        sB[u] = fb.x + fb.y + qrB[u % 3];
    }

    float mx = -1e30f;
#pragma unroll
    for (int u = 0; u < 9; u++) mx = fmaxf(mx, fmaxf(sA[u], sB[u]));
    mx = fmaxf(mx, __shfl_xor_sync(0xffffffffu, mx, 1));
    mx = fmaxf(mx, __shfl_xor_sync(0xffffffffu, mx, 2));
    float sum = 0.f;
#pragma unroll
    for (int u = 0; u < 9; u++) {
        sA[u] = __expf(sA[u] - mx);
        sB[u] = __expf(sB[u] - mx);
        sum += sA[u] + sB[u];
    }
    sum += __shfl_xor_sync(0xffffffffu, sum, 1);
    sum += __shfl_xor_sync(0xffffffffu, sum, 2);
    float inv = 1.f / sum;

    __syncthreads();

    __half2* awT = attd + wi * 576;
#pragma unroll
    for (int u = 0; u < 9; u++) {
        awT[((e0 * 9 + u) * 8 + g)]       = __float2half2_rn(sA[u] * inv);
        awT[(((e0 + 4) * 9 + u) * 8 + g)] = __float2half2_rn(sB[u] * inv);
    }
    __syncwarp();

    __half2 acc2[8];
#pragma unroll
    for (int gg = 0; gg < 8; gg++) acc2[gg] = z2;
#pragma unroll 1
    for (int e = 0; e < 8; e++) {
        const __half* vb = sv + e * EPS_H + 2 * l;
#pragma unroll
        for (int nb = 0; nb < 9; nb++) {
            __half2 v2 = *(const __half2*)(vb + posoff[nb]);
            const uint4* wp2 = (const uint4*)(awT + (e * 9 + nb) * 8);
            uint4 wa = wp2[0], wb = wp2[1];
            acc2[0] = __hfma2(h2u(wa.x), v2, acc2[0]);
            acc2[1] = __hfma2(h2u(wa.y), v2, acc2[1]);
            acc2[2] = __hfma2(h2u(wa.z), v2, acc2[2]);
            acc2[3] = __hfma2(h2u(wa.w), v2, acc2[3]);
            acc2[4] = __hfma2(h2u(wb.x), v2, acc2[4]);
            acc2[5] = __hfma2(h2u(wb.y), v2, acc2[5]);
            acc2[6] = __hfma2(h2u(wb.z), v2, acc2[6]);
            acc2[7] = __hfma2(h2u(wb.w), v2, acc2[7]);
        }
    }
    __half* so = sout + wi * OPS_H;
#pragma unroll
    for (int gg = 0; gg < 8; gg++)
        *(__half2*)(so + gg * 64 + 2 * l) = acc2[gg];
    __syncthreads();

#pragma unroll
    for (int it = 0; it < 4; it++) {
        int flat = t + it * 512;
        int dq  = flat & 15;
        int g2  = (flat >> 4) & 7;
        int pix = flat >> 7;
        u64 hp = *(const u64*)(sout + pix * OPS_H + g2 * 64 + dq * 4);
        int p = (h0 + (pix >> 3)) * 32 + w0 + (pix & 7);
        size_t o = (((size_t)(n * 8 + g2) * 1024) + p) * 256 + m * 64 + dq * 4;
        *(u64*)(avhT + o) = hp;
    }
}

// ---------------------------------------------------------------------------
extern "C" void kernel_launch(void* const* d_in, const int* in_sizes, int n_in,
                              void* d_out, int out_size)
{
    (void)in_sizes; (void)n_in; (void)out_size;
    const float* x     = (const float*)d_in[0];
    const float* wq    = (const float*)d_in[1];
    const float* wk    = (const float*)d_in[2];
    const float* wv    = (const float*)d_in[3];
    const float* hm    = (const float*)d_in[4];
    const float* wm    = (const float*)d_in[5];
    const float* wconv = (const float*)d_in[6];
    const float* bconv = (const float*)d_in[7];
    const float* wf1   = (const float*)d_in[8];
    const float* bf1   = (const float*)d_in[9];
    const float* wf2   = (const float*)d_in[10];
    const float* bf2   = (const float*)d_in[11];
    const float* g1    = (const float*)d_in[12];
    const float* b1    = (const float*)d_in[13];
    const float* g2    = (const float*)d_in[14];
    const float* b2    = (const float*)d_in[15];

    __half *qkvh, *xhT, *xh2, *whi;
    cudaGetSymbolAddress((void**)&qkvh, g_qkv);
    cudaGetSymbolAddress((void**)&xhT,  g_xhT);
    cudaGetSymbolAddress((void**)&xh2,  g_xh2);
    cudaGetSymbolAddress((void**)&whi,  g_whi);

    cudaFuncSetAttribute(attn_kernel,
                         cudaFuncAttributeMaxDynamicSharedMemorySize, ATTN_SMEM_B);
    const int GEMM_SMEM = 98304;
    cudaFuncSetAttribute(hgemm_kernel,
                         cudaFuncAttributeMaxDynamicSharedMemorySize, GEMM_SMEM);

    const size_t WS = 524288;        // per-slot W elements
    const size_t QS = 8388608;       // per-slot qkv halves

    // fused weight-convert (slot4 k-permuted) + x transpose-convert
    prep_kernel<<<11264, 256>>>(wq, wk, wv, wconv, wf1, wf2, whi, x, xhT);

    // fused q/k/v GEMM -> fp16 transposed [bz][p][c] per slot
    hgemm_kernel<<<dim3(8, 6, 32), 256, GEMM_SMEM>>>(whi, xhT, nullptr,
        nullptr, qkvh, nullptr, nullptr, nullptr, 2, 0);

    attn_kernel<<<dim3(4, 16, 16), 512, ATTN_SMEM_B>>>(qkvh, qkvh + QS, qkvh + 2 * QS,
                                                       hm, wm, xhT);

    // w_conv GEMM: skip(x)+LN1 -> fp16 k-permuted tbh (into qkv slot 0)
    hgemm_kernel<<<dim3(8, 2, 32), 256, GEMM_SMEM>>>(whi + 3*WS, xhT, bconv,
        nullptr, qkvh, x, g1, b1, 4, 0);

    // f1 GEMM (relu, permuted weights) reads tbh -> fp16 transposed xh2
    hgemm_kernel<<<dim3(8, 2, 32), 256, GEMM_SMEM>>>(whi + 4*WS, qkvh, bf1,
        nullptr, xh2, nullptr, nullptr, nullptr, 2, 1);

    // f2 GEMM: skip(tbh fp16)+LN2 -> scrambled fp32 d_out
    hgemm_kernel<<<dim3(8, 2, 32), 256, GEMM_SMEM>>>(whi + 5*WS, xh2, bf2,
        (float*)d_out, qkvh, nullptr, g2, b2, 5, 0);
}